// round 3
// baseline (speedup 1.0000x reference)
#include <cuda_runtime.h>
#include <math.h>

// ---------------- problem constants ----------------
#define BB    8
#define DIMC  256
#define D3    768          // 3*DIM
#define HEADS 4
#define CH    64           // per-head channels
#define HH    128
#define WW    128
#define NPIX  16384        // H*W

// ---------------- scratch (device globals; no runtime alloc) ----------------
__device__ float g_qkv[100663296];   // [B,768,NPIX] post 1x1 conv        (402 MB)
__device__ float g_dwb[100663296];   // [B,768,NPIX] post depthwise conv  (402 MB)
__device__ float g_g1b[16777216];    // [B,128,NPIX] gate hidden          (67 MB)
__device__ float g_part[4194304];    // [32 chunks][32 bh][64][64] attn partials (16 MB)
__device__ float g_attn[131072];     // [32 bh][64][64] attn (raw -> softmaxed in place)
__device__ float g_inv[4096];        // [B][512] inverse L2 norms of q(0..255) / k(256..511) rows
__device__ float g_gatepart[512];    // per-block gate sums
__device__ int   g_dk;               // dynamic k

// ================= SGEMM: C[z] = A (MxK) * B[z] (KxN)  (row-major) =================
// BM=BN=128, BK=8, 256 threads, 8x8 microtile. K and N multiples of 8/128 assumed.
__global__ __launch_bounds__(256, 2) void sgemm_k(
    const float* __restrict__ A, const float* __restrict__ B, float* __restrict__ C,
    int M, int N, int K, long bStride, long cStride,
    const float* __restrict__ bias, int relu)
{
    const float* Bb = B + (size_t)blockIdx.z * bStride;
    float*       Cb = C + (size_t)blockIdx.z * cStride;
    const int m0 = blockIdx.y * 128, n0 = blockIdx.x * 128;

    __shared__ float As[8][132];   // transposed A tile, padded
    __shared__ float Bs[8][128];

    const int tid = threadIdx.x;
    const int tx  = tid & 15, ty = tid >> 4;

    float acc[8][8];
#pragma unroll
    for (int i = 0; i < 8; i++)
#pragma unroll
        for (int j = 0; j < 8; j++) acc[i][j] = 0.f;

    const int arow = tid >> 1, acol = (tid & 1) << 2;   // 128 rows x 8 cols via float4
    const int brow = tid >> 5, bcol = (tid & 31) << 2;  // 8 rows x 128 cols via float4

    for (int k0 = 0; k0 < K; k0 += 8) {
        float4 a4 = *(const float4*)(A + (size_t)(m0 + arow) * K + k0 + acol);
        As[acol + 0][arow] = a4.x;
        As[acol + 1][arow] = a4.y;
        As[acol + 2][arow] = a4.z;
        As[acol + 3][arow] = a4.w;
        *(float4*)(&Bs[brow][bcol]) =
            *(const float4*)(Bb + (size_t)(k0 + brow) * N + n0 + bcol);
        __syncthreads();
#pragma unroll
        for (int kk = 0; kk < 8; kk++) {
            float a[8], b[8];
#pragma unroll
            for (int i = 0; i < 8; i++) a[i] = As[kk][ty * 8 + i];
#pragma unroll
            for (int j = 0; j < 8; j++) b[j] = Bs[kk][tx * 8 + j];
#pragma unroll
            for (int i = 0; i < 8; i++)
#pragma unroll
                for (int j = 0; j < 8; j++) acc[i][j] += a[i] * b[j];
        }
        __syncthreads();
    }

#pragma unroll
    for (int i = 0; i < 8; i++) {
        const int m = m0 + ty * 8 + i;
        const float bv = bias ? bias[m] : 0.f;
#pragma unroll
        for (int j = 0; j < 8; j += 4) {
            float4 o;
            o.x = acc[i][j + 0] + bv;
            o.y = acc[i][j + 1] + bv;
            o.z = acc[i][j + 2] + bv;
            o.w = acc[i][j + 3] + bv;
            if (relu) {
                o.x = fmaxf(o.x, 0.f); o.y = fmaxf(o.y, 0.f);
                o.z = fmaxf(o.z, 0.f); o.w = fmaxf(o.w, 0.f);
            }
            *(float4*)(Cb + (size_t)m * N + n0 + tx * 8 + j) = o;
        }
    }
}

// ================= depthwise 3x3 (SAME, zero pad), g_qkv -> g_dwb =================
__global__ __launch_bounds__(128) void dwconv_k(const float* __restrict__ wdw)
{
    const int x  = threadIdx.x;
    const int y  = blockIdx.x & (HH - 1);
    const int bc = blockIdx.x >> 7;           // b*768 + ch
    const int ch = bc % D3;
    const float* __restrict__ w = wdw + ch * 9;
    const float* __restrict__ in = g_qkv + (size_t)bc * NPIX;

    float acc = 0.f;
#pragma unroll
    for (int dy = -1; dy <= 1; dy++) {
        const int yy = y + dy;
        if ((unsigned)yy < HH) {
            const float* r = in + yy * WW;
#pragma unroll
            for (int dx = -1; dx <= 1; dx++) {
                const int xx = x + dx;
                if ((unsigned)xx < WW)
                    acc += __ldg(r + xx) * __ldg(w + (dy + 1) * 3 + (dx + 1));
            }
        }
    }
    g_dwb[(size_t)bc * NPIX + y * WW + x] = acc;
}

// ================= gate stage 2: sigmoid(w2 . g1 + b2), per-block partial sums =======
__global__ __launch_bounds__(256) void gate2_k(const float* __restrict__ w2,
                                               const float* __restrict__ b2)
{
    __shared__ float w2s[128];
    const int tid = threadIdx.x;
    if (tid < 128) w2s[tid] = w2[tid];
    __syncthreads();

    const int pg = blockIdx.x * 256 + tid;    // global pixel over B*NPIX
    const int b  = pg >> 14;
    const int p  = pg & (NPIX - 1);
    const float* __restrict__ g = g_g1b + (size_t)b * 128 * NPIX + p;

    float acc = b2[0];
#pragma unroll 8
    for (int j = 0; j < 128; j++) acc += w2s[j] * g[(size_t)j * NPIX];
    const float sig = 1.f / (1.f + expf(-acc));

    __shared__ float red[256];
    red[tid] = sig;
    __syncthreads();
    for (int s = 128; s > 0; s >>= 1) {
        if (tid < s) red[tid] += red[tid + s];
        __syncthreads();
    }
    if (tid == 0) g_gatepart[blockIdx.x] = red[0];
}

// ================= dynamic-k from gate mean =================
__global__ void dk_k()
{
    __shared__ float red[256];
    const int tid = threadIdx.x;
    float s = 0.f;
    for (int i = tid; i < 512; i += 256) s += g_gatepart[i];
    red[tid] = s;
    __syncthreads();
    for (int st = 128; st > 0; st >>= 1) {
        if (tid < st) red[tid] += red[tid + st];
        __syncthreads();
    }
    if (tid == 0) {
        const float mean = red[0] / (float)(BB * NPIX);
        int dk = (int)floorf(64.f * mean);
        if (dk < 1) dk = 1;
        if (dk > 64) dk = 64;
        g_dk = dk;
    }
}

// ================= per-row (b,h,c) inverse L2 norms of q & k =================
__global__ __launch_bounds__(256) void norm_k()
{
    const int idx = blockIdx.x;                    // 0..4095 = b*512 + ch(0..511)
    const int b = idx >> 9, ch = idx & 511;
    const float* __restrict__ row = g_dwb + (size_t)(b * D3 + ch) * NPIX;
    const int tid = threadIdx.x;

    float s = 0.f;
    for (int p = tid; p < NPIX; p += 256) { const float v = row[p]; s += v * v; }
#pragma unroll
    for (int o = 16; o > 0; o >>= 1) s += __shfl_down_sync(0xffffffffu, s, o);

    __shared__ float ws[8];
    if ((tid & 31) == 0) ws[tid >> 5] = s;
    __syncthreads();
    if (tid == 0) {
        float t = 0.f;
#pragma unroll
        for (int i = 0; i < 8; i++) t += ws[i];
        g_inv[idx] = 1.f / fmaxf(sqrtf(t), 1e-12f);
    }
}

// ================= attn partials: S[c,d] += sum_n Q[c,n]K[d,n] over a 512-n chunk ====
__global__ __launch_bounds__(256) void attn_partial_k()
{
    const int bh = blockIdx.y;                 // 0..31
    const int b = bh >> 2, h = bh & 3;
    const float* __restrict__ Q = g_dwb + (size_t)b * D3 * NPIX + (size_t)(h * CH) * NPIX;
    const float* __restrict__ Kp = g_dwb + (size_t)b * D3 * NPIX + (size_t)(256 + h * CH) * NPIX;
    const int n0c = blockIdx.x * 512;

    __shared__ float Qs[64][66];
    __shared__ float Ks[64][66];

    const int tid = threadIdx.x;
    const int tx = tid & 15, ty = tid >> 4;

    float acc[4][4];
#pragma unroll
    for (int i = 0; i < 4; i++)
#pragma unroll
        for (int j = 0; j < 4; j++) acc[i][j] = 0.f;

    for (int ns = 0; ns < 512; ns += 64) {
        const int n0 = n0c + ns;
#pragma unroll
        for (int e = 0; e < 16; e++) {
            const int idx = tid + e * 256;       // 0..4095
            const int c = idx >> 6, nn = idx & 63;
            Qs[nn][c] = Q[(size_t)c * NPIX + n0 + nn];
            Ks[nn][c] = Kp[(size_t)c * NPIX + n0 + nn];
        }
        __syncthreads();
#pragma unroll 16
        for (int kk = 0; kk < 64; kk++) {
            float a[4], bv[4];
#pragma unroll
            for (int i = 0; i < 4; i++) a[i] = Qs[kk][ty * 4 + i];
#pragma unroll
            for (int j = 0; j < 4; j++) bv[j] = Ks[kk][tx * 4 + j];
#pragma unroll
            for (int i = 0; i < 4; i++)
#pragma unroll
                for (int j = 0; j < 4; j++) acc[i][j] += a[i] * bv[j];
        }
        __syncthreads();
    }

    const int base = (blockIdx.x * 32 + bh) * 4096;
#pragma unroll
    for (int i = 0; i < 4; i++)
#pragma unroll
        for (int j = 0; j < 4; j++)
            g_part[base + (ty * 4 + i) * 64 + tx * 4 + j] = acc[i][j];
}

// ================= deterministic partial reduction =================
__global__ __launch_bounds__(256) void attn_reduce_k()
{
    const int i = blockIdx.x * 256 + threadIdx.x;  // 0..131071
    float s = 0.f;
#pragma unroll
    for (int c = 0; c < 32; c++) s += g_part[c * 131072 + i];
    g_attn[i] = s;
}

// ================= normalize, temperature, top-k mask, softmax, 4x scale ============
__global__ __launch_bounds__(64) void softmax_k(const float* __restrict__ temp,
                                                const float* __restrict__ a1,
                                                const float* __restrict__ a2,
                                                const float* __restrict__ a3,
                                                const float* __restrict__ a4)
{
    const int row = blockIdx.x;                 // 0..2047 = bh*64 + c
    const int bh = row >> 6, c = row & 63;
    const int b = bh >> 2, h = bh & 3;
    const int d = threadIdx.x;

    const float invq = g_inv[b * 512 + h * CH + c];
    const float invk = g_inv[b * 512 + 256 + h * CH + d];
    const float a = g_attn[row * 64 + d] * invq * invk * temp[h];

    __shared__ float sv[64], se[64];
    sv[d] = a;
    __syncthreads();

    const int dk = g_dk;
    int rank = 0;
    float mx = -3.4e38f;
#pragma unroll 8
    for (int j = 0; j < 64; j++) {
        const float v = sv[j];
        rank += (v > a);
        mx = fmaxf(mx, v);
    }
    se[d] = (rank < dk) ? a : 3.4e38f;          // candidates for the dk-th largest
    __syncthreads();
    float t = 3.4e38f;
#pragma unroll 8
    for (int j = 0; j < 64; j++) t = fminf(t, se[j]);
    __syncthreads();

    const float e = (a >= t) ? expf(a - mx) : 0.f;
    se[d] = e;
    __syncthreads();
    float sum = 0.f;
#pragma unroll 8
    for (int j = 0; j < 64; j++) sum += se[j];

    const float s4 = a1[0] + a2[0] + a3[0] + a4[0];
    g_attn[row * 64 + d] = e / sum * s4;
}

// ================= out[b, h*64+c, n] = sum_d P[c,d] * V[d,n]  =================
__global__ __launch_bounds__(256) void av_k(float* __restrict__ out)
{
    const int bh = blockIdx.y;
    const int b = bh >> 2, h = bh & 3;
    const float* __restrict__ Pm = g_attn + bh * 4096;
    const float* __restrict__ V = g_dwb + (size_t)b * D3 * NPIX + (size_t)(512 + h * CH) * NPIX;
    float* __restrict__ O = out + (size_t)b * DIMC * NPIX + (size_t)(h * CH) * NPIX;

    __shared__ float As[64][68];                 // transposed P: As[d][c]
    const int tid = threadIdx.x;
    for (int e = tid; e < 4096; e += 256) {
        const int cc = e >> 6, dd = e & 63;
        As[dd][cc] = Pm[e];
    }
    __syncthreads();

    const int tx = tid & 31, ty = tid >> 5;      // ty: c-group of 8
    const int n = blockIdx.x * 128 + tx * 4;

    float acc[8][4];
#pragma unroll
    for (int i = 0; i < 8; i++)
#pragma unroll
        for (int j = 0; j < 4; j++) acc[i][j] = 0.f;

#pragma unroll 8
    for (int dd = 0; dd < 64; dd++) {
        const float4 v = *(const float4*)(V + (size_t)dd * NPIX + n);
        float a[8];
#pragma unroll
        for (int i = 0; i < 8; i++) a[i] = As[dd][ty * 8 + i];
#pragma unroll
        for (int i = 0; i < 8; i++) {
            acc[i][0] += a[i] * v.x;
            acc[i][1] += a[i] * v.y;
            acc[i][2] += a[i] * v.z;
            acc[i][3] += a[i] * v.w;
        }
    }
#pragma unroll
    for (int i = 0; i < 8; i++) {
        float4 o;
        o.x = acc[i][0]; o.y = acc[i][1]; o.z = acc[i][2]; o.w = acc[i][3];
        *(float4*)(O + (size_t)(ty * 8 + i) * NPIX + n) = o;
    }
}

// ================================ launch ================================
extern "C" void kernel_launch(void* const* d_in, const int* in_sizes, int n_in,
                              void* d_out, int out_size)
{
    (void)in_sizes; (void)n_in; (void)out_size;
    const float* x     = (const float*)d_in[0];
    const float* w_qkv = (const float*)d_in[1];
    const float* w_dw  = (const float*)d_in[2];
    const float* temp  = (const float*)d_in[3];
    const float* a1    = (const float*)d_in[4];
    const float* a2    = (const float*)d_in[5];
    const float* a3    = (const float*)d_in[6];
    const float* a4    = (const float*)d_in[7];
    const float* gw1   = (const float*)d_in[8];
    const float* gb1   = (const float*)d_in[9];
    const float* gw2   = (const float*)d_in[10];
    const float* gb2   = (const float*)d_in[11];
    float* out = (float*)d_out;

    void *p_qkv = nullptr, *p_g1 = nullptr;
    cudaGetSymbolAddress(&p_qkv, g_qkv);
    cudaGetSymbolAddress(&p_g1, g_g1b);

    // 1) qkv = W_qkv (768x256) @ X[b] (256x16384)
    {
        dim3 g(NPIX / 128, D3 / 128, BB);
        sgemm_k<<<g, 256>>>(w_qkv, x, (float*)p_qkv, D3, NPIX, DIMC,
                            (long)DIMC * NPIX, (long)D3 * NPIX, nullptr, 0);
    }
    // 2) gate hidden g1 = relu(Gw1 (128x256) @ X[b] + b1)
    {
        dim3 g(NPIX / 128, 1, BB);
        sgemm_k<<<g, 256>>>(gw1, x, (float*)p_g1, 128, NPIX, DIMC,
                            (long)DIMC * NPIX, (long)128 * NPIX, gb1, 1);
    }
    // 3) depthwise 3x3
    dwconv_k<<<BB * D3 * HH, 128>>>(w_dw);
    // 4) gate stage 2 + partial sums, then dynamic k
    gate2_k<<<512, 256>>>(gw2, gb2);
    dk_k<<<1, 256>>>();
    // 5) q/k row inverse norms
    norm_k<<<4096, 256>>>();
    // 6) attention S = Q K^T (split-K partials + deterministic reduce)
    {
        dim3 g(32, 32);
        attn_partial_k<<<g, 256>>>();
    }
    attn_reduce_k<<<512, 256>>>();
    // 7) normalize + temperature + top-k mask + softmax + (attn1+..+attn4) scale
    softmax_k<<<2048, 64>>>(temp, a1, a2, a3, a4);
    // 8) out = P @ V
    {
        dim3 g(NPIX / 128, 32);
        av_k<<<g, 256>>>(out);
    }
}

// round 5
// speedup vs baseline: 1.5158x; 1.5158x over previous
#include <cuda_runtime.h>
#include <cuda_bf16.h>
#include <math.h>
#include <stdint.h>

// ---------------- problem constants ----------------
#define BB    8
#define DIMC  256
#define D3    768          // 3*DIM
#define HEADS 4
#define CH    64           // per-head channels
#define HH    128
#define WW    128
#define NPIX  16384        // H*W

// ---------------- scratch (device globals; no runtime alloc) ----------------
__device__ float g_qkv[100663296];   // [B,768,NPIX] post 1x1 conv        (402 MB)
__device__ float g_dwb[100663296];   // [B,768,NPIX] post depthwise conv  (402 MB)
__device__ float g_g1b[16777216];    // [B,128,NPIX] gate hidden          (67 MB)
__device__ float g_part[4194304];    // [32 chunks][32 bh][64][64] attn partials
__device__ float g_attn[131072];     // [32 bh][64][64]
__device__ float g_inv[4096];        // inverse L2 norms
__device__ float g_gatepart[512];
__device__ int   g_dk;

__device__ __nv_bfloat16 g_xhi[33554432];   // X split hi  [B,256,NPIX]
__device__ __nv_bfloat16 g_xlo[33554432];   // X split lo
__device__ __nv_bfloat16 g_whi[196608];     // w_qkv split [768,256]
__device__ __nv_bfloat16 g_wlo[196608];
__device__ __nv_bfloat16 g_gwhi[32768];     // gate_w1 split [128,256]
__device__ __nv_bfloat16 g_gwlo[32768];

// ================= bf16 split conversion: v = hi + lo =================
__global__ __launch_bounds__(256) void split_k(const float* __restrict__ in,
                                               __nv_bfloat16* __restrict__ hi,
                                               __nv_bfloat16* __restrict__ lo, int n4)
{
    const int i = blockIdx.x * 256 + threadIdx.x;
    if (i >= n4) return;
    const float4 v = ((const float4*)in)[i];
    __nv_bfloat16 h0 = __float2bfloat16(v.x);
    __nv_bfloat16 h1 = __float2bfloat16(v.y);
    __nv_bfloat16 h2 = __float2bfloat16(v.z);
    __nv_bfloat16 h3 = __float2bfloat16(v.w);
    __nv_bfloat162* H = (__nv_bfloat162*)hi;
    __nv_bfloat162* L = (__nv_bfloat162*)lo;
    H[i * 2 + 0] = __nv_bfloat162(h0, h1);
    H[i * 2 + 1] = __nv_bfloat162(h2, h3);
    L[i * 2 + 0] = __nv_bfloat162(__float2bfloat16(v.x - __bfloat162float(h0)),
                                  __float2bfloat16(v.y - __bfloat162float(h1)));
    L[i * 2 + 1] = __nv_bfloat162(__float2bfloat16(v.z - __bfloat162float(h2)),
                                  __float2bfloat16(v.w - __bfloat162float(h3)));
}

// ================= tensor-core bf16-split GEMM =================
// C[z] (MxN fp32) = (Ahi+Alo)(MxK) @ (Bhi+Blo)[z](KxN), dropping lo*lo.
// Block tile 128x128, k-step 32, 256 threads = 8 warps (2m x 4n), warp tile 64x32.
#define ASTR 40    // A smem row stride in bf16 (pad 32 -> 40, conflict-free ldmatrix)
#define BSTR 136   // B smem row stride in bf16 (pad 128 -> 136)

__device__ __forceinline__ uint32_t smem_u32(const void* p) {
    return (uint32_t)__cvta_generic_to_shared(p);
}
__device__ __forceinline__ void ldsm_x4(uint32_t* r, uint32_t a) {
    asm volatile("ldmatrix.sync.aligned.m8n8.x4.shared.b16 {%0,%1,%2,%3}, [%4];"
                 : "=r"(r[0]), "=r"(r[1]), "=r"(r[2]), "=r"(r[3]) : "r"(a));
}
__device__ __forceinline__ void ldsm_x2t(uint32_t* r, uint32_t a) {
    asm volatile("ldmatrix.sync.aligned.m8n8.x2.trans.shared.b16 {%0,%1}, [%2];"
                 : "=r"(r[0]), "=r"(r[1]) : "r"(a));
}
__device__ __forceinline__ void mma_bf16(float* c, const uint32_t* a, const uint32_t* b) {
    asm volatile("mma.sync.aligned.m16n8k16.row.col.f32.bf16.bf16.f32 "
                 "{%0,%1,%2,%3}, {%4,%5,%6,%7}, {%8,%9}, {%0,%1,%2,%3};"
                 : "+f"(c[0]), "+f"(c[1]), "+f"(c[2]), "+f"(c[3])
                 : "r"(a[0]), "r"(a[1]), "r"(a[2]), "r"(a[3]), "r"(b[0]), "r"(b[1]));
}

__global__ __launch_bounds__(256) void bfgemm_k(
    const __nv_bfloat16* __restrict__ Ahi, const __nv_bfloat16* __restrict__ Alo,
    const __nv_bfloat16* __restrict__ Bhi, const __nv_bfloat16* __restrict__ Blo,
    float* __restrict__ C, int M, int N, int K, long bStride, long cStride,
    const float* __restrict__ bias, int relu)
{
    const __nv_bfloat16* __restrict__ Bh = Bhi + (size_t)blockIdx.z * bStride;
    const __nv_bfloat16* __restrict__ Bl = Blo + (size_t)blockIdx.z * bStride;
    float* __restrict__ Cb = C + (size_t)blockIdx.z * cStride;
    const int m0 = blockIdx.y * 128, n0 = blockIdx.x * 128;

    __shared__ __nv_bfloat16 sAh[128 * ASTR], sAl[128 * ASTR];
    __shared__ __nv_bfloat16 sBh[32 * BSTR], sBl[32 * BSTR];

    const int tid = threadIdx.x;
    const int warp = tid >> 5, lane = tid & 31;
    const int wm = (warp & 1) * 64;     // warp m offset
    const int wn = (warp >> 1) * 32;    // warp n offset

    const int ar = tid >> 4, ac = tid & 15;   // A copy: row base, u32 col (k = 2*ac)
    const int br = tid >> 4, bc = tid & 15;   // B copy: k-row base, uint4 col (n = 8*bc)

    const uint32_t uAh = smem_u32(sAh), uAl = smem_u32(sAl);
    const uint32_t uBh = smem_u32(sBh), uBl = smem_u32(sBl);

    float acc[16][4];
#pragma unroll
    for (int f = 0; f < 16; f++)
#pragma unroll
        for (int r = 0; r < 4; r++) acc[f][r] = 0.f;

    // initial tile -> smem
#pragma unroll
    for (int p = 0; p < 8; p++) {
        const size_t ga = (size_t)(m0 + ar + p * 16) * K + ac * 2;
        ((uint32_t*)sAh)[(ar + p * 16) * (ASTR / 2) + ac] = *(const uint32_t*)(Ahi + ga);
        ((uint32_t*)sAl)[(ar + p * 16) * (ASTR / 2) + ac] = *(const uint32_t*)(Alo + ga);
    }
#pragma unroll
    for (int p = 0; p < 2; p++) {
        const size_t gb = (size_t)(br + p * 16) * N + n0 + bc * 8;
        ((uint4*)sBh)[(br + p * 16) * (BSTR / 8) + bc] = *(const uint4*)(Bh + gb);
        ((uint4*)sBl)[(br + p * 16) * (BSTR / 8) + bc] = *(const uint4*)(Bl + gb);
    }
    __syncthreads();

    const int nsteps = K >> 5;
    for (int it = 0; it < nsteps; it++) {
        uint32_t pah[8], pal[8];
        uint4 pbh[2], pbl[2];
        const bool more = (it + 1 < nsteps);
        if (more) {
            const int k0 = (it + 1) * 32;
#pragma unroll
            for (int p = 0; p < 8; p++) {
                const size_t ga = (size_t)(m0 + ar + p * 16) * K + k0 + ac * 2;
                pah[p] = *(const uint32_t*)(Ahi + ga);
                pal[p] = *(const uint32_t*)(Alo + ga);
            }
#pragma unroll
            for (int p = 0; p < 2; p++) {
                const size_t gb = (size_t)(k0 + br + p * 16) * N + n0 + bc * 8;
                pbh[p] = *(const uint4*)(Bh + gb);
                pbl[p] = *(const uint4*)(Bl + gb);
            }
        }

#pragma unroll
        for (int s = 0; s < 2; s++) {
            const int kk = s * 16;
            uint32_t ah[4][4], al[4][4], bh[4][2], bl[4][2];
#pragma unroll
            for (int f = 0; f < 4; f++) {
                const int mrow = wm + f * 16 + (lane & 15);
                const int kcol = kk + ((lane >> 4) & 1) * 8;
                const uint32_t off = (uint32_t)(mrow * ASTR + kcol) * 2;
                ldsm_x4(ah[f], uAh + off);
                ldsm_x4(al[f], uAl + off);
            }
#pragma unroll
            for (int g = 0; g < 4; g++) {
                const int krow = kk + (lane & 15);
                const int ncol = wn + g * 8;
                const uint32_t off = (uint32_t)(krow * BSTR + ncol) * 2;
                ldsm_x2t(bh[g], uBh + off);
                ldsm_x2t(bl[g], uBl + off);
            }
#pragma unroll
            for (int f = 0; f < 4; f++)
#pragma unroll
                for (int g = 0; g < 4; g++) mma_bf16(acc[f * 4 + g], ah[f], bh[g]);
#pragma unroll
            for (int f = 0; f < 4; f++)
#pragma unroll
                for (int g = 0; g < 4; g++) mma_bf16(acc[f * 4 + g], ah[f], bl[g]);
#pragma unroll
            for (int f = 0; f < 4; f++)
#pragma unroll
                for (int g = 0; g < 4; g++) mma_bf16(acc[f * 4 + g], al[f], bh[g]);
        }
        __syncthreads();
        if (more) {
#pragma unroll
            for (int p = 0; p < 8; p++) {
                ((uint32_t*)sAh)[(ar + p * 16) * (ASTR / 2) + ac] = pah[p];
                ((uint32_t*)sAl)[(ar + p * 16) * (ASTR / 2) + ac] = pal[p];
            }
#pragma unroll
            for (int p = 0; p < 2; p++) {
                ((uint4*)sBh)[(br + p * 16) * (BSTR / 8) + bc] = pbh[p];
                ((uint4*)sBl)[(br + p * 16) * (BSTR / 8) + bc] = pbl[p];
            }
            __syncthreads();
        }
    }

    // epilogue
    const int gid = lane >> 2, t4 = lane & 3;
#pragma unroll
    for (int f = 0; f < 4; f++) {
#pragma unroll
        for (int g = 0; g < 4; g++) {
            const int row = m0 + wm + f * 16 + gid;
            const int col = n0 + wn + g * 8 + t4 * 2;
            const float* a = acc[f * 4 + g];
            float bv0 = bias ? bias[row] : 0.f;
            float bv1 = bias ? bias[row + 8] : 0.f;
            float2 v0 = make_float2(a[0] + bv0, a[1] + bv0);
            float2 v1 = make_float2(a[2] + bv1, a[3] + bv1);
            if (relu) {
                v0.x = fmaxf(v0.x, 0.f); v0.y = fmaxf(v0.y, 0.f);
                v1.x = fmaxf(v1.x, 0.f); v1.y = fmaxf(v1.y, 0.f);
            }
            *(float2*)(Cb + (size_t)row * N + col) = v0;
            *(float2*)(Cb + (size_t)(row + 8) * N + col) = v1;
        }
    }
}

// ================= depthwise 3x3 (SAME, zero pad), g_qkv -> g_dwb =================
__global__ __launch_bounds__(128) void dwconv_k(const float* __restrict__ wdw)
{
    const int x  = threadIdx.x;
    const int y  = blockIdx.x & (HH - 1);
    const int bc = blockIdx.x >> 7;
    const int ch = bc % D3;
    const float* __restrict__ w = wdw + ch * 9;
    const float* __restrict__ in = g_qkv + (size_t)bc * NPIX;

    float acc = 0.f;
#pragma unroll
    for (int dy = -1; dy <= 1; dy++) {
        const int yy = y + dy;
        if ((unsigned)yy < HH) {
            const float* r = in + yy * WW;
#pragma unroll
            for (int dx = -1; dx <= 1; dx++) {
                const int xx = x + dx;
                if ((unsigned)xx < WW)
                    acc += __ldg(r + xx) * __ldg(w + (dy + 1) * 3 + (dx + 1));
            }
        }
    }
    g_dwb[(size_t)bc * NPIX + y * WW + x] = acc;
}

// ================= gate stage 2 =================
__global__ __launch_bounds__(256) void gate2_k(const float* __restrict__ w2,
                                               const float* __restrict__ b2)
{
    __shared__ float w2s[128];
    const int tid = threadIdx.x;
    if (tid < 128) w2s[tid] = w2[tid];
    __syncthreads();

    const int pg = blockIdx.x * 256 + tid;
    const int b  = pg >> 14;
    const int p  = pg & (NPIX - 1);
    const float* __restrict__ g = g_g1b + (size_t)b * 128 * NPIX + p;

    float acc = b2[0];
#pragma unroll 8
    for (int j = 0; j < 128; j++) acc += w2s[j] * g[(size_t)j * NPIX];
    const float sig = 1.f / (1.f + expf(-acc));

    __shared__ float red[256];
    red[tid] = sig;
    __syncthreads();
    for (int s = 128; s > 0; s >>= 1) {
        if (tid < s) red[tid] += red[tid + s];
        __syncthreads();
    }
    if (tid == 0) g_gatepart[blockIdx.x] = red[0];
}

// ================= dynamic-k =================
__global__ void dk_k()
{
    __shared__ float red[256];
    const int tid = threadIdx.x;
    float s = 0.f;
    for (int i = tid; i < 512; i += 256) s += g_gatepart[i];
    red[tid] = s;
    __syncthreads();
    for (int st = 128; st > 0; st >>= 1) {
        if (tid < st) red[tid] += red[tid + st];
        __syncthreads();
    }
    if (tid == 0) {
        const float mean = red[0] / (float)(BB * NPIX);
        int dk = (int)floorf(64.f * mean);
        if (dk < 1) dk = 1;
        if (dk > 64) dk = 64;
        g_dk = dk;
    }
}

// ================= inverse L2 norms of q & k rows =================
__global__ __launch_bounds__(256) void norm_k()
{
    const int idx = blockIdx.x;
    const int b = idx >> 9, ch = idx & 511;
    const float* __restrict__ row = g_dwb + (size_t)(b * D3 + ch) * NPIX;
    const int tid = threadIdx.x;

    float s = 0.f;
    for (int p = tid; p < NPIX; p += 256) { const float v = row[p]; s += v * v; }
#pragma unroll
    for (int o = 16; o > 0; o >>= 1) s += __shfl_down_sync(0xffffffffu, s, o);

    __shared__ float ws[8];
    if ((tid & 31) == 0) ws[tid >> 5] = s;
    __syncthreads();
    if (tid == 0) {
        float t = 0.f;
#pragma unroll
        for (int i = 0; i < 8; i++) t += ws[i];
        g_inv[idx] = 1.f / fmaxf(sqrtf(t), 1e-12f);
    }
}

// ================= attn partials =================
__global__ __launch_bounds__(256) void attn_partial_k()
{
    const int bh = blockIdx.y;
    const int b = bh >> 2, h = bh & 3;
    const float* __restrict__ Q = g_dwb + (size_t)b * D3 * NPIX + (size_t)(h * CH) * NPIX;
    const float* __restrict__ Kp = g_dwb + (size_t)b * D3 * NPIX + (size_t)(256 + h * CH) * NPIX;
    const int n0c = blockIdx.x * 512;

    __shared__ float Qs[64][66];
    __shared__ float Ks[64][66];

    const int tid = threadIdx.x;
    const int tx = tid & 15, ty = tid >> 4;

    float acc[4][4];
#pragma unroll
    for (int i = 0; i < 4; i++)
#pragma unroll
        for (int j = 0; j < 4; j++) acc[i][j] = 0.f;

    for (int ns = 0; ns < 512; ns += 64) {
        const int n0 = n0c + ns;
#pragma unroll
        for (int e = 0; e < 16; e++) {
            const int idx = tid + e * 256;
            const int c = idx >> 6, nn = idx & 63;
            Qs[nn][c] = Q[(size_t)c * NPIX + n0 + nn];
            Ks[nn][c] = Kp[(size_t)c * NPIX + n0 + nn];
        }
        __syncthreads();
#pragma unroll 16
        for (int kk = 0; kk < 64; kk++) {
            float a[4], bv[4];
#pragma unroll
            for (int i = 0; i < 4; i++) a[i] = Qs[kk][ty * 4 + i];
#pragma unroll
            for (int j = 0; j < 4; j++) bv[j] = Ks[kk][tx * 4 + j];
#pragma unroll
            for (int i = 0; i < 4; i++)
#pragma unroll
                for (int j = 0; j < 4; j++) acc[i][j] += a[i] * bv[j];
        }
        __syncthreads();
    }

    const int base = (blockIdx.x * 32 + bh) * 4096;
#pragma unroll
    for (int i = 0; i < 4; i++)
#pragma unroll
        for (int j = 0; j < 4; j++)
            g_part[base + (ty * 4 + i) * 64 + tx * 4 + j] = acc[i][j];
}

__global__ __launch_bounds__(256) void attn_reduce_k()
{
    const int i = blockIdx.x * 256 + threadIdx.x;
    float s = 0.f;
#pragma unroll
    for (int c = 0; c < 32; c++) s += g_part[c * 131072 + i];
    g_attn[i] = s;
}

// ================= softmax + top-k =================
__global__ __launch_bounds__(64) void softmax_k(const float* __restrict__ temp,
                                                const float* __restrict__ a1,
                                                const float* __restrict__ a2,
                                                const float* __restrict__ a3,
                                                const float* __restrict__ a4)
{
    const int row = blockIdx.x;
    const int bh = row >> 6, c = row & 63;
    const int b = bh >> 2, h = bh & 3;
    const int d = threadIdx.x;

    const float invq = g_inv[b * 512 + h * CH + c];
    const float invk = g_inv[b * 512 + 256 + h * CH + d];
    const float a = g_attn[row * 64 + d] * invq * invk * temp[h];

    __shared__ float sv[64], se[64];
    sv[d] = a;
    __syncthreads();

    const int dk = g_dk;
    int rank = 0;
    float mx = -3.4e38f;
#pragma unroll 8
    for (int j = 0; j < 64; j++) {
        const float v = sv[j];
        rank += (v > a);
        mx = fmaxf(mx, v);
    }
    se[d] = (rank < dk) ? a : 3.4e38f;
    __syncthreads();
    float t = 3.4e38f;
#pragma unroll 8
    for (int j = 0; j < 64; j++) t = fminf(t, se[j]);
    __syncthreads();

    const float e = (a >= t) ? expf(a - mx) : 0.f;
    se[d] = e;
    __syncthreads();
    float sum = 0.f;
#pragma unroll 8
    for (int j = 0; j < 64; j++) sum += se[j];

    const float s4 = a1[0] + a2[0] + a3[0] + a4[0];
    g_attn[row * 64 + d] = e / sum * s4;
}

// ================= out = P @ V =================
__global__ __launch_bounds__(256) void av_k(float* __restrict__ out)
{
    const int bh = blockIdx.y;
    const int b = bh >> 2, h = bh & 3;
    const float* __restrict__ Pm = g_attn + bh * 4096;
    const float* __restrict__ V = g_dwb + (size_t)b * D3 * NPIX + (size_t)(512 + h * CH) * NPIX;
    float* __restrict__ O = out + (size_t)b * DIMC * NPIX + (size_t)(h * CH) * NPIX;

    __shared__ float As[64][68];
    const int tid = threadIdx.x;
    for (int e = tid; e < 4096; e += 256) {
        const int cc = e >> 6, dd = e & 63;
        As[dd][cc] = Pm[e];
    }
    __syncthreads();

    const int tx = tid & 31, ty = tid >> 5;
    const int n = blockIdx.x * 128 + tx * 4;

    float acc[8][4];
#pragma unroll
    for (int i = 0; i < 8; i++)
#pragma unroll
        for (int j = 0; j < 4; j++) acc[i][j] = 0.f;

#pragma unroll 8
    for (int dd = 0; dd < 64; dd++) {
        const float4 v = *(const float4*)(V + (size_t)dd * NPIX + n);
        float a[8];
#pragma unroll
        for (int i = 0; i < 8; i++) a[i] = As[dd][ty * 8 + i];
#pragma unroll
        for (int i = 0; i < 8; i++) {
            acc[i][0] += a[i] * v.x;
            acc[i][1] += a[i] * v.y;
            acc[i][2] += a[i] * v.z;
            acc[i][3] += a[i] * v.w;
        }
    }
#pragma unroll
    for (int i = 0; i < 8; i++) {
        float4 o;
        o.x = acc[i][0]; o.y = acc[i][1]; o.z = acc[i][2]; o.w = acc[i][3];
        *(float4*)(O + (size_t)(ty * 8 + i) * NPIX + n) = o;
    }
}

// ================================ launch ================================
extern "C" void kernel_launch(void* const* d_in, const int* in_sizes, int n_in,
                              void* d_out, int out_size)
{
    (void)in_sizes; (void)n_in; (void)out_size;
    const float* x     = (const float*)d_in[0];
    const float* w_qkv = (const float*)d_in[1];
    const float* w_dw  = (const float*)d_in[2];
    const float* temp  = (const float*)d_in[3];
    const float* a1    = (const float*)d_in[4];
    const float* a2    = (const float*)d_in[5];
    const float* a3    = (const float*)d_in[6];
    const float* a4    = (const float*)d_in[7];
    const float* gw1   = (const float*)d_in[8];
    const float* gb1   = (const float*)d_in[9];
    const float* gw2   = (const float*)d_in[10];
    const float* gb2   = (const float*)d_in[11];
    float* out = (float*)d_out;

    void *p_qkv, *p_g1, *p_xhi, *p_xlo, *p_whi, *p_wlo, *p_gwhi, *p_gwlo;
    cudaGetSymbolAddress(&p_qkv, g_qkv);
    cudaGetSymbolAddress(&p_g1, g_g1b);
    cudaGetSymbolAddress(&p_xhi, g_xhi);
    cudaGetSymbolAddress(&p_xlo, g_xlo);
    cudaGetSymbolAddress(&p_whi, g_whi);
    cudaGetSymbolAddress(&p_wlo, g_wlo);
    cudaGetSymbolAddress(&p_gwhi, g_gwhi);
    cudaGetSymbolAddress(&p_gwlo, g_gwlo);

    // 0) bf16 splits
    split_k<<<(33554432 / 4 + 255) / 256, 256>>>(x, (__nv_bfloat16*)p_xhi, (__nv_bfloat16*)p_xlo, 33554432 / 4);
    split_k<<<(196608 / 4 + 255) / 256, 256>>>(w_qkv, (__nv_bfloat16*)p_whi, (__nv_bfloat16*)p_wlo, 196608 / 4);
    split_k<<<(32768 / 4 + 255) / 256, 256>>>(gw1, (__nv_bfloat16*)p_gwhi, (__nv_bfloat16*)p_gwlo, 32768 / 4);

    // 1) qkv = W_qkv @ X[b]   (tensor cores, bf16 3-term split)
    {
        dim3 g(NPIX / 128, D3 / 128, BB);
        bfgemm_k<<<g, 256>>>((const __nv_bfloat16*)p_whi, (const __nv_bfloat16*)p_wlo,
                             (const __nv_bfloat16*)p_xhi, (const __nv_bfloat16*)p_xlo,
                             (float*)p_qkv, D3, NPIX, DIMC,
                             (long)DIMC * NPIX, (long)D3 * NPIX, nullptr, 0);
    }
    // 2) gate hidden g1 = relu(Gw1 @ X[b] + b1)
    {
        dim3 g(NPIX / 128, 1, BB);
        bfgemm_k<<<g, 256>>>((const __nv_bfloat16*)p_gwhi, (const __nv_bfloat16*)p_gwlo,
                             (const __nv_bfloat16*)p_xhi, (const __nv_bfloat16*)p_xlo,
                             (float*)p_g1, 128, NPIX, DIMC,
                             (long)DIMC * NPIX, (long)128 * NPIX, gb1, 1);
    }
    // 3) depthwise 3x3
    dwconv_k<<<BB * D3 * HH, 128>>>(w_dw);
    // 4) gate stage 2 + dk
    gate2_k<<<512, 256>>>(gw2, gb2);
    dk_k<<<1, 256>>>();
    // 5) q/k inverse norms
    norm_k<<<4096, 256>>>();
    // 6) attention S = Q K^T
    {
        dim3 g(32, 32);
        attn_partial_k<<<g, 256>>>();
    }
    attn_reduce_k<<<512, 256>>>();
    // 7) softmax with top-k
    softmax_k<<<2048, 64>>>(temp, a1, a2, a3, a4);
    // 8) out = P @ V
    {
        dim3 g(NPIX / 128, 32);
        av_k<<<g, 256>>>(out);
    }
}

// round 8
// speedup vs baseline: 2.0067x; 1.3239x over previous
#include <cuda_runtime.h>
#include <cuda_bf16.h>
#include <math.h>
#include <stdint.h>

// ---------------- problem constants ----------------
#define BB    8
#define DIMC  256
#define D3    768          // 3*DIM
#define HEADS 4
#define CH    64           // per-head channels
#define HH    128
#define WW    128
#define NPIX  16384        // H*W
#define MTOT  896          // 768 qkv rows + 128 gate rows (fused GEMM)

// ---------------- scratch (device globals; no runtime alloc) ----------------
__device__ float g_qkv[100663296];   // [B,768,NPIX] post 1x1 conv
__device__ float g_dwb[100663296];   // [B,768,NPIX] post depthwise conv
__device__ float g_g1b[16777216];    // [B,128,NPIX] gate hidden
__device__ float g_part[4194304];    // [32 chunks][32 bh][64][64] attn partials
__device__ float g_attn[131072];     // [32 bh][64][64]
__device__ float g_inv[4096];        // inverse L2 norms
__device__ float g_normpart[65536];  // [b*512+ch][16] sum-of-square partials
__device__ float g_gatepart[512];
__device__ int   g_dk;

__device__ __nv_bfloat16 g_xhi[33554432];   // X split hi  [B,256,NPIX]
__device__ __nv_bfloat16 g_xlo[33554432];   // X split lo
__device__ __nv_bfloat16 g_wchi[229376];    // combined weights split [896,256]
__device__ __nv_bfloat16 g_wclo[229376];

// ================= bf16 split conversion: v = hi + lo =================
__global__ __launch_bounds__(256) void split_k(const float* __restrict__ in,
                                               __nv_bfloat16* __restrict__ hi,
                                               __nv_bfloat16* __restrict__ lo, int n4)
{
    const int i = blockIdx.x * 256 + threadIdx.x;
    if (i >= n4) return;
    const float4 v = ((const float4*)in)[i];
    __nv_bfloat16 h0 = __float2bfloat16(v.x);
    __nv_bfloat16 h1 = __float2bfloat16(v.y);
    __nv_bfloat16 h2 = __float2bfloat16(v.z);
    __nv_bfloat16 h3 = __float2bfloat16(v.w);
    __nv_bfloat162* H = (__nv_bfloat162*)hi;
    __nv_bfloat162* L = (__nv_bfloat162*)lo;
    H[i * 2 + 0] = __nv_bfloat162(h0, h1);
    H[i * 2 + 1] = __nv_bfloat162(h2, h3);
    L[i * 2 + 0] = __nv_bfloat162(__float2bfloat16(v.x - __bfloat162float(h0)),
                                  __float2bfloat16(v.y - __bfloat162float(h1)));
    L[i * 2 + 1] = __nv_bfloat162(__float2bfloat16(v.z - __bfloat162float(h2)),
                                  __float2bfloat16(v.w - __bfloat162float(h3)));
}

// ================= tensor-core bf16-split GEMM (cp.async, static smem) =============
// C (896 x 16384 per batch) = Wc(896x256) @ X[b](256x16384), split hi/lo, 3 terms.
// Rows 0..767 -> g_qkv, rows 768..895 -> g_g1b with bias+relu.
// Block tile 128x128, k-step 16, 256 threads = 8 warps (2m x 4n), double-buffered
// STATIC shared memory (41984 B total -> no cudaFuncSetAttribute, no dynamic smem).
#define ASTR3 24        // A smem row stride in bf16 (48 B rows, 16B aligned)
#define BSTR3 136       // B smem row stride in bf16 (272 B rows)
#define OFF3_AL 6144
#define OFF3_BH 12288
#define OFF3_BL 16640
#define STAGE3  20992   // bytes per stage

__device__ __forceinline__ uint32_t smem_u32(const void* p) {
    return (uint32_t)__cvta_generic_to_shared(p);
}
__device__ __forceinline__ void cp16(uint32_t dst, const void* src) {
    asm volatile("cp.async.cg.shared.global [%0], [%1], 16;\n" :: "r"(dst), "l"(src));
}
__device__ __forceinline__ void ldsm_x4(uint32_t* r, uint32_t a) {
    asm volatile("ldmatrix.sync.aligned.m8n8.x4.shared.b16 {%0,%1,%2,%3}, [%4];"
                 : "=r"(r[0]), "=r"(r[1]), "=r"(r[2]), "=r"(r[3]) : "r"(a));
}
__device__ __forceinline__ void ldsm_x2t(uint32_t* r, uint32_t a) {
    asm volatile("ldmatrix.sync.aligned.m8n8.x2.trans.shared.b16 {%0,%1}, [%2];"
                 : "=r"(r[0]), "=r"(r[1]) : "r"(a));
}
__device__ __forceinline__ void mma_bf16(float* c, const uint32_t* a, const uint32_t* b) {
    asm volatile("mma.sync.aligned.m16n8k16.row.col.f32.bf16.bf16.f32 "
                 "{%0,%1,%2,%3}, {%4,%5,%6,%7}, {%8,%9}, {%0,%1,%2,%3};"
                 : "+f"(c[0]), "+f"(c[1]), "+f"(c[2]), "+f"(c[3])
                 : "r"(a[0]), "r"(a[1]), "r"(a[2]), "r"(a[3]), "r"(b[0]), "r"(b[1]));
}

__global__ __launch_bounds__(256, 2) void bfgemm3_k(
    const __nv_bfloat16* __restrict__ Ahi, const __nv_bfloat16* __restrict__ Alo,
    const __nv_bfloat16* __restrict__ Xhi, const __nv_bfloat16* __restrict__ Xlo,
    float* __restrict__ Cqkv, float* __restrict__ Cg1,
    const float* __restrict__ gb1)
{
    __shared__ alignas(16) char sm[2 * STAGE3];
    const int z = blockIdx.z;
    const __nv_bfloat16* __restrict__ Bh = Xhi + (size_t)z * DIMC * NPIX;
    const __nv_bfloat16* __restrict__ Bl = Xlo + (size_t)z * DIMC * NPIX;
    const int m0 = blockIdx.y * 128, n0 = blockIdx.x * 128;

    const int tid = threadIdx.x;
    const int warp = tid >> 5, lane = tid & 31;
    const int wm = (warp & 1) * 64;
    const int wn = (warp >> 1) * 32;

    const uint32_t uS = smem_u32(sm);

    // copy-thread mapping (one 16B chunk per tensor per thread per stage)
    const int aRow = tid >> 1, aKc = tid & 1;    // A: 128 rows x 2 chunks
    const int bRow = tid >> 4, bNc = tid & 15;   // B: 16 rows x 16 chunks

    float acc[16][4];
#pragma unroll
    for (int f = 0; f < 16; f++)
#pragma unroll
        for (int r = 0; r < 4; r++) acc[f][r] = 0.f;

    auto copy_stage = [&](int buf, int k0) {
        const uint32_t sb = uS + buf * STAGE3;
        {
            const size_t ga = (size_t)(m0 + aRow) * DIMC + k0 + aKc * 8;
            const uint32_t so = (uint32_t)aRow * 48 + aKc * 16;
            cp16(sb + so, Ahi + ga);
            cp16(sb + OFF3_AL + so, Alo + ga);
        }
        {
            const size_t gb = (size_t)(k0 + bRow) * NPIX + n0 + bNc * 8;
            const uint32_t so = (uint32_t)bRow * 272 + bNc * 16;
            cp16(sb + OFF3_BH + so, Bh + gb);
            cp16(sb + OFF3_BL + so, Bl + gb);
        }
    };

    copy_stage(0, 0);
    asm volatile("cp.async.commit_group;\n");

    const int nsteps = DIMC / 16;  // 16
    for (int it = 0; it < nsteps; it++) {
        if (it + 1 < nsteps) {
            copy_stage((it + 1) & 1, (it + 1) * 16);
            asm volatile("cp.async.commit_group;\n");
            asm volatile("cp.async.wait_group 1;\n");
        } else {
            asm volatile("cp.async.wait_group 0;\n");
        }
        __syncthreads();

        const uint32_t sb = uS + (it & 1) * STAGE3;
        uint32_t ah[4][4], al[4][4];
#pragma unroll
        for (int f = 0; f < 4; f++) {
            const int mrow = wm + f * 16 + (lane & 15);
            const int kcol = ((lane >> 4) & 1) * 8;
            const uint32_t off = (uint32_t)(mrow * ASTR3 + kcol) * 2;
            ldsm_x4(ah[f], sb + off);
            ldsm_x4(al[f], sb + OFF3_AL + off);
        }
#pragma unroll
        for (int g = 0; g < 4; g++) {
            const int krow = lane & 15;
            const int ncol = wn + g * 8;
            const uint32_t boff = (uint32_t)(krow * BSTR3 + ncol) * 2;
            uint32_t bh[2], bl[2];
            ldsm_x2t(bh, sb + OFF3_BH + boff);
            ldsm_x2t(bl, sb + OFF3_BL + boff);
#pragma unroll
            for (int f = 0; f < 4; f++) {
                mma_bf16(acc[f * 4 + g], ah[f], bh);
                mma_bf16(acc[f * 4 + g], ah[f], bl);
                mma_bf16(acc[f * 4 + g], al[f], bh);
            }
        }
        __syncthreads();
    }

    // ---- epilogue: route to qkv or gate ----
    const int gid = lane >> 2, t4 = lane & 3;
    const bool isGate = (m0 >= D3);
    float* __restrict__ Cb = isGate ? (Cg1 + (size_t)z * 128 * NPIX)
                                    : (Cqkv + (size_t)z * D3 * NPIX);
    const int mAdj = isGate ? (m0 - D3) : m0;
#pragma unroll
    for (int f = 0; f < 4; f++) {
#pragma unroll
        for (int g = 0; g < 4; g++) {
            const int row = mAdj + wm + f * 16 + gid;
            const int col = n0 + wn + g * 8 + t4 * 2;
            const float* a = acc[f * 4 + g];
            float bv0 = 0.f, bv1 = 0.f;
            if (isGate) { bv0 = gb1[row]; bv1 = gb1[row + 8]; }
            float2 v0 = make_float2(a[0] + bv0, a[1] + bv0);
            float2 v1 = make_float2(a[2] + bv1, a[3] + bv1);
            if (isGate) {
                v0.x = fmaxf(v0.x, 0.f); v0.y = fmaxf(v0.y, 0.f);
                v1.x = fmaxf(v1.x, 0.f); v1.y = fmaxf(v1.y, 0.f);
            }
            *(float2*)(Cb + (size_t)row * NPIX + col) = v0;
            *(float2*)(Cb + (size_t)(row + 8) * NPIX + col) = v1;
        }
    }
}

// ================= depthwise 3x3 (8 rows/block) + fused q/k sumsq partials =========
__global__ __launch_bounds__(128) void dwconv2_k(const float* __restrict__ wdw)
{
    const int x     = threadIdx.x;
    const int ytile = blockIdx.x & 15;
    const int bc    = blockIdx.x >> 4;          // b*768 + ch
    const int ch    = bc % D3;
    const int b     = bc / D3;
    const int y0    = ytile * 8;
    const float* __restrict__ in = g_qkv + (size_t)bc * NPIX;
    float* __restrict__ outp = g_dwb + (size_t)bc * NPIX;

    __shared__ float s[10][130];
    __shared__ float red[4];

#pragma unroll
    for (int r = 0; r < 10; r++) {
        const int yy = y0 - 1 + r;
        s[r][x + 1] = ((unsigned)yy < HH) ? in[yy * WW + x] : 0.f;
    }
    if (x == 0) {
#pragma unroll
        for (int r = 0; r < 10; r++) { s[r][0] = 0.f; s[r][129] = 0.f; }
    }
    __syncthreads();

    float w[9];
#pragma unroll
    for (int i = 0; i < 9; i++) w[i] = __ldg(wdw + ch * 9 + i);

    float sq = 0.f;
#pragma unroll
    for (int oy = 0; oy < 8; oy++) {
        float acc = 0.f;
#pragma unroll
        for (int dy = 0; dy < 3; dy++)
#pragma unroll
            for (int dx = 0; dx < 3; dx++)
                acc += s[oy + dy][x + dx] * w[dy * 3 + dx];
        outp[(y0 + oy) * WW + x] = acc;
        sq += acc * acc;
    }

    if (ch < 512) {
#pragma unroll
        for (int o = 16; o > 0; o >>= 1) sq += __shfl_down_sync(0xffffffffu, sq, o);
        if ((x & 31) == 0) red[x >> 5] = sq;
        __syncthreads();
        if (x == 0)
            g_normpart[(b * 512 + ch) * 16 + ytile] = red[0] + red[1] + red[2] + red[3];
    }
}

// ================= finish inverse norms from partials =================
__global__ __launch_bounds__(256) void norm2_k()
{
    const int r = blockIdx.x * 256 + threadIdx.x;   // 0..4095
    if (r >= 4096) return;
    float s = 0.f;
#pragma unroll
    for (int i = 0; i < 16; i++) s += g_normpart[r * 16 + i];
    g_inv[r] = 1.f / fmaxf(sqrtf(s), 1e-12f);
}

// ================= gate stage 2 =================
__global__ __launch_bounds__(256) void gate2_k(const float* __restrict__ w2,
                                               const float* __restrict__ b2)
{
    __shared__ float w2s[128];
    const int tid = threadIdx.x;
    if (tid < 128) w2s[tid] = w2[tid];
    __syncthreads();

    const int pg = blockIdx.x * 256 + tid;
    const int b  = pg >> 14;
    const int p  = pg & (NPIX - 1);
    const float* __restrict__ g = g_g1b + (size_t)b * 128 * NPIX + p;

    float acc = b2[0];
#pragma unroll 8
    for (int j = 0; j < 128; j++) acc += w2s[j] * g[(size_t)j * NPIX];
    const float sig = 1.f / (1.f + expf(-acc));

    __shared__ float red[256];
    red[tid] = sig;
    __syncthreads();
    for (int s = 128; s > 0; s >>= 1) {
        if (tid < s) red[tid] += red[tid + s];
        __syncthreads();
    }
    if (tid == 0) g_gatepart[blockIdx.x] = red[0];
}

// ================= dynamic-k =================
__global__ void dk_k()
{
    __shared__ float red[256];
    const int tid = threadIdx.x;
    float s = 0.f;
    for (int i = tid; i < 512; i += 256) s += g_gatepart[i];
    red[tid] = s;
    __syncthreads();
    for (int st = 128; st > 0; st >>= 1) {
        if (tid < st) red[tid] += red[tid + st];
        __syncthreads();
    }
    if (tid == 0) {
        const float mean = red[0] / (float)(BB * NPIX);
        int dk = (int)floorf(64.f * mean);
        if (dk < 1) dk = 1;
        if (dk > 64) dk = 64;
        g_dk = dk;
    }
}

// ================= attn partials =================
__global__ __launch_bounds__(256) void attn_partial_k()
{
    const int bh = blockIdx.y;
    const int b = bh >> 2, h = bh & 3;
    const float* __restrict__ Q = g_dwb + (size_t)b * D3 * NPIX + (size_t)(h * CH) * NPIX;
    const float* __restrict__ Kp = g_dwb + (size_t)b * D3 * NPIX + (size_t)(256 + h * CH) * NPIX;
    const int n0c = blockIdx.x * 512;

    __shared__ float Qs[64][66];
    __shared__ float Ks[64][66];

    const int tid = threadIdx.x;
    const int tx = tid & 15, ty = tid >> 4;

    float acc[4][4];
#pragma unroll
    for (int i = 0; i < 4; i++)
#pragma unroll
        for (int j = 0; j < 4; j++) acc[i][j] = 0.f;

    for (int ns = 0; ns < 512; ns += 64) {
        const int n0 = n0c + ns;
#pragma unroll
        for (int e = 0; e < 16; e++) {
            const int idx = tid + e * 256;
            const int c = idx >> 6, nn = idx & 63;
            Qs[nn][c] = Q[(size_t)c * NPIX + n0 + nn];
            Ks[nn][c] = Kp[(size_t)c * NPIX + n0 + nn];
        }
        __syncthreads();
#pragma unroll 16
        for (int kk = 0; kk < 64; kk++) {
            float a[4], bv[4];
#pragma unroll
            for (int i = 0; i < 4; i++) a[i] = Qs[kk][ty * 4 + i];
#pragma unroll
            for (int j = 0; j < 4; j++) bv[j] = Ks[kk][tx * 4 + j];
#pragma unroll
            for (int i = 0; i < 4; i++)
#pragma unroll
                for (int j = 0; j < 4; j++) acc[i][j] += a[i] * bv[j];
        }
        __syncthreads();
    }

    const int base = (blockIdx.x * 32 + bh) * 4096;
#pragma unroll
    for (int i = 0; i < 4; i++)
#pragma unroll
        for (int j = 0; j < 4; j++)
            g_part[base + (ty * 4 + i) * 64 + tx * 4 + j] = acc[i][j];
}

__global__ __launch_bounds__(256) void attn_reduce_k()
{
    const int i = blockIdx.x * 256 + threadIdx.x;
    float s = 0.f;
#pragma unroll
    for (int c = 0; c < 32; c++) s += g_part[c * 131072 + i];
    g_attn[i] = s;
}

// ================= softmax + top-k =================
__global__ __launch_bounds__(64) void softmax_k(const float* __restrict__ temp,
                                                const float* __restrict__ a1,
                                                const float* __restrict__ a2,
                                                const float* __restrict__ a3,
                                                const float* __restrict__ a4)
{
    const int row = blockIdx.x;
    const int bh = row >> 6, c = row & 63;
    const int b = bh >> 2, h = bh & 3;
    const int d = threadIdx.x;

    const float invq = g_inv[b * 512 + h * CH + c];
    const float invk = g_inv[b * 512 + 256 + h * CH + d];
    const float a = g_attn[row * 64 + d] * invq * invk * temp[h];

    __shared__ float sv[64], se[64];
    sv[d] = a;
    __syncthreads();

    const int dk = g_dk;
    int rank = 0;
    float mx = -3.4e38f;
#pragma unroll 8
    for (int j = 0; j < 64; j++) {
        const float v = sv[j];
        rank += (v > a);
        mx = fmaxf(mx, v);
    }
    se[d] = (rank < dk) ? a : 3.4e38f;
    __syncthreads();
    float t = 3.4e38f;
#pragma unroll 8
    for (int j = 0; j < 64; j++) t = fminf(t, se[j]);
    __syncthreads();

    const float e = (a >= t) ? expf(a - mx) : 0.f;
    se[d] = e;
    __syncthreads();
    float sum = 0.f;
#pragma unroll 8
    for (int j = 0; j < 64; j++) sum += se[j];

    const float s4 = a1[0] + a2[0] + a3[0] + a4[0];
    g_attn[row * 64 + d] = e / sum * s4;
}

// ================= out = P @ V =================
__global__ __launch_bounds__(256) void av_k(float* __restrict__ out)
{
    const int bh = blockIdx.y;
    const int b = bh >> 2, h = bh & 3;
    const float* __restrict__ Pm = g_attn + bh * 4096;
    const float* __restrict__ V = g_dwb + (size_t)b * D3 * NPIX + (size_t)(512 + h * CH) * NPIX;
    float* __restrict__ O = out + (size_t)b * DIMC * NPIX + (size_t)(h * CH) * NPIX;

    __shared__ float As[64][68];
    const int tid = threadIdx.x;
    for (int e = tid; e < 4096; e += 256) {
        const int cc = e >> 6, dd = e & 63;
        As[dd][cc] = Pm[e];
    }
    __syncthreads();

    const int tx = tid & 31, ty = tid >> 5;
    const int n = blockIdx.x * 128 + tx * 4;

    float acc[8][4];
#pragma unroll
    for (int i = 0; i < 8; i++)
#pragma unroll
        for (int j = 0; j < 4; j++) acc[i][j] = 0.f;

#pragma unroll 8
    for (int dd = 0; dd < 64; dd++) {
        const float4 v = *(const float4*)(V + (size_t)dd * NPIX + n);
        float a[8];
#pragma unroll
        for (int i = 0; i < 8; i++) a[i] = As[dd][ty * 8 + i];
#pragma unroll
        for (int i = 0; i < 8; i++) {
            acc[i][0] += a[i] * v.x;
            acc[i][1] += a[i] * v.y;
            acc[i][2] += a[i] * v.z;
            acc[i][3] += a[i] * v.w;
        }
    }
#pragma unroll
    for (int i = 0; i < 8; i++) {
        float4 o;
        o.x = acc[i][0]; o.y = acc[i][1]; o.z = acc[i][2]; o.w = acc[i][3];
        *(float4*)(O + (size_t)(ty * 8 + i) * NPIX + n) = o;
    }
}

// ================================ launch ================================
extern "C" void kernel_launch(void* const* d_in, const int* in_sizes, int n_in,
                              void* d_out, int out_size)
{
    (void)in_sizes; (void)n_in; (void)out_size;
    const float* x     = (const float*)d_in[0];
    const float* w_qkv = (const float*)d_in[1];
    const float* w_dw  = (const float*)d_in[2];
    const float* temp  = (const float*)d_in[3];
    const float* a1    = (const float*)d_in[4];
    const float* a2    = (const float*)d_in[5];
    const float* a3    = (const float*)d_in[6];
    const float* a4    = (const float*)d_in[7];
    const float* gw1   = (const float*)d_in[8];
    const float* gb1   = (const float*)d_in[9];
    const float* gw2   = (const float*)d_in[10];
    const float* gb2   = (const float*)d_in[11];
    float* out = (float*)d_out;

    void *p_qkv, *p_g1, *p_xhi, *p_xlo, *p_wchi, *p_wclo;
    cudaGetSymbolAddress(&p_qkv, g_qkv);
    cudaGetSymbolAddress(&p_g1, g_g1b);
    cudaGetSymbolAddress(&p_xhi, g_xhi);
    cudaGetSymbolAddress(&p_xlo, g_xlo);
    cudaGetSymbolAddress(&p_wchi, g_wchi);
    cudaGetSymbolAddress(&p_wclo, g_wclo);

    // 0) bf16 splits: X, then combined weights [w_qkv ; gate_w1] -> rows 0..895
    split_k<<<(33554432 / 4 + 255) / 256, 256>>>(x, (__nv_bfloat16*)p_xhi,
                                                 (__nv_bfloat16*)p_xlo, 33554432 / 4);
    split_k<<<(196608 / 4 + 255) / 256, 256>>>(w_qkv, (__nv_bfloat16*)p_wchi,
                                               (__nv_bfloat16*)p_wclo, 196608 / 4);
    split_k<<<(32768 / 4 + 255) / 256, 256>>>(gw1,
                                              (__nv_bfloat16*)p_wchi + 196608,
                                              (__nv_bfloat16*)p_wclo + 196608, 32768 / 4);

    // 1) fused qkv + gate1 GEMM (tensor cores, cp.async double-buffered, static smem)
    {
        dim3 g(NPIX / 128, MTOT / 128, BB);
        bfgemm3_k<<<g, 256>>>(
            (const __nv_bfloat16*)p_wchi, (const __nv_bfloat16*)p_wclo,
            (const __nv_bfloat16*)p_xhi, (const __nv_bfloat16*)p_xlo,
            (float*)p_qkv, (float*)p_g1, gb1);
    }
    // 2) depthwise 3x3 + fused q/k sumsq partials
    dwconv2_k<<<BB * D3 * 16, 128>>>(w_dw);
    // 3) gate stage 2 + dk
    gate2_k<<<512, 256>>>(gw2, gb2);
    dk_k<<<1, 256>>>();
    // 4) finish inverse norms
    norm2_k<<<16, 256>>>();
    // 5) attention S = Q K^T
    {
        dim3 g(32, 32);
        attn_partial_k<<<g, 256>>>();
    }
    attn_reduce_k<<<512, 256>>>();
    // 6) softmax with top-k
    softmax_k<<<2048, 64>>>(temp, a1, a2, a3, a4);
    // 7) out = P @ V
    {
        dim3 g(NPIX / 128, 32);
        av_k<<<g, 256>>>(out);
    }
}

// round 9
// speedup vs baseline: 2.2895x; 1.1410x over previous
#include <cuda_runtime.h>
#include <cuda_bf16.h>
#include <math.h>
#include <stdint.h>

// ---------------- problem constants ----------------
#define BB    8
#define DIMC  256
#define D3    768          // 3*DIM
#define HEADS 4
#define CH    64           // per-head channels
#define HH    128
#define WW    128
#define NPIX  16384        // H*W
#define MTOT  896          // 768 qkv rows + 128 gate rows (fused GEMM)
#define NCHUNK 16          // attn pixel chunks (1024 px each)

// ---------------- scratch (device globals; no runtime alloc) ----------------
__device__ float g_qkv[100663296];   // [B,768,NPIX] post 1x1 conv
__device__ float g_dwb[100663296];   // [B,768,NPIX] post depthwise conv (v channels used)
__device__ float g_g1b[16777216];    // [B,128,NPIX] gate hidden
__device__ float g_part[2097152];    // [16 chunks][32 bh][64][64] attn partials
__device__ float g_attn[131072];     // [32 bh][64][64]
__device__ float g_inv[4096];        // inverse L2 norms
__device__ float g_normpart[65536];  // [b*512+ch][16] sum-of-square partials
__device__ float g_gatepart[512];
__device__ int   g_dk;

__device__ __nv_bfloat16 g_xhi[33554432];   // X split hi  [B,256,NPIX]
__device__ __nv_bfloat16 g_xlo[33554432];   // X split lo
__device__ __nv_bfloat16 g_wchi[229376];    // combined weights split [896,256]
__device__ __nv_bfloat16 g_wclo[229376];
__device__ __nv_bfloat16 g_qkh[67108864];   // q/k post-dw bf16 hi [B,512,NPIX]
__device__ __nv_bfloat16 g_qkl[67108864];   // q/k post-dw bf16 lo

// ================= bf16 split conversion: v = hi + lo =================
__global__ __launch_bounds__(256) void split_k(const float* __restrict__ in,
                                               __nv_bfloat16* __restrict__ hi,
                                               __nv_bfloat16* __restrict__ lo, int n4)
{
    const int i = blockIdx.x * 256 + threadIdx.x;
    if (i >= n4) return;
    const float4 v = ((const float4*)in)[i];
    __nv_bfloat16 h0 = __float2bfloat16(v.x);
    __nv_bfloat16 h1 = __float2bfloat16(v.y);
    __nv_bfloat16 h2 = __float2bfloat16(v.z);
    __nv_bfloat16 h3 = __float2bfloat16(v.w);
    __nv_bfloat162* H = (__nv_bfloat162*)hi;
    __nv_bfloat162* L = (__nv_bfloat162*)lo;
    H[i * 2 + 0] = __nv_bfloat162(h0, h1);
    H[i * 2 + 1] = __nv_bfloat162(h2, h3);
    L[i * 2 + 0] = __nv_bfloat162(__float2bfloat16(v.x - __bfloat162float(h0)),
                                  __float2bfloat16(v.y - __bfloat162float(h1)));
    L[i * 2 + 1] = __nv_bfloat162(__float2bfloat16(v.z - __bfloat162float(h2)),
                                  __float2bfloat16(v.w - __bfloat162float(h3)));
}

// ================= MMA helpers =================
__device__ __forceinline__ uint32_t smem_u32(const void* p) {
    return (uint32_t)__cvta_generic_to_shared(p);
}
__device__ __forceinline__ void cp16(uint32_t dst, const void* src) {
    asm volatile("cp.async.cg.shared.global [%0], [%1], 16;\n" :: "r"(dst), "l"(src));
}
__device__ __forceinline__ void ldsm_x4(uint32_t* r, uint32_t a) {
    asm volatile("ldmatrix.sync.aligned.m8n8.x4.shared.b16 {%0,%1,%2,%3}, [%4];"
                 : "=r"(r[0]), "=r"(r[1]), "=r"(r[2]), "=r"(r[3]) : "r"(a));
}
__device__ __forceinline__ void ldsm_x4t(uint32_t* r, uint32_t a) {
    asm volatile("ldmatrix.sync.aligned.m8n8.x4.trans.shared.b16 {%0,%1,%2,%3}, [%4];"
                 : "=r"(r[0]), "=r"(r[1]), "=r"(r[2]), "=r"(r[3]) : "r"(a));
}
__device__ __forceinline__ void mma_bf16(float* c, const uint32_t* a, const uint32_t* b) {
    asm volatile("mma.sync.aligned.m16n8k16.row.col.f32.bf16.bf16.f32 "
                 "{%0,%1,%2,%3}, {%4,%5,%6,%7}, {%8,%9}, {%0,%1,%2,%3};"
                 : "+f"(c[0]), "+f"(c[1]), "+f"(c[2]), "+f"(c[3])
                 : "r"(a[0]), "r"(a[1]), "r"(a[2]), "r"(a[3]), "r"(b[0]), "r"(b[1]));
}

// ================= tensor-core bf16-split GEMM (cp.async, static smem) =============
// C (896 x 16384 per batch) = Wc(896x256) @ X[b](256x16384), split hi/lo, 3 terms.
// Rows 0..767 -> g_qkv, rows 768..895 -> g_g1b with bias+relu.
// Block tile 128x128, k-step 16, 256 threads = 8 warps (2m x 4n), double-buffered
// STATIC shared memory (41984 B total).
#define ASTR3 24        // A smem row stride in bf16 (48 B rows)
#define BSTR3 136       // B smem row stride in bf16 (272 B rows)
#define OFF3_AL 6144
#define OFF3_BH 12288
#define OFF3_BL 16640
#define STAGE3  20992   // bytes per stage

__global__ __launch_bounds__(256, 2) void bfgemm3_k(
    const __nv_bfloat16* __restrict__ Ahi, const __nv_bfloat16* __restrict__ Alo,
    const __nv_bfloat16* __restrict__ Xhi, const __nv_bfloat16* __restrict__ Xlo,
    float* __restrict__ Cqkv, float* __restrict__ Cg1,
    const float* __restrict__ gb1)
{
    __shared__ alignas(16) char sm[2 * STAGE3];
    const int z = blockIdx.z;
    const __nv_bfloat16* __restrict__ Bh = Xhi + (size_t)z * DIMC * NPIX;
    const __nv_bfloat16* __restrict__ Bl = Xlo + (size_t)z * DIMC * NPIX;
    const int m0 = blockIdx.y * 128, n0 = blockIdx.x * 128;

    const int tid = threadIdx.x;
    const int warp = tid >> 5, lane = tid & 31;
    const int wm = (warp & 1) * 64;
    const int wn = (warp >> 1) * 32;

    const uint32_t uS = smem_u32(sm);

    const int aRow = tid >> 1, aKc = tid & 1;    // A: 128 rows x 2 chunks
    const int bRow = tid >> 4, bNc = tid & 15;   // B: 16 rows x 16 chunks

    float acc[16][4];
#pragma unroll
    for (int f = 0; f < 16; f++)
#pragma unroll
        for (int r = 0; r < 4; r++) acc[f][r] = 0.f;

    auto copy_stage = [&](int buf, int k0) {
        const uint32_t sb = uS + buf * STAGE3;
        {
            const size_t ga = (size_t)(m0 + aRow) * DIMC + k0 + aKc * 8;
            const uint32_t so = (uint32_t)aRow * 48 + aKc * 16;
            cp16(sb + so, Ahi + ga);
            cp16(sb + OFF3_AL + so, Alo + ga);
        }
        {
            const size_t gb = (size_t)(k0 + bRow) * NPIX + n0 + bNc * 8;
            const uint32_t so = (uint32_t)bRow * 272 + bNc * 16;
            cp16(sb + OFF3_BH + so, Bh + gb);
            cp16(sb + OFF3_BL + so, Bl + gb);
        }
    };

    copy_stage(0, 0);
    asm volatile("cp.async.commit_group;\n");

    const int nsteps = DIMC / 16;  // 16
    for (int it = 0; it < nsteps; it++) {
        if (it + 1 < nsteps) {
            copy_stage((it + 1) & 1, (it + 1) * 16);
            asm volatile("cp.async.commit_group;\n");
            asm volatile("cp.async.wait_group 1;\n");
        } else {
            asm volatile("cp.async.wait_group 0;\n");
        }
        __syncthreads();

        const uint32_t sb = uS + (it & 1) * STAGE3;
        uint32_t ah[4][4], al[4][4];
#pragma unroll
        for (int f = 0; f < 4; f++) {
            const int mrow = wm + f * 16 + (lane & 15);
            const int kcol = ((lane >> 4) & 1) * 8;
            const uint32_t off = (uint32_t)(mrow * ASTR3 + kcol) * 2;
            ldsm_x4(ah[f], sb + off);
            ldsm_x4(al[f], sb + OFF3_AL + off);
        }
#pragma unroll
        for (int gg = 0; gg < 2; gg++) {
            // x4.trans covers k16 x n16: lanes 0-15 -> k rows at col base, 16-31 at col+8
            const int krow = lane & 15;
            const int ncol = wn + gg * 16 + ((lane >> 4) & 1) * 8;
            const uint32_t boff = (uint32_t)(krow * BSTR3 + ncol) * 2;
            uint32_t b4h[4], b4l[4];
            ldsm_x4t(b4h, sb + OFF3_BH + boff);
            ldsm_x4t(b4l, sb + OFF3_BL + boff);
#pragma unroll
            for (int oct = 0; oct < 2; oct++) {
                const int g = gg * 2 + oct;
                const uint32_t bhf[2] = { b4h[oct * 2], b4h[oct * 2 + 1] };
                const uint32_t blf[2] = { b4l[oct * 2], b4l[oct * 2 + 1] };
#pragma unroll
                for (int f = 0; f < 4; f++) {
                    mma_bf16(acc[f * 4 + g], ah[f], bhf);
                    mma_bf16(acc[f * 4 + g], ah[f], blf);
                    mma_bf16(acc[f * 4 + g], al[f], bhf);
                }
            }
        }
        __syncthreads();
    }

    // ---- epilogue: route to qkv or gate ----
    const int gid = lane >> 2, t4 = lane & 3;
    const bool isGate = (m0 >= D3);
    float* __restrict__ Cb = isGate ? (Cg1 + (size_t)z * 128 * NPIX)
                                    : (Cqkv + (size_t)z * D3 * NPIX);
    const int mAdj = isGate ? (m0 - D3) : m0;
#pragma unroll
    for (int f = 0; f < 4; f++) {
#pragma unroll
        for (int g = 0; g < 4; g++) {
            const int row = mAdj + wm + f * 16 + gid;
            const int col = n0 + wn + g * 8 + t4 * 2;
            const float* a = acc[f * 4 + g];
            float bv0 = 0.f, bv1 = 0.f;
            if (isGate) { bv0 = gb1[row]; bv1 = gb1[row + 8]; }
            float2 v0 = make_float2(a[0] + bv0, a[1] + bv0);
            float2 v1 = make_float2(a[2] + bv1, a[3] + bv1);
            if (isGate) {
                v0.x = fmaxf(v0.x, 0.f); v0.y = fmaxf(v0.y, 0.f);
                v1.x = fmaxf(v1.x, 0.f); v1.y = fmaxf(v1.y, 0.f);
            }
            *(float2*)(Cb + (size_t)row * NPIX + col) = v0;
            *(float2*)(Cb + (size_t)(row + 8) * NPIX + col) = v1;
        }
    }
}

// ================= depthwise 3x3 + fused sumsq; q/k -> bf16 hi/lo, v -> fp32 =======
__global__ __launch_bounds__(128) void dwconv3_k(const float* __restrict__ wdw)
{
    const int x     = threadIdx.x;
    const int ytile = blockIdx.x & 15;
    const int bc    = blockIdx.x >> 4;          // b*768 + ch
    const int ch    = bc % D3;
    const int b     = bc / D3;
    const int y0    = ytile * 8;
    const float* __restrict__ in = g_qkv + (size_t)bc * NPIX;

    __shared__ float s[10][130];
    __shared__ float red[4];

#pragma unroll
    for (int r = 0; r < 10; r++) {
        const int yy = y0 - 1 + r;
        s[r][x + 1] = ((unsigned)yy < HH) ? in[yy * WW + x] : 0.f;
    }
    if (x == 0) {
#pragma unroll
        for (int r = 0; r < 10; r++) { s[r][0] = 0.f; s[r][129] = 0.f; }
    }
    __syncthreads();

    float w[9];
#pragma unroll
    for (int i = 0; i < 9; i++) w[i] = __ldg(wdw + ch * 9 + i);

    float res[8];
    float sq = 0.f;
#pragma unroll
    for (int oy = 0; oy < 8; oy++) {
        float acc = 0.f;
#pragma unroll
        for (int dy = 0; dy < 3; dy++)
#pragma unroll
            for (int dx = 0; dx < 3; dx++)
                acc += s[oy + dy][x + dx] * w[dy * 3 + dx];
        res[oy] = acc;
        sq += acc * acc;
    }

    if (ch < 512) {
        __nv_bfloat16* __restrict__ oh = g_qkh + (size_t)(b * 512 + ch) * NPIX;
        __nv_bfloat16* __restrict__ ol = g_qkl + (size_t)(b * 512 + ch) * NPIX;
#pragma unroll
        for (int oy = 0; oy < 8; oy++) {
            const __nv_bfloat16 h = __float2bfloat16(res[oy]);
            oh[(y0 + oy) * WW + x] = h;
            ol[(y0 + oy) * WW + x] = __float2bfloat16(res[oy] - __bfloat162float(h));
        }
#pragma unroll
        for (int o = 16; o > 0; o >>= 1) sq += __shfl_down_sync(0xffffffffu, sq, o);
        if ((x & 31) == 0) red[x >> 5] = sq;
        __syncthreads();
        if (x == 0)
            g_normpart[(b * 512 + ch) * 16 + ytile] = red[0] + red[1] + red[2] + red[3];
    } else {
        float* __restrict__ outp = g_dwb + (size_t)bc * NPIX;
#pragma unroll
        for (int oy = 0; oy < 8; oy++) outp[(y0 + oy) * WW + x] = res[oy];
    }
}

// ================= finish inverse norms from partials =================
__global__ __launch_bounds__(256) void norm2_k()
{
    const int r = blockIdx.x * 256 + threadIdx.x;   // 0..4095
    if (r >= 4096) return;
    float s = 0.f;
#pragma unroll
    for (int i = 0; i < 16; i++) s += g_normpart[r * 16 + i];
    g_inv[r] = 1.f / fmaxf(sqrtf(s), 1e-12f);
}

// ================= gate stage 2 =================
__global__ __launch_bounds__(256) void gate2_k(const float* __restrict__ w2,
                                               const float* __restrict__ b2)
{
    __shared__ float w2s[128];
    const int tid = threadIdx.x;
    if (tid < 128) w2s[tid] = w2[tid];
    __syncthreads();

    const int pg = blockIdx.x * 256 + tid;
    const int b  = pg >> 14;
    const int p  = pg & (NPIX - 1);
    const float* __restrict__ g = g_g1b + (size_t)b * 128 * NPIX + p;

    float acc = b2[0];
#pragma unroll 8
    for (int j = 0; j < 128; j++) acc += w2s[j] * g[(size_t)j * NPIX];
    const float sig = 1.f / (1.f + expf(-acc));

    __shared__ float red[256];
    red[tid] = sig;
    __syncthreads();
    for (int s = 128; s > 0; s >>= 1) {
        if (tid < s) red[tid] += red[tid + s];
        __syncthreads();
    }
    if (tid == 0) g_gatepart[blockIdx.x] = red[0];
}

// ================= dynamic-k =================
__global__ void dk_k()
{
    __shared__ float red[256];
    const int tid = threadIdx.x;
    float s = 0.f;
    for (int i = tid; i < 512; i += 256) s += g_gatepart[i];
    red[tid] = s;
    __syncthreads();
    for (int st = 128; st > 0; st >>= 1) {
        if (tid < st) red[tid] += red[tid + st];
        __syncthreads();
    }
    if (tid == 0) {
        const float mean = red[0] / (float)(BB * NPIX);
        int dk = (int)floorf(64.f * mean);
        if (dk < 1) dk = 1;
        if (dk > 64) dk = 64;
        g_dk = dk;
    }
}

// ================= attn partials: tensor-core bf16-split QK^T =================
// S_partial[c,d] = sum over 1024-px chunk of q[c,p] k[d,p]; 3-term hi/lo split.
// Per CTA: 16 sub-tiles of 64 px; smem [64][72] bf16 x4 tensors (36,864 B).
#define QSTR 72
__global__ __launch_bounds__(256, 2) void attn_mma_k()
{
    const int bh = blockIdx.y;                 // 0..31
    const int b = bh >> 2, h = bh & 3;
    const int chunk = blockIdx.x;              // 0..15
    const __nv_bfloat16* __restrict__ Qh = g_qkh + (size_t)(b * 512 + h * CH) * NPIX;
    const __nv_bfloat16* __restrict__ Ql = g_qkl + (size_t)(b * 512 + h * CH) * NPIX;
    const __nv_bfloat16* __restrict__ Kh = g_qkh + (size_t)(b * 512 + 256 + h * CH) * NPIX;
    const __nv_bfloat16* __restrict__ Kl = g_qkl + (size_t)(b * 512 + 256 + h * CH) * NPIX;

    __shared__ alignas(16) __nv_bfloat16 sQh[64 * QSTR], sQl[64 * QSTR];
    __shared__ alignas(16) __nv_bfloat16 sKh[64 * QSTR], sKl[64 * QSTR];

    const int tid = threadIdx.x;
    const int warp = tid >> 5, lane = tid & 31;
    const int wm = (warp & 3) * 16;            // m-group (c rows)
    const int wn = (warp >> 2) * 32;           // n-group (d rows)

    const uint32_t uQh = smem_u32(sQh), uQl = smem_u32(sQl);
    const uint32_t uKh = smem_u32(sKh), uKl = smem_u32(sKl);

    float acc[4][4];
#pragma unroll
    for (int g = 0; g < 4; g++)
#pragma unroll
        for (int r = 0; r < 4; r++) acc[g][r] = 0.f;

    for (int sub = 0; sub < 16; sub++) {
        const int pix0 = chunk * 1024 + sub * 64;
        // load 64 rows x 64 bf16 per tensor; 512 uint4 per tensor, 2/thread
#pragma unroll
        for (int i = 0; i < 2; i++) {
            const int idx = tid + i * 256;
            const int row = idx >> 3, c8 = idx & 7;
            const size_t gofs = (size_t)row * NPIX + pix0 + c8 * 8;
            const uint32_t sofs = (uint32_t)row * QSTR + c8 * 8;
            *(uint4*)(sQh + sofs) = *(const uint4*)(Qh + gofs);
            *(uint4*)(sQl + sofs) = *(const uint4*)(Ql + gofs);
            *(uint4*)(sKh + sofs) = *(const uint4*)(Kh + gofs);
            *(uint4*)(sKl + sofs) = *(const uint4*)(Kl + gofs);
        }
        __syncthreads();

#pragma unroll
        for (int ks = 0; ks < 4; ks++) {
            const int kk = ks * 16;
            const int arow = wm + (lane & 15);
            const int acol = kk + ((lane >> 4) & 1) * 8;
            const uint32_t aoff = (uint32_t)(arow * QSTR + acol) * 2;
            uint32_t ah[4], al[4];
            ldsm_x4(ah, uQh + aoff);
            ldsm_x4(al, uQl + aoff);
#pragma unroll
            for (int gg = 0; gg < 2; gg++) {
                const int brow = wn + gg * 16 + (lane & 15);
                const int bcol = kk + ((lane >> 4) & 1) * 8;
                const uint32_t boff = (uint32_t)(brow * QSTR + bcol) * 2;
                uint32_t b4h[4], b4l[4];
                ldsm_x4(b4h, uKh + boff);
                ldsm_x4(b4l, uKl + boff);
                // non-trans x4: r0=(n0-7,k0-7) r1=(n8-15,k0-7) r2=(n0-7,k8-15) r3=(n8-15,k8-15)
#pragma unroll
                for (int oct = 0; oct < 2; oct++) {
                    const int g = gg * 2 + oct;
                    const uint32_t bhf[2] = { b4h[oct], b4h[oct + 2] };
                    const uint32_t blf[2] = { b4l[oct], b4l[oct + 2] };
                    mma_bf16(acc[g], ah, bhf);
                    mma_bf16(acc[g], ah, blf);
                    mma_bf16(acc[g], al, bhf);
                }
            }
        }
        __syncthreads();
    }

    // epilogue: partial S tile -> g_part[chunk][bh]
    float* __restrict__ P = g_part + ((size_t)chunk * 32 + bh) * 4096;
    const int gid = lane >> 2, t4 = lane & 3;
#pragma unroll
    for (int g = 0; g < 4; g++) {
        const int row = wm + gid;
        const int col = wn + g * 8 + t4 * 2;
        *(float2*)(P + row * 64 + col) = make_float2(acc[g][0], acc[g][1]);
        *(float2*)(P + (row + 8) * 64 + col) = make_float2(acc[g][2], acc[g][3]);
    }
}

__global__ __launch_bounds__(256) void attn_reduce_k()
{
    const int i = blockIdx.x * 256 + threadIdx.x;   // 0..131071
    float s = 0.f;
#pragma unroll
    for (int c = 0; c < NCHUNK; c++) s += g_part[c * 131072 + i];
    g_attn[i] = s;
}

// ================= softmax + top-k =================
__global__ __launch_bounds__(64) void softmax_k(const float* __restrict__ temp,
                                                const float* __restrict__ a1,
                                                const float* __restrict__ a2,
                                                const float* __restrict__ a3,
                                                const float* __restrict__ a4)
{
    const int row = blockIdx.x;
    const int bh = row >> 6, c = row & 63;
    const int b = bh >> 2, h = bh & 3;
    const int d = threadIdx.x;

    const float invq = g_inv[b * 512 + h * CH + c];
    const float invk = g_inv[b * 512 + 256 + h * CH + d];
    const float a = g_attn[row * 64 + d] * invq * invk * temp[h];

    __shared__ float sv[64], se[64];
    sv[d] = a;
    __syncthreads();

    const int dk = g_dk;
    int rank = 0;
    float mx = -3.4e38f;
#pragma unroll 8
    for (int j = 0; j < 64; j++) {
        const float v = sv[j];
        rank += (v > a);
        mx = fmaxf(mx, v);
    }
    se[d] = (rank < dk) ? a : 3.4e38f;
    __syncthreads();
    float t = 3.4e38f;
#pragma unroll 8
    for (int j = 0; j < 64; j++) t = fminf(t, se[j]);
    __syncthreads();

    const float e = (a >= t) ? expf(a - mx) : 0.f;
    se[d] = e;
    __syncthreads();
    float sum = 0.f;
#pragma unroll 8
    for (int j = 0; j < 64; j++) sum += se[j];

    const float s4 = a1[0] + a2[0] + a3[0] + a4[0];
    g_attn[row * 64 + d] = e / sum * s4;
}

// ================= out = P @ V =================
__global__ __launch_bounds__(256) void av_k(float* __restrict__ out)
{
    const int bh = blockIdx.y;
    const int b = bh >> 2, h = bh & 3;
    const float* __restrict__ Pm = g_attn + bh * 4096;
    const float* __restrict__ V = g_dwb + (size_t)b * D3 * NPIX + (size_t)(512 + h * CH) * NPIX;
    float* __restrict__ O = out + (size_t)b * DIMC * NPIX + (size_t)(h * CH) * NPIX;

    __shared__ float As[64][68];
    const int tid = threadIdx.x;
    for (int e = tid; e < 4096; e += 256) {
        const int cc = e >> 6, dd = e & 63;
        As[dd][cc] = Pm[e];
    }
    __syncthreads();

    const int tx = tid & 31, ty = tid >> 5;
    const int n = blockIdx.x * 128 + tx * 4;

    float acc[8][4];
#pragma unroll
    for (int i = 0; i < 8; i++)
#pragma unroll
        for (int j = 0; j < 4; j++) acc[i][j] = 0.f;

#pragma unroll 8
    for (int dd = 0; dd < 64; dd++) {
        const float4 v = *(const float4*)(V + (size_t)dd * NPIX + n);
        float a[8];
#pragma unroll
        for (int i = 0; i < 8; i++) a[i] = As[dd][ty * 8 + i];
#pragma unroll
        for (int i = 0; i < 8; i++) {
            acc[i][0] += a[i] * v.x;
            acc[i][1] += a[i] * v.y;
            acc[i][2] += a[i] * v.z;
            acc[i][3] += a[i] * v.w;
        }
    }
#pragma unroll
    for (int i = 0; i < 8; i++) {
        float4 o;
        o.x = acc[i][0]; o.y = acc[i][1]; o.z = acc[i][2]; o.w = acc[i][3];
        *(float4*)(O + (size_t)(ty * 8 + i) * NPIX + n) = o;
    }
}

// ================================ launch ================================
extern "C" void kernel_launch(void* const* d_in, const int* in_sizes, int n_in,
                              void* d_out, int out_size)
{
    (void)in_sizes; (void)n_in; (void)out_size;
    const float* x     = (const float*)d_in[0];
    const float* w_qkv = (const float*)d_in[1];
    const float* w_dw  = (const float*)d_in[2];
    const float* temp  = (const float*)d_in[3];
    const float* a1    = (const float*)d_in[4];
    const float* a2    = (const float*)d_in[5];
    const float* a3    = (const float*)d_in[6];
    const float* a4    = (const float*)d_in[7];
    const float* gw1   = (const float*)d_in[8];
    const float* gb1   = (const float*)d_in[9];
    const float* gw2   = (const float*)d_in[10];
    const float* gb2   = (const float*)d_in[11];
    float* out = (float*)d_out;

    void *p_qkv, *p_g1, *p_xhi, *p_xlo, *p_wchi, *p_wclo;
    cudaGetSymbolAddress(&p_qkv, g_qkv);
    cudaGetSymbolAddress(&p_g1, g_g1b);
    cudaGetSymbolAddress(&p_xhi, g_xhi);
    cudaGetSymbolAddress(&p_xlo, g_xlo);
    cudaGetSymbolAddress(&p_wchi, g_wchi);
    cudaGetSymbolAddress(&p_wclo, g_wclo);

    // 0) bf16 splits: X, then combined weights [w_qkv ; gate_w1] -> rows 0..895
    split_k<<<(33554432 / 4 + 255) / 256, 256>>>(x, (__nv_bfloat16*)p_xhi,
                                                 (__nv_bfloat16*)p_xlo, 33554432 / 4);
    split_k<<<(196608 / 4 + 255) / 256, 256>>>(w_qkv, (__nv_bfloat16*)p_wchi,
                                               (__nv_bfloat16*)p_wclo, 196608 / 4);
    split_k<<<(32768 / 4 + 255) / 256, 256>>>(gw1,
                                              (__nv_bfloat16*)p_wchi + 196608,
                                              (__nv_bfloat16*)p_wclo + 196608, 32768 / 4);

    // 1) fused qkv + gate1 GEMM (tensor cores, cp.async double-buffered, static smem)
    {
        dim3 g(NPIX / 128, MTOT / 128, BB);
        bfgemm3_k<<<g, 256>>>(
            (const __nv_bfloat16*)p_wchi, (const __nv_bfloat16*)p_wclo,
            (const __nv_bfloat16*)p_xhi, (const __nv_bfloat16*)p_xlo,
            (float*)p_qkv, (float*)p_g1, gb1);
    }
    // 2) depthwise 3x3 + fused q/k sumsq; q/k -> bf16 hi/lo, v -> fp32
    dwconv3_k<<<BB * D3 * 16, 128>>>(w_dw);
    // 3) gate stage 2 + dk
    gate2_k<<<512, 256>>>(gw2, gb2);
    dk_k<<<1, 256>>>();
    // 4) finish inverse norms
    norm2_k<<<16, 256>>>();
    // 5) attention S = Q K^T (tensor cores, bf16 split, 16-chunk partials)
    {
        dim3 g(NCHUNK, 32);
        attn_mma_k<<<g, 256>>>();
    }
    attn_reduce_k<<<512, 256>>>();
    // 6) softmax with top-k
    softmax_k<<<2048, 64>>>(temp, a1, a2, a3, a4);
    // 7) out = P @ V
    {
        dim3 g(NPIX / 128, 32);
        av_k<<<g, 256>>>(out);
    }
}

// round 10
// speedup vs baseline: 2.3992x; 1.0479x over previous
#include <cuda_runtime.h>
#include <cuda_bf16.h>
#include <math.h>
#include <stdint.h>

// ---------------- problem constants ----------------
#define BB    8
#define DIMC  256
#define D3    768          // 3*DIM
#define HEADS 4
#define CH    64           // per-head channels
#define HH    128
#define WW    128
#define NPIX  16384        // H*W
#define MTOT  896          // 768 qkv rows + 128 gate rows (fused GEMM)
#define NCHUNK 16          // attn pixel chunks (1024 px each)

// ---------------- scratch (device globals; no runtime alloc) ----------------
__device__ float g_qkv[100663296];   // [B,768,NPIX] post 1x1 conv
__device__ float g_g1b[16777216];    // [B,128,NPIX] gate hidden
__device__ float g_part[2097152];    // [16 chunks][32 bh][64][64] attn partials
__device__ float g_attn[131072];     // [32 bh][64][64]
__device__ float g_inv[4096];        // inverse L2 norms
__device__ float g_normpart[65536];  // [b*512+ch][16] sum-of-square partials
__device__ float g_gatepart[512];
__device__ int   g_dk;

__device__ __nv_bfloat16 g_xhi[33554432];   // X split hi  [B,256,NPIX]
__device__ __nv_bfloat16 g_xlo[33554432];   // X split lo
__device__ __nv_bfloat16 g_wchi[229376];    // combined weights split [896,256]
__device__ __nv_bfloat16 g_wclo[229376];
__device__ __nv_bfloat16 g_qkh[67108864];   // q/k post-dw bf16 hi [B,512,NPIX]
__device__ __nv_bfloat16 g_qkl[67108864];   // q/k post-dw bf16 lo
__device__ __nv_bfloat16 g_vh[33554432];    // v post-dw bf16 hi [B,256,NPIX]
__device__ __nv_bfloat16 g_vl[33554432];    // v post-dw bf16 lo

// ================= bf16 split conversion: v = hi + lo =================
__global__ __launch_bounds__(256) void split_k(const float* __restrict__ in,
                                               __nv_bfloat16* __restrict__ hi,
                                               __nv_bfloat16* __restrict__ lo, int n4)
{
    const int i = blockIdx.x * 256 + threadIdx.x;
    if (i >= n4) return;
    const float4 v = ((const float4*)in)[i];
    __nv_bfloat16 h0 = __float2bfloat16(v.x);
    __nv_bfloat16 h1 = __float2bfloat16(v.y);
    __nv_bfloat16 h2 = __float2bfloat16(v.z);
    __nv_bfloat16 h3 = __float2bfloat16(v.w);
    __nv_bfloat162* H = (__nv_bfloat162*)hi;
    __nv_bfloat162* L = (__nv_bfloat162*)lo;
    H[i * 2 + 0] = __nv_bfloat162(h0, h1);
    H[i * 2 + 1] = __nv_bfloat162(h2, h3);
    L[i * 2 + 0] = __nv_bfloat162(__float2bfloat16(v.x - __bfloat162float(h0)),
                                  __float2bfloat16(v.y - __bfloat162float(h1)));
    L[i * 2 + 1] = __nv_bfloat162(__float2bfloat16(v.z - __bfloat162float(h2)),
                                  __float2bfloat16(v.w - __bfloat162float(h3)));
}

// ================= MMA helpers =================
__device__ __forceinline__ uint32_t smem_u32(const void* p) {
    return (uint32_t)__cvta_generic_to_shared(p);
}
__device__ __forceinline__ void cp16(uint32_t dst, const void* src) {
    asm volatile("cp.async.cg.shared.global [%0], [%1], 16;\n" :: "r"(dst), "l"(src));
}
__device__ __forceinline__ void ldsm_x4(uint32_t* r, uint32_t a) {
    asm volatile("ldmatrix.sync.aligned.m8n8.x4.shared.b16 {%0,%1,%2,%3}, [%4];"
                 : "=r"(r[0]), "=r"(r[1]), "=r"(r[2]), "=r"(r[3]) : "r"(a));
}
__device__ __forceinline__ void ldsm_x4t(uint32_t* r, uint32_t a) {
    asm volatile("ldmatrix.sync.aligned.m8n8.x4.trans.shared.b16 {%0,%1,%2,%3}, [%4];"
                 : "=r"(r[0]), "=r"(r[1]), "=r"(r[2]), "=r"(r[3]) : "r"(a));
}
__device__ __forceinline__ void mma_bf16(float* c, const uint32_t* a, const uint32_t* b) {
    asm volatile("mma.sync.aligned.m16n8k16.row.col.f32.bf16.bf16.f32 "
                 "{%0,%1,%2,%3}, {%4,%5,%6,%7}, {%8,%9}, {%0,%1,%2,%3};"
                 : "+f"(c[0]), "+f"(c[1]), "+f"(c[2]), "+f"(c[3])
                 : "r"(a[0]), "r"(a[1]), "r"(a[2]), "r"(a[3]), "r"(b[0]), "r"(b[1]));
}

// ================= tensor-core bf16-split GEMM (cp.async, static smem) =============
// Block tile 128x128, k-step 16, 256 threads = 8 warps (2m x 4n), double-buffered,
// ONE __syncthreads per k-iter (next-stage cp.async issued right after the sync).
#define ASTR3 24        // A smem row stride in bf16 (48 B rows)
#define BSTR3 136       // B smem row stride in bf16 (272 B rows)
#define OFF3_AL 6144
#define OFF3_BH 12288
#define OFF3_BL 16640
#define STAGE3  20992   // bytes per stage

__global__ __launch_bounds__(256, 2) void bfgemm3_k(
    const __nv_bfloat16* __restrict__ Ahi, const __nv_bfloat16* __restrict__ Alo,
    const __nv_bfloat16* __restrict__ Xhi, const __nv_bfloat16* __restrict__ Xlo,
    float* __restrict__ Cqkv, float* __restrict__ Cg1,
    const float* __restrict__ gb1)
{
    __shared__ alignas(16) char sm[2 * STAGE3];
    const int z = blockIdx.z;
    const __nv_bfloat16* __restrict__ Bh = Xhi + (size_t)z * DIMC * NPIX;
    const __nv_bfloat16* __restrict__ Bl = Xlo + (size_t)z * DIMC * NPIX;
    const int m0 = blockIdx.y * 128, n0 = blockIdx.x * 128;

    const int tid = threadIdx.x;
    const int warp = tid >> 5, lane = tid & 31;
    const int wm = (warp & 1) * 64;
    const int wn = (warp >> 1) * 32;

    const uint32_t uS = smem_u32(sm);

    const int aRow = tid >> 1, aKc = tid & 1;    // A: 128 rows x 2 chunks
    const int bRow = tid >> 4, bNc = tid & 15;   // B: 16 rows x 16 chunks

    float acc[16][4];
#pragma unroll
    for (int f = 0; f < 16; f++)
#pragma unroll
        for (int r = 0; r < 4; r++) acc[f][r] = 0.f;

    auto copy_stage = [&](int buf, int k0) {
        const uint32_t sb = uS + buf * STAGE3;
        {
            const size_t ga = (size_t)(m0 + aRow) * DIMC + k0 + aKc * 8;
            const uint32_t so = (uint32_t)aRow * 48 + aKc * 16;
            cp16(sb + so, Ahi + ga);
            cp16(sb + OFF3_AL + so, Alo + ga);
        }
        {
            const size_t gb = (size_t)(k0 + bRow) * NPIX + n0 + bNc * 8;
            const uint32_t so = (uint32_t)bRow * 272 + bNc * 16;
            cp16(sb + OFF3_BH + so, Bh + gb);
            cp16(sb + OFF3_BL + so, Bl + gb);
        }
    };

    copy_stage(0, 0);
    asm volatile("cp.async.commit_group;\n");

    const int nsteps = DIMC / 16;  // 16
    for (int it = 0; it < nsteps; it++) {
        asm volatile("cp.async.wait_group 0;\n");
        __syncthreads();   // stage 'it' visible; all threads done reading the other buf
        if (it + 1 < nsteps) {
            copy_stage((it + 1) & 1, (it + 1) * 16);
            asm volatile("cp.async.commit_group;\n");
        }

        const uint32_t sb = uS + (it & 1) * STAGE3;
        uint32_t ah[4][4], al[4][4];
#pragma unroll
        for (int f = 0; f < 4; f++) {
            const int mrow = wm + f * 16 + (lane & 15);
            const int kcol = ((lane >> 4) & 1) * 8;
            const uint32_t off = (uint32_t)(mrow * ASTR3 + kcol) * 2;
            ldsm_x4(ah[f], sb + off);
            ldsm_x4(al[f], sb + OFF3_AL + off);
        }
#pragma unroll
        for (int gg = 0; gg < 2; gg++) {
            const int krow = lane & 15;
            const int ncol = wn + gg * 16 + ((lane >> 4) & 1) * 8;
            const uint32_t boff = (uint32_t)(krow * BSTR3 + ncol) * 2;
            uint32_t b4h[4], b4l[4];
            ldsm_x4t(b4h, sb + OFF3_BH + boff);
            ldsm_x4t(b4l, sb + OFF3_BL + boff);
#pragma unroll
            for (int oct = 0; oct < 2; oct++) {
                const int g = gg * 2 + oct;
                const uint32_t bhf[2] = { b4h[oct * 2], b4h[oct * 2 + 1] };
                const uint32_t blf[2] = { b4l[oct * 2], b4l[oct * 2 + 1] };
#pragma unroll
                for (int f = 0; f < 4; f++) {
                    mma_bf16(acc[f * 4 + g], ah[f], bhf);
                    mma_bf16(acc[f * 4 + g], ah[f], blf);
                    mma_bf16(acc[f * 4 + g], al[f], bhf);
                }
            }
        }
    }

    // ---- epilogue: route to qkv or gate ----
    const int gid = lane >> 2, t4 = lane & 3;
    const bool isGate = (m0 >= D3);
    float* __restrict__ Cb = isGate ? (Cg1 + (size_t)z * 128 * NPIX)
                                    : (Cqkv + (size_t)z * D3 * NPIX);
    const int mAdj = isGate ? (m0 - D3) : m0;
#pragma unroll
    for (int f = 0; f < 4; f++) {
#pragma unroll
        for (int g = 0; g < 4; g++) {
            const int row = mAdj + wm + f * 16 + gid;
            const int col = n0 + wn + g * 8 + t4 * 2;
            const float* a = acc[f * 4 + g];
            float bv0 = 0.f, bv1 = 0.f;
            if (isGate) { bv0 = gb1[row]; bv1 = gb1[row + 8]; }
            float2 v0 = make_float2(a[0] + bv0, a[1] + bv0);
            float2 v1 = make_float2(a[2] + bv1, a[3] + bv1);
            if (isGate) {
                v0.x = fmaxf(v0.x, 0.f); v0.y = fmaxf(v0.y, 0.f);
                v1.x = fmaxf(v1.x, 0.f); v1.y = fmaxf(v1.y, 0.f);
            }
            *(float2*)(Cb + (size_t)row * NPIX + col) = v0;
            *(float2*)(Cb + (size_t)(row + 8) * NPIX + col) = v1;
        }
    }
}

// ========== depthwise 3x3 + fused sumsq; q/k -> bf16 hi/lo, v -> bf16 hi/lo ========
__global__ __launch_bounds__(128) void dwconv4_k(const float* __restrict__ wdw)
{
    const int x     = threadIdx.x;
    const int ytile = blockIdx.x & 15;
    const int bc    = blockIdx.x >> 4;          // b*768 + ch
    const int ch    = bc % D3;
    const int b     = bc / D3;
    const int y0    = ytile * 8;
    const float* __restrict__ in = g_qkv + (size_t)bc * NPIX;

    __shared__ float s[10][130];
    __shared__ float red[4];

#pragma unroll
    for (int r = 0; r < 10; r++) {
        const int yy = y0 - 1 + r;
        s[r][x + 1] = ((unsigned)yy < HH) ? in[yy * WW + x] : 0.f;
    }
    if (x == 0) {
#pragma unroll
        for (int r = 0; r < 10; r++) { s[r][0] = 0.f; s[r][129] = 0.f; }
    }
    __syncthreads();

    float w[9];
#pragma unroll
    for (int i = 0; i < 9; i++) w[i] = __ldg(wdw + ch * 9 + i);

    float res[8];
    float sq = 0.f;
#pragma unroll
    for (int oy = 0; oy < 8; oy++) {
        float acc = 0.f;
#pragma unroll
        for (int dy = 0; dy < 3; dy++)
#pragma unroll
            for (int dx = 0; dx < 3; dx++)
                acc += s[oy + dy][x + dx] * w[dy * 3 + dx];
        res[oy] = acc;
        sq += acc * acc;
    }

    if (ch < 512) {
        __nv_bfloat16* __restrict__ oh = g_qkh + (size_t)(b * 512 + ch) * NPIX;
        __nv_bfloat16* __restrict__ ol = g_qkl + (size_t)(b * 512 + ch) * NPIX;
#pragma unroll
        for (int oy = 0; oy < 8; oy++) {
            const __nv_bfloat16 h = __float2bfloat16(res[oy]);
            oh[(y0 + oy) * WW + x] = h;
            ol[(y0 + oy) * WW + x] = __float2bfloat16(res[oy] - __bfloat162float(h));
        }
#pragma unroll
        for (int o = 16; o > 0; o >>= 1) sq += __shfl_down_sync(0xffffffffu, sq, o);
        if ((x & 31) == 0) red[x >> 5] = sq;
        __syncthreads();
        if (x == 0)
            g_normpart[(b * 512 + ch) * 16 + ytile] = red[0] + red[1] + red[2] + red[3];
    } else {
        const int vch = ch - 512;
        __nv_bfloat16* __restrict__ oh = g_vh + (size_t)(b * 256 + vch) * NPIX;
        __nv_bfloat16* __restrict__ ol = g_vl + (size_t)(b * 256 + vch) * NPIX;
#pragma unroll
        for (int oy = 0; oy < 8; oy++) {
            const __nv_bfloat16 h = __float2bfloat16(res[oy]);
            oh[(y0 + oy) * WW + x] = h;
            ol[(y0 + oy) * WW + x] = __float2bfloat16(res[oy] - __bfloat162float(h));
        }
    }
}

// ================= finish inverse norms from partials =================
__global__ __launch_bounds__(256) void norm2_k()
{
    const int r = blockIdx.x * 256 + threadIdx.x;   // 0..4095
    if (r >= 4096) return;
    float s = 0.f;
#pragma unroll
    for (int i = 0; i < 16; i++) s += g_normpart[r * 16 + i];
    g_inv[r] = 1.f / fmaxf(sqrtf(s), 1e-12f);
}

// ================= gate stage 2 =================
__global__ __launch_bounds__(256) void gate2_k(const float* __restrict__ w2,
                                               const float* __restrict__ b2)
{
    __shared__ float w2s[128];
    const int tid = threadIdx.x;
    if (tid < 128) w2s[tid] = w2[tid];
    __syncthreads();

    const int pg = blockIdx.x * 256 + tid;
    const int b  = pg >> 14;
    const int p  = pg & (NPIX - 1);
    const float* __restrict__ g = g_g1b + (size_t)b * 128 * NPIX + p;

    float acc = b2[0];
#pragma unroll 8
    for (int j = 0; j < 128; j++) acc += w2s[j] * g[(size_t)j * NPIX];
    const float sig = 1.f / (1.f + expf(-acc));

    __shared__ float red[256];
    red[tid] = sig;
    __syncthreads();
    for (int s = 128; s > 0; s >>= 1) {
        if (tid < s) red[tid] += red[tid + s];
        __syncthreads();
    }
    if (tid == 0) g_gatepart[blockIdx.x] = red[0];
}

// ================= dynamic-k =================
__global__ void dk_k()
{
    __shared__ float red[256];
    const int tid = threadIdx.x;
    float s = 0.f;
    for (int i = tid; i < 512; i += 256) s += g_gatepart[i];
    red[tid] = s;
    __syncthreads();
    for (int st = 128; st > 0; st >>= 1) {
        if (tid < st) red[tid] += red[tid + st];
        __syncthreads();
    }
    if (tid == 0) {
        const float mean = red[0] / (float)(BB * NPIX);
        int dk = (int)floorf(64.f * mean);
        if (dk < 1) dk = 1;
        if (dk > 64) dk = 64;
        g_dk = dk;
    }
}

// ================= attn partials: tensor-core bf16-split QK^T =================
#define QSTR 72
__global__ __launch_bounds__(256, 2) void attn_mma_k()
{
    const int bh = blockIdx.y;                 // 0..31
    const int b = bh >> 2, h = bh & 3;
    const int chunk = blockIdx.x;              // 0..15
    const __nv_bfloat16* __restrict__ Qh = g_qkh + (size_t)(b * 512 + h * CH) * NPIX;
    const __nv_bfloat16* __restrict__ Ql = g_qkl + (size_t)(b * 512 + h * CH) * NPIX;
    const __nv_bfloat16* __restrict__ Kh = g_qkh + (size_t)(b * 512 + 256 + h * CH) * NPIX;
    const __nv_bfloat16* __restrict__ Kl = g_qkl + (size_t)(b * 512 + 256 + h * CH) * NPIX;

    __shared__ alignas(16) __nv_bfloat16 sQh[64 * QSTR], sQl[64 * QSTR];
    __shared__ alignas(16) __nv_bfloat16 sKh[64 * QSTR], sKl[64 * QSTR];

    const int tid = threadIdx.x;
    const int warp = tid >> 5, lane = tid & 31;
    const int wm = (warp & 3) * 16;            // m-group (c rows)
    const int wn = (warp >> 2) * 32;           // n-group (d rows)

    const uint32_t uQh = smem_u32(sQh), uQl = smem_u32(sQl);
    const uint32_t uKh = smem_u32(sKh), uKl = smem_u32(sKl);

    float acc[4][4];
#pragma unroll
    for (int g = 0; g < 4; g++)
#pragma unroll
        for (int r = 0; r < 4; r++) acc[g][r] = 0.f;

    for (int sub = 0; sub < 16; sub++) {
        const int pix0 = chunk * 1024 + sub * 64;
#pragma unroll
        for (int i = 0; i < 2; i++) {
            const int idx = tid + i * 256;
            const int row = idx >> 3, c8 = idx & 7;
            const size_t gofs = (size_t)row * NPIX + pix0 + c8 * 8;
            const uint32_t sofs = (uint32_t)row * QSTR + c8 * 8;
            *(uint4*)(sQh + sofs) = *(const uint4*)(Qh + gofs);
            *(uint4*)(sQl + sofs) = *(const uint4*)(Ql + gofs);
            *(uint4*)(sKh + sofs) = *(const uint4*)(Kh + gofs);
            *(uint4*)(sKl + sofs) = *(const uint4*)(Kl + gofs);
        }
        __syncthreads();

#pragma unroll
        for (int ks = 0; ks < 4; ks++) {
            const int kk = ks * 16;
            const int arow = wm + (lane & 15);
            const int acol = kk + ((lane >> 4) & 1) * 8;
            const uint32_t aoff = (uint32_t)(arow * QSTR + acol) * 2;
            uint32_t ah[4], al[4];
            ldsm_x4(ah, uQh + aoff);
            ldsm_x4(al, uQl + aoff);
#pragma unroll
            for (int gg = 0; gg < 2; gg++) {
                const int brow = wn + gg * 16 + (lane & 15);
                const int bcol = kk + ((lane >> 4) & 1) * 8;
                const uint32_t boff = (uint32_t)(brow * QSTR + bcol) * 2;
                uint32_t b4h[4], b4l[4];
                ldsm_x4(b4h, uKh + boff);
                ldsm_x4(b4l, uKl + boff);
#pragma unroll
                for (int oct = 0; oct < 2; oct++) {
                    const int g = gg * 2 + oct;
                    const uint32_t bhf[2] = { b4h[oct], b4h[oct + 2] };
                    const uint32_t blf[2] = { b4l[oct], b4l[oct + 2] };
                    mma_bf16(acc[g], ah, bhf);
                    mma_bf16(acc[g], ah, blf);
                    mma_bf16(acc[g], al, bhf);
                }
            }
        }
        __syncthreads();
    }

    float* __restrict__ P = g_part + ((size_t)chunk * 32 + bh) * 4096;
    const int gid = lane >> 2, t4 = lane & 3;
#pragma unroll
    for (int g = 0; g < 4; g++) {
        const int row = wm + gid;
        const int col = wn + g * 8 + t4 * 2;
        *(float2*)(P + row * 64 + col) = make_float2(acc[g][0], acc[g][1]);
        *(float2*)(P + (row + 8) * 64 + col) = make_float2(acc[g][2], acc[g][3]);
    }
}

__global__ __launch_bounds__(256) void attn_reduce_k()
{
    const int i = blockIdx.x * 256 + threadIdx.x;   // 0..131071
    float s = 0.f;
#pragma unroll
    for (int c = 0; c < NCHUNK; c++) s += g_part[c * 131072 + i];
    g_attn[i] = s;
}

// ================= softmax + top-k (writes dense weighted P) =================
__global__ __launch_bounds__(64) void softmax_k(const float* __restrict__ temp,
                                                const float* __restrict__ a1,
                                                const float* __restrict__ a2,
                                                const float* __restrict__ a3,
                                                const float* __restrict__ a4)
{
    const int row = blockIdx.x;
    const int bh = row >> 6, c = row & 63;
    const int b = bh >> 2, h = bh & 3;
    const int d = threadIdx.x;

    const float invq = g_inv[b * 512 + h * CH + c];
    const float invk = g_inv[b * 512 + 256 + h * CH + d];
    const float a = g_attn[row * 64 + d] * invq * invk * temp[h];

    __shared__ float sv[64], se[64];
    sv[d] = a;
    __syncthreads();

    const int dk = g_dk;
    int rank = 0;
    float mx = -3.4e38f;
#pragma unroll 8
    for (int j = 0; j < 64; j++) {
        const float v = sv[j];
        rank += (v > a);
        mx = fmaxf(mx, v);
    }
    se[d] = (rank < dk) ? a : 3.4e38f;
    __syncthreads();
    float t = 3.4e38f;
#pragma unroll 8
    for (int j = 0; j < 64; j++) t = fminf(t, se[j]);
    __syncthreads();

    const float e = (a >= t) ? expf(a - mx) : 0.f;
    se[d] = e;
    __syncthreads();
    float sum = 0.f;
#pragma unroll 8
    for (int j = 0; j < 64; j++) sum += se[j];

    const float s4 = a1[0] + a2[0] + a3[0] + a4[0];
    g_attn[row * 64 + d] = e / sum * s4;
}

// ================= out = P @ V (tensor cores, bf16 split) =================
// Per CTA: m=64 c-rows, n=128 px, k=64 d (two 32-k chunks). 8 warps 4m x 2n.
#define VSTR 136
__global__ __launch_bounds__(256, 2) void av_mma_k(float* __restrict__ out)
{
    const int bh = blockIdx.y;
    const int b = bh >> 2, h = bh & 3;
    const int n0 = blockIdx.x * 128;
    const __nv_bfloat16* __restrict__ Vh = g_vh + (size_t)(b * 256 + h * CH) * NPIX;
    const __nv_bfloat16* __restrict__ Vl = g_vl + (size_t)(b * 256 + h * CH) * NPIX;
    float* __restrict__ O = out + (size_t)b * DIMC * NPIX + (size_t)(h * CH) * NPIX + n0;

    __shared__ alignas(16) __nv_bfloat16 sPh[64 * QSTR], sPl[64 * QSTR];  // 9216 B each
    __shared__ alignas(16) __nv_bfloat16 sVh[32 * VSTR], sVl[32 * VSTR];  // 8704 B each

    const int tid = threadIdx.x;
    const int warp = tid >> 5, lane = tid & 31;
    const int wm = (warp & 3) * 16;            // c group
    const int wn = (warp >> 2) * 64;           // px group

    const uint32_t uPh = smem_u32(sPh), uPl = smem_u32(sPl);
    const uint32_t uVh = smem_u32(sVh), uVl = smem_u32(sVl);

    // load P dense (fp32) and split to bf16 hi/lo
    const float* __restrict__ Pm = g_attn + bh * 4096;
    for (int i = tid; i < 4096; i += 256) {
        const int c = i >> 6, d = i & 63;
        const float v = Pm[i];
        const __nv_bfloat16 hh = __float2bfloat16(v);
        sPh[c * QSTR + d] = hh;
        sPl[c * QSTR + d] = __float2bfloat16(v - __bfloat162float(hh));
    }

    float acc[8][4];
#pragma unroll
    for (int g = 0; g < 8; g++)
#pragma unroll
        for (int r = 0; r < 4; r++) acc[g][r] = 0.f;

#pragma unroll
    for (int kc = 0; kc < 2; kc++) {
        __syncthreads();   // previous chunk fully read (and first iter: nothing yet)
        // load V chunk: 32 d-rows x 128 px, bf16 hi/lo
#pragma unroll
        for (int i = 0; i < 2; i++) {
            const int idx = tid + i * 256;
            const int row = idx >> 4, c8 = idx & 15;
            const size_t gofs = (size_t)(kc * 32 + row) * NPIX + n0 + c8 * 8;
            const uint32_t sofs = (uint32_t)row * VSTR + c8 * 8;
            *(uint4*)(sVh + sofs) = *(const uint4*)(Vh + gofs);
            *(uint4*)(sVl + sofs) = *(const uint4*)(Vl + gofs);
        }
        __syncthreads();   // V chunk (and on first iter, P) visible

#pragma unroll
        for (int ks = 0; ks < 2; ks++) {
            const int kl = ks * 16;               // k within chunk
            const int kg = kc * 32 + kl;          // global d
            const int arow = wm + (lane & 15);
            const int acol = kg + ((lane >> 4) & 1) * 8;
            const uint32_t aoff = (uint32_t)(arow * QSTR + acol) * 2;
            uint32_t ah[4], al[4];
            ldsm_x4(ah, uPh + aoff);
            ldsm_x4(al, uPl + aoff);
#pragma unroll
            for (int gg = 0; gg < 4; gg++) {
                const int krow = kl + (lane & 15);
                const int ncol = wn + gg * 16 + ((lane >> 4) & 1) * 8;
                const uint32_t boff = (uint32_t)(krow * VSTR + ncol) * 2;
                uint32_t b4h[4], b4l[4];
                ldsm_x4t(b4h, uVh + boff);
                ldsm_x4t(b4l, uVl + boff);
#pragma unroll
                for (int oct = 0; oct < 2; oct++) {
                    const int g = gg * 2 + oct;
                    const uint32_t bhf[2] = { b4h[oct * 2], b4h[oct * 2 + 1] };
                    const uint32_t blf[2] = { b4l[oct * 2], b4l[oct * 2 + 1] };
                    mma_bf16(acc[g], ah, bhf);
                    mma_bf16(acc[g], ah, blf);
                    mma_bf16(acc[g], al, bhf);
                }
            }
        }
    }

    // epilogue: fp32 out [c][px]
    const int gid = lane >> 2, t4 = lane & 3;
#pragma unroll
    for (int g = 0; g < 8; g++) {
        const int row = wm + gid;
        const int col = wn + g * 8 + t4 * 2;
        *(float2*)(O + (size_t)row * NPIX + col) = make_float2(acc[g][0], acc[g][1]);
        *(float2*)(O + (size_t)(row + 8) * NPIX + col) = make_float2(acc[g][2], acc[g][3]);
    }
}

// ================================ launch ================================
extern "C" void kernel_launch(void* const* d_in, const int* in_sizes, int n_in,
                              void* d_out, int out_size)
{
    (void)in_sizes; (void)n_in; (void)out_size;
    const float* x     = (const float*)d_in[0];
    const float* w_qkv = (const float*)d_in[1];
    const float* w_dw  = (const float*)d_in[2];
    const float* temp  = (const float*)d_in[3];
    const float* a1    = (const float*)d_in[4];
    const float* a2    = (const float*)d_in[5];
    const float* a3    = (const float*)d_in[6];
    const float* a4    = (const float*)d_in[7];
    const float* gw1   = (const float*)d_in[8];
    const float* gb1   = (const float*)d_in[9];
    const float* gw2   = (const float*)d_in[10];
    const float* gb2   = (const float*)d_in[11];
    float* out = (float*)d_out;

    void *p_qkv, *p_g1, *p_xhi, *p_xlo, *p_wchi, *p_wclo;
    cudaGetSymbolAddress(&p_qkv, g_qkv);
    cudaGetSymbolAddress(&p_g1, g_g1b);
    cudaGetSymbolAddress(&p_xhi, g_xhi);
    cudaGetSymbolAddress(&p_xlo, g_xlo);
    cudaGetSymbolAddress(&p_wchi, g_wchi);
    cudaGetSymbolAddress(&p_wclo, g_wclo);

    // 0) bf16 splits
    split_k<<<(33554432 / 4 + 255) / 256, 256>>>(x, (__nv_bfloat16*)p_xhi,
                                                 (__nv_bfloat16*)p_xlo, 33554432 / 4);
    split_k<<<(196608 / 4 + 255) / 256, 256>>>(w_qkv, (__nv_bfloat16*)p_wchi,
                                               (__nv_bfloat16*)p_wclo, 196608 / 4);
    split_k<<<(32768 / 4 + 255) / 256, 256>>>(gw1,
                                              (__nv_bfloat16*)p_wchi + 196608,
                                              (__nv_bfloat16*)p_wclo + 196608, 32768 / 4);

    // 1) fused qkv + gate1 GEMM
    {
        dim3 g(NPIX / 128, MTOT / 128, BB);
        bfgemm3_k<<<g, 256>>>(
            (const __nv_bfloat16*)p_wchi, (const __nv_bfloat16*)p_wclo,
            (const __nv_bfloat16*)p_xhi, (const __nv_bfloat16*)p_xlo,
            (float*)p_qkv, (float*)p_g1, gb1);
    }
    // 2) depthwise 3x3 + fused sumsq; q/k and v -> bf16 hi/lo
    dwconv4_k<<<BB * D3 * 16, 128>>>(w_dw);
    // 3) gate stage 2 + dk
    gate2_k<<<512, 256>>>(gw2, gb2);
    dk_k<<<1, 256>>>();
    // 4) finish inverse norms
    norm2_k<<<16, 256>>>();
    // 5) attention S = Q K^T
    {
        dim3 g(NCHUNK, 32);
        attn_mma_k<<<g, 256>>>();
    }
    attn_reduce_k<<<512, 256>>>();
    // 6) softmax with top-k
    softmax_k<<<2048, 64>>>(temp, a1, a2, a3, a4);
    // 7) out = P @ V (tensor cores)
    {
        dim3 g(NPIX / 128, 32);
        av_mma_k<<<g, 256>>>(out);
    }
}

// round 11
// speedup vs baseline: 2.4990x; 1.0416x over previous
#include <cuda_runtime.h>
#include <cuda_bf16.h>
#include <math.h>
#include <stdint.h>

// ---------------- problem constants ----------------
#define BB    8
#define DIMC  256
#define D3    768          // 3*DIM
#define HEADS 4
#define CH    64           // per-head channels
#define HH    128
#define WW    128
#define NPIX  16384        // H*W
#define MTOT  896          // 768 qkv rows + 128 gate rows (fused GEMM)
#define NCHUNK 16          // attn pixel chunks (1024 px each)

// ---------------- scratch (device globals; no runtime alloc) ----------------
__device__ float g_qkv[100663296];   // [B,768,NPIX] post 1x1 conv
__device__ float g_g1b[16777216];    // [B,128,NPIX] gate hidden
__device__ float g_part[2097152];    // [16 chunks][32 bh][64][64] attn partials
__device__ float g_attn[131072];     // [32 bh][64][64] weighted P
__device__ float g_inv[4096];        // inverse L2 norms
__device__ float g_normpart[65536];  // [b*512+ch][16] sum-of-square partials
__device__ float g_gatepart[512];
__device__ int   g_dk;

__device__ __nv_bfloat16 g_xhi[33554432];   // X split hi  [B,256,NPIX]
__device__ __nv_bfloat16 g_xlo[33554432];   // X split lo
__device__ __nv_bfloat16 g_wchi[229376];    // combined weights split [896,256]
__device__ __nv_bfloat16 g_wclo[229376];
__device__ uint32_t g_wpk[229376];          // W packed in mma-fragment order
__device__ __nv_bfloat16 g_qkh[67108864];   // q/k post-dw bf16 hi [B,512,NPIX]
__device__ __nv_bfloat16 g_qkl[67108864];   // q/k post-dw bf16 lo
__device__ __nv_bfloat16 g_vh[33554432];    // v post-dw bf16 hi [B,256,NPIX]
__device__ __nv_bfloat16 g_vl[33554432];    // v post-dw bf16 lo

// ================= bf16 split conversion: v = hi + lo =================
__global__ __launch_bounds__(256) void split_k(const float* __restrict__ in,
                                               __nv_bfloat16* __restrict__ hi,
                                               __nv_bfloat16* __restrict__ lo, int n4)
{
    const int i = blockIdx.x * 256 + threadIdx.x;
    if (i >= n4) return;
    const float4 v = ((const float4*)in)[i];
    __nv_bfloat16 h0 = __float2bfloat16(v.x);
    __nv_bfloat16 h1 = __float2bfloat16(v.y);
    __nv_bfloat16 h2 = __float2bfloat16(v.z);
    __nv_bfloat16 h3 = __float2bfloat16(v.w);
    __nv_bfloat162* H = (__nv_bfloat162*)hi;
    __nv_bfloat162* L = (__nv_bfloat162*)lo;
    H[i * 2 + 0] = __nv_bfloat162(h0, h1);
    H[i * 2 + 1] = __nv_bfloat162(h2, h3);
    L[i * 2 + 0] = __nv_bfloat162(__float2bfloat16(v.x - __bfloat162float(h0)),
                                  __float2bfloat16(v.y - __bfloat162float(h1)));
    L[i * 2 + 1] = __nv_bfloat162(__float2bfloat16(v.z - __bfloat162float(h2)),
                                  __float2bfloat16(v.w - __bfloat162float(h3)));
}

// ================= MMA helpers =================
__device__ __forceinline__ uint32_t smem_u32(const void* p) {
    return (uint32_t)__cvta_generic_to_shared(p);
}
__device__ __forceinline__ void cp16(uint32_t dst, const void* src) {
    asm volatile("cp.async.cg.shared.global [%0], [%1], 16;\n" :: "r"(dst), "l"(src));
}
__device__ __forceinline__ void ldsm_x4(uint32_t* r, uint32_t a) {
    asm volatile("ldmatrix.sync.aligned.m8n8.x4.shared.b16 {%0,%1,%2,%3}, [%4];"
                 : "=r"(r[0]), "=r"(r[1]), "=r"(r[2]), "=r"(r[3]) : "r"(a));
}
__device__ __forceinline__ void ldsm_x4t(uint32_t* r, uint32_t a) {
    asm volatile("ldmatrix.sync.aligned.m8n8.x4.trans.shared.b16 {%0,%1,%2,%3}, [%4];"
                 : "=r"(r[0]), "=r"(r[1]), "=r"(r[2]), "=r"(r[3]) : "r"(a));
}
__device__ __forceinline__ void mma_bf16(float* c, const uint32_t* a, const uint32_t* b) {
    asm volatile("mma.sync.aligned.m16n8k16.row.col.f32.bf16.bf16.f32 "
                 "{%0,%1,%2,%3}, {%4,%5,%6,%7}, {%8,%9}, {%0,%1,%2,%3};"
                 : "+f"(c[0]), "+f"(c[1]), "+f"(c[2]), "+f"(c[3])
                 : "r"(a[0]), "r"(a[1]), "r"(a[2]), "r"(a[3]), "r"(b[0]), "r"(b[1]));
}

// ================= pack W fragments (replay ldmatrix semantics) =================
// grid (16 ksteps, 7 mtiles), 256 threads. For each (mtile,kstep): 8 m16-sets x {hi,lo}.
// dest: g_wpk[(((mtile*16+kstep)*8 + set)*2 + hilo)*128 + lane*4 .. +3]
#define PSTR 24
__global__ __launch_bounds__(256) void packA_k()
{
    const int kstep = blockIdx.x;      // 0..15
    const int mtile = blockIdx.y;      // 0..6
    __shared__ alignas(16) __nv_bfloat16 sh[128 * PSTR], sl[128 * PSTR];
    const int tid = threadIdx.x;
    {
        const int row = tid >> 1, kc = tid & 1;
        const size_t g = (size_t)(mtile * 128 + row) * DIMC + kstep * 16 + kc * 8;
        *(uint4*)(sh + row * PSTR + kc * 8) = *(const uint4*)(g_wchi + g);
        *(uint4*)(sl + row * PSTR + kc * 8) = *(const uint4*)(g_wclo + g);
    }
    __syncthreads();
    const int warp = tid >> 5, lane = tid & 31;   // warp = m16-set 0..7
    const int mrow = warp * 16 + (lane & 15);
    const int kcol = ((lane >> 4) & 1) * 8;
    const uint32_t off = (uint32_t)(mrow * PSTR + kcol) * 2;
    uint32_t r[4];
    ldsm_x4(r, smem_u32(sh) + off);
    const size_t base = ((size_t)(mtile * 16 + kstep) * 8 + warp) * 2;
    *(uint4*)(g_wpk + base * 128 + lane * 4) = *(const uint4*)r;
    ldsm_x4(r, smem_u32(sl) + off);
    *(uint4*)(g_wpk + (base + 1) * 128 + lane * 4) = *(const uint4*)r;
}

// ================= tensor-core bf16-split GEMM: A frags from global ===============
// Block tile 128x128, k-step 16, 8 warps (2m x 4n), B double-buffered cp.async,
// A fragments loaded per-iter from g_wpk (L2-resident, coalesced LDG.128).
#define BSTR3 136       // B smem row stride in bf16 (272 B rows)
#define OFF3_BL 4352
#define STAGE3  8704    // bytes per stage (Bh + Bl)

__global__ __launch_bounds__(256, 2) void bfgemm4_k(
    const __nv_bfloat16* __restrict__ Xhi, const __nv_bfloat16* __restrict__ Xlo,
    float* __restrict__ Cqkv, float* __restrict__ Cg1,
    const float* __restrict__ gb1)
{
    __shared__ alignas(16) char sm[2 * STAGE3];
    const int z = blockIdx.z;
    const __nv_bfloat16* __restrict__ Bh = Xhi + (size_t)z * DIMC * NPIX;
    const __nv_bfloat16* __restrict__ Bl = Xlo + (size_t)z * DIMC * NPIX;
    const int mtidx = blockIdx.y;
    const int m0 = mtidx * 128, n0 = blockIdx.x * 128;

    const int tid = threadIdx.x;
    const int warp = tid >> 5, lane = tid & 31;
    const int wm = (warp & 1) * 64;
    const int wn = (warp >> 1) * 32;
    const int mset0 = (warp & 1) * 4;          // wm/16

    const uint32_t uS = smem_u32(sm);
    const int bRow = tid >> 4, bNc = tid & 15; // B: 16 rows x 16 chunks

    float acc[16][4];
#pragma unroll
    for (int f = 0; f < 16; f++)
#pragma unroll
        for (int r = 0; r < 4; r++) acc[f][r] = 0.f;

    auto copy_stage = [&](int buf, int k0) {
        const uint32_t sb = uS + buf * STAGE3;
        const size_t gb = (size_t)(k0 + bRow) * NPIX + n0 + bNc * 8;
        const uint32_t so = (uint32_t)bRow * 272 + bNc * 16;
        cp16(sb + so, Bh + gb);
        cp16(sb + OFF3_BL + so, Bl + gb);
    };

    copy_stage(0, 0);
    asm volatile("cp.async.commit_group;\n");

    const int nsteps = DIMC / 16;  // 16
    for (int it = 0; it < nsteps; it++) {
        // A fragments from global (no smem dependency) — overlap L2 latency with wait
        uint32_t ah[4][4], al[4][4];
#pragma unroll
        for (int f = 0; f < 4; f++) {
            const uint32_t* src = g_wpk +
                ((size_t)((mtidx * 16 + it) * 8 + mset0 + f) * 2) * 128 + lane * 4;
            *(uint4*)ah[f] = *(const uint4*)src;
            *(uint4*)al[f] = *(const uint4*)(src + 128);
        }

        asm volatile("cp.async.wait_group 0;\n");
        __syncthreads();
        if (it + 1 < nsteps) {
            copy_stage((it + 1) & 1, (it + 1) * 16);
            asm volatile("cp.async.commit_group;\n");
        }

        const uint32_t sb = uS + (it & 1) * STAGE3;
#pragma unroll
        for (int gg = 0; gg < 2; gg++) {
            const int krow = lane & 15;
            const int ncol = wn + gg * 16 + ((lane >> 4) & 1) * 8;
            const uint32_t boff = (uint32_t)(krow * BSTR3 + ncol) * 2;
            uint32_t b4h[4], b4l[4];
            ldsm_x4t(b4h, sb + boff);
            ldsm_x4t(b4l, sb + OFF3_BL + boff);
#pragma unroll
            for (int oct = 0; oct < 2; oct++) {
                const int g = gg * 2 + oct;
                const uint32_t bhf[2] = { b4h[oct * 2], b4h[oct * 2 + 1] };
                const uint32_t blf[2] = { b4l[oct * 2], b4l[oct * 2 + 1] };
#pragma unroll
                for (int f = 0; f < 4; f++) {
                    mma_bf16(acc[f * 4 + g], ah[f], bhf);
                    mma_bf16(acc[f * 4 + g], ah[f], blf);
                    mma_bf16(acc[f * 4 + g], al[f], bhf);
                }
            }
        }
    }

    // ---- epilogue: route to qkv or gate ----
    const int gid = lane >> 2, t4 = lane & 3;
    const bool isGate = (m0 >= D3);
    float* __restrict__ Cb = isGate ? (Cg1 + (size_t)z * 128 * NPIX)
                                    : (Cqkv + (size_t)z * D3 * NPIX);
    const int mAdj = isGate ? (m0 - D3) : m0;
#pragma unroll
    for (int f = 0; f < 4; f++) {
#pragma unroll
        for (int g = 0; g < 4; g++) {
            const int row = mAdj + wm + f * 16 + gid;
            const int col = n0 + wn + g * 8 + t4 * 2;
            const float* a = acc[f * 4 + g];
            float bv0 = 0.f, bv1 = 0.f;
            if (isGate) { bv0 = gb1[row]; bv1 = gb1[row + 8]; }
            float2 v0 = make_float2(a[0] + bv0, a[1] + bv0);
            float2 v1 = make_float2(a[2] + bv1, a[3] + bv1);
            if (isGate) {
                v0.x = fmaxf(v0.x, 0.f); v0.y = fmaxf(v0.y, 0.f);
                v1.x = fmaxf(v1.x, 0.f); v1.y = fmaxf(v1.y, 0.f);
            }
            *(float2*)(Cb + (size_t)row * NPIX + col) = v0;
            *(float2*)(Cb + (size_t)(row + 8) * NPIX + col) = v1;
        }
    }
}

// ========== depthwise 3x3 + fused sumsq; q/k -> bf16 hi/lo, v -> bf16 hi/lo ========
__global__ __launch_bounds__(128) void dwconv4_k(const float* __restrict__ wdw)
{
    const int x     = threadIdx.x;
    const int ytile = blockIdx.x & 15;
    const int bc    = blockIdx.x >> 4;          // b*768 + ch
    const int ch    = bc % D3;
    const int b     = bc / D3;
    const int y0    = ytile * 8;
    const float* __restrict__ in = g_qkv + (size_t)bc * NPIX;

    __shared__ float s[10][130];
    __shared__ float red[4];

#pragma unroll
    for (int r = 0; r < 10; r++) {
        const int yy = y0 - 1 + r;
        s[r][x + 1] = ((unsigned)yy < HH) ? in[yy * WW + x] : 0.f;
    }
    if (x == 0) {
#pragma unroll
        for (int r = 0; r < 10; r++) { s[r][0] = 0.f; s[r][129] = 0.f; }
    }
    __syncthreads();

    float w[9];
#pragma unroll
    for (int i = 0; i < 9; i++) w[i] = __ldg(wdw + ch * 9 + i);

    float res[8];
    float sq = 0.f;
#pragma unroll
    for (int oy = 0; oy < 8; oy++) {
        float acc = 0.f;
#pragma unroll
        for (int dy = 0; dy < 3; dy++)
#pragma unroll
            for (int dx = 0; dx < 3; dx++)
                acc += s[oy + dy][x + dx] * w[dy * 3 + dx];
        res[oy] = acc;
        sq += acc * acc;
    }

    if (ch < 512) {
        __nv_bfloat16* __restrict__ oh = g_qkh + (size_t)(b * 512 + ch) * NPIX;
        __nv_bfloat16* __restrict__ ol = g_qkl + (size_t)(b * 512 + ch) * NPIX;
#pragma unroll
        for (int oy = 0; oy < 8; oy++) {
            const __nv_bfloat16 h = __float2bfloat16(res[oy]);
            oh[(y0 + oy) * WW + x] = h;
            ol[(y0 + oy) * WW + x] = __float2bfloat16(res[oy] - __bfloat162float(h));
        }
#pragma unroll
        for (int o = 16; o > 0; o >>= 1) sq += __shfl_down_sync(0xffffffffu, sq, o);
        if ((x & 31) == 0) red[x >> 5] = sq;
        __syncthreads();
        if (x == 0)
            g_normpart[(b * 512 + ch) * 16 + ytile] = red[0] + red[1] + red[2] + red[3];
    } else {
        const int vch = ch - 512;
        __nv_bfloat16* __restrict__ oh = g_vh + (size_t)(b * 256 + vch) * NPIX;
        __nv_bfloat16* __restrict__ ol = g_vl + (size_t)(b * 256 + vch) * NPIX;
#pragma unroll
        for (int oy = 0; oy < 8; oy++) {
            const __nv_bfloat16 h = __float2bfloat16(res[oy]);
            oh[(y0 + oy) * WW + x] = h;
            ol[(y0 + oy) * WW + x] = __float2bfloat16(res[oy] - __bfloat162float(h));
        }
    }
}

// ================= finish inverse norms from partials =================
__global__ __launch_bounds__(256) void norm2_k()
{
    const int r = blockIdx.x * 256 + threadIdx.x;   // 0..4095
    if (r >= 4096) return;
    float s = 0.f;
#pragma unroll
    for (int i = 0; i < 16; i++) s += g_normpart[r * 16 + i];
    g_inv[r] = 1.f / fmaxf(sqrtf(s), 1e-12f);
}

// ================= gate stage 2 =================
__global__ __launch_bounds__(256) void gate2_k(const float* __restrict__ w2,
                                               const float* __restrict__ b2)
{
    __shared__ float w2s[128];
    const int tid = threadIdx.x;
    if (tid < 128) w2s[tid] = w2[tid];
    __syncthreads();

    const int pg = blockIdx.x * 256 + tid;
    const int b  = pg >> 14;
    const int p  = pg & (NPIX - 1);
    const float* __restrict__ g = g_g1b + (size_t)b * 128 * NPIX + p;

    float acc = b2[0];
#pragma unroll 8
    for (int j = 0; j < 128; j++) acc += w2s[j] * g[(size_t)j * NPIX];
    const float sig = 1.f / (1.f + expf(-acc));

    __shared__ float red[256];
    red[tid] = sig;
    __syncthreads();
    for (int s = 128; s > 0; s >>= 1) {
        if (tid < s) red[tid] += red[tid + s];
        __syncthreads();
    }
    if (tid == 0) g_gatepart[blockIdx.x] = red[0];
}

// ================= dynamic-k =================
__global__ void dk_k()
{
    __shared__ float red[256];
    const int tid = threadIdx.x;
    float s = 0.f;
    for (int i = tid; i < 512; i += 256) s += g_gatepart[i];
    red[tid] = s;
    __syncthreads();
    for (int st = 128; st > 0; st >>= 1) {
        if (tid < st) red[tid] += red[tid + st];
        __syncthreads();
    }
    if (tid == 0) {
        const float mean = red[0] / (float)(BB * NPIX);
        int dk = (int)floorf(64.f * mean);
        if (dk < 1) dk = 1;
        if (dk > 64) dk = 64;
        g_dk = dk;
    }
}

// ================= attn partials: tensor-core bf16-split QK^T =================
#define QSTR 72
__global__ __launch_bounds__(256, 2) void attn_mma_k()
{
    const int bh = blockIdx.y;                 // 0..31
    const int b = bh >> 2, h = bh & 3;
    const int chunk = blockIdx.x;              // 0..15
    const __nv_bfloat16* __restrict__ Qh = g_qkh + (size_t)(b * 512 + h * CH) * NPIX;
    const __nv_bfloat16* __restrict__ Ql = g_qkl + (size_t)(b * 512 + h * CH) * NPIX;
    const __nv_bfloat16* __restrict__ Kh = g_qkh + (size_t)(b * 512 + 256 + h * CH) * NPIX;
    const __nv_bfloat16* __restrict__ Kl = g_qkl + (size_t)(b * 512 + 256 + h * CH) * NPIX;

    __shared__ alignas(16) __nv_bfloat16 sQh[64 * QSTR], sQl[64 * QSTR];
    __shared__ alignas(16) __nv_bfloat16 sKh[64 * QSTR], sKl[64 * QSTR];

    const int tid = threadIdx.x;
    const int warp = tid >> 5, lane = tid & 31;
    const int wm = (warp & 3) * 16;            // m-group (c rows)
    const int wn = (warp >> 2) * 32;           // n-group (d rows)

    const uint32_t uQh = smem_u32(sQh), uQl = smem_u32(sQl);
    const uint32_t uKh = smem_u32(sKh), uKl = smem_u32(sKl);

    float acc[4][4];
#pragma unroll
    for (int g = 0; g < 4; g++)
#pragma unroll
        for (int r = 0; r < 4; r++) acc[g][r] = 0.f;

    for (int sub = 0; sub < 16; sub++) {
        const int pix0 = chunk * 1024 + sub * 64;
#pragma unroll
        for (int i = 0; i < 2; i++) {
            const int idx = tid + i * 256;
            const int row = idx >> 3, c8 = idx & 7;
            const size_t gofs = (size_t)row * NPIX + pix0 + c8 * 8;
            const uint32_t sofs = (uint32_t)row * QSTR + c8 * 8;
            *(uint4*)(sQh + sofs) = *(const uint4*)(Qh + gofs);
            *(uint4*)(sQl + sofs) = *(const uint4*)(Ql + gofs);
            *(uint4*)(sKh + sofs) = *(const uint4*)(Kh + gofs);
            *(uint4*)(sKl + sofs) = *(const uint4*)(Kl + gofs);
        }
        __syncthreads();

#pragma unroll
        for (int ks = 0; ks < 4; ks++) {
            const int kk = ks * 16;
            const int arow = wm + (lane & 15);
            const int acol = kk + ((lane >> 4) & 1) * 8;
            const uint32_t aoff = (uint32_t)(arow * QSTR + acol) * 2;
            uint32_t ah[4], al[4];
            ldsm_x4(ah, uQh + aoff);
            ldsm_x4(al, uQl + aoff);
#pragma unroll
            for (int gg = 0; gg < 2; gg++) {
                const int brow = wn + gg * 16 + (lane & 15);
                const int bcol = kk + ((lane >> 4) & 1) * 8;
                const uint32_t boff = (uint32_t)(brow * QSTR + bcol) * 2;
                uint32_t b4h[4], b4l[4];
                ldsm_x4(b4h, uKh + boff);
                ldsm_x4(b4l, uKl + boff);
#pragma unroll
                for (int oct = 0; oct < 2; oct++) {
                    const int g = gg * 2 + oct;
                    const uint32_t bhf[2] = { b4h[oct], b4h[oct + 2] };
                    const uint32_t blf[2] = { b4l[oct], b4l[oct + 2] };
                    mma_bf16(acc[g], ah, bhf);
                    mma_bf16(acc[g], ah, blf);
                    mma_bf16(acc[g], al, bhf);
                }
            }
        }
        __syncthreads();
    }

    float* __restrict__ P = g_part + ((size_t)chunk * 32 + bh) * 4096;
    const int gid = lane >> 2, t4 = lane & 3;
#pragma unroll
    for (int g = 0; g < 4; g++) {
        const int row = wm + gid;
        const int col = wn + g * 8 + t4 * 2;
        *(float2*)(P + row * 64 + col) = make_float2(acc[g][0], acc[g][1]);
        *(float2*)(P + (row + 8) * 64 + col) = make_float2(acc[g][2], acc[g][3]);
    }
}

// ====== softmax + top-k (fused partial reduction; writes dense weighted P) ======
__global__ __launch_bounds__(64) void softmax_k(const float* __restrict__ temp,
                                                const float* __restrict__ a1,
                                                const float* __restrict__ a2,
                                                const float* __restrict__ a3,
                                                const float* __restrict__ a4)
{
    const int row = blockIdx.x;
    const int bh = row >> 6, c = row & 63;
    const int b = bh >> 2, h = bh & 3;
    const int d = threadIdx.x;

    float sraw = 0.f;
#pragma unroll
    for (int cc = 0; cc < NCHUNK; cc++) sraw += g_part[cc * 131072 + row * 64 + d];

    const float invq = g_inv[b * 512 + h * CH + c];
    const float invk = g_inv[b * 512 + 256 + h * CH + d];
    const float a = sraw * invq * invk * temp[h];

    __shared__ float sv[64], se[64];
    sv[d] = a;
    __syncthreads();

    const int dk = g_dk;
    int rank = 0;
    float mx = -3.4e38f;
#pragma unroll 8
    for (int j = 0; j < 64; j++) {
        const float v = sv[j];
        rank += (v > a);
        mx = fmaxf(mx, v);
    }
    se[d] = (rank < dk) ? a : 3.4e38f;
    __syncthreads();
    float t = 3.4e38f;
#pragma unroll 8
    for (int j = 0; j < 64; j++) t = fminf(t, se[j]);
    __syncthreads();

    const float e = (a >= t) ? expf(a - mx) : 0.f;
    se[d] = e;
    __syncthreads();
    float sum = 0.f;
#pragma unroll 8
    for (int j = 0; j < 64; j++) sum += se[j];

    const float s4 = a1[0] + a2[0] + a3[0] + a4[0];
    g_attn[row * 64 + d] = e / sum * s4;
}

// ================= out = P @ V (tensor cores, bf16 split) =================
#define VSTR 136
__global__ __launch_bounds__(256, 2) void av_mma_k(float* __restrict__ out)
{
    const int bh = blockIdx.y;
    const int b = bh >> 2, h = bh & 3;
    const int n0 = blockIdx.x * 128;
    const __nv_bfloat16* __restrict__ Vh = g_vh + (size_t)(b * 256 + h * CH) * NPIX;
    const __nv_bfloat16* __restrict__ Vl = g_vl + (size_t)(b * 256 + h * CH) * NPIX;
    float* __restrict__ O = out + (size_t)b * DIMC * NPIX + (size_t)(h * CH) * NPIX + n0;

    __shared__ alignas(16) __nv_bfloat16 sPh[64 * QSTR], sPl[64 * QSTR];
    __shared__ alignas(16) __nv_bfloat16 sVh[32 * VSTR], sVl[32 * VSTR];

    const int tid = threadIdx.x;
    const int warp = tid >> 5, lane = tid & 31;
    const int wm = (warp & 3) * 16;            // c group
    const int wn = (warp >> 2) * 64;           // px group

    const uint32_t uPh = smem_u32(sPh), uPl = smem_u32(sPl);
    const uint32_t uVh = smem_u32(sVh), uVl = smem_u32(sVl);

    const float* __restrict__ Pm = g_attn + bh * 4096;
    for (int i = tid; i < 4096; i += 256) {
        const int c = i >> 6, d = i & 63;
        const float v = Pm[i];
        const __nv_bfloat16 hh = __float2bfloat16(v);
        sPh[c * QSTR + d] = hh;
        sPl[c * QSTR + d] = __float2bfloat16(v - __bfloat162float(hh));
    }

    float acc[8][4];
#pragma unroll
    for (int g = 0; g < 8; g++)
#pragma unroll
        for (int r = 0; r < 4; r++) acc[g][r] = 0.f;

#pragma unroll
    for (int kc = 0; kc < 2; kc++) {
        __syncthreads();
#pragma unroll
        for (int i = 0; i < 2; i++) {
            const int idx = tid + i * 256;
            const int row = idx >> 4, c8 = idx & 15;
            const size_t gofs = (size_t)(kc * 32 + row) * NPIX + n0 + c8 * 8;
            const uint32_t sofs = (uint32_t)row * VSTR + c8 * 8;
            *(uint4*)(sVh + sofs) = *(const uint4*)(Vh + gofs);
            *(uint4*)(sVl + sofs) = *(const uint4*)(Vl + gofs);
        }
        __syncthreads();

#pragma unroll
        for (int ks = 0; ks < 2; ks++) {
            const int kl = ks * 16;
            const int kg = kc * 32 + kl;
            const int arow = wm + (lane & 15);
            const int acol = kg + ((lane >> 4) & 1) * 8;
            const uint32_t aoff = (uint32_t)(arow * QSTR + acol) * 2;
            uint32_t ah[4], al[4];
            ldsm_x4(ah, uPh + aoff);
            ldsm_x4(al, uPl + aoff);
#pragma unroll
            for (int gg = 0; gg < 4; gg++) {
                const int krow = kl + (lane & 15);
                const int ncol = wn + gg * 16 + ((lane >> 4) & 1) * 8;
                const uint32_t boff = (uint32_t)(krow * VSTR + ncol) * 2;
                uint32_t b4h[4], b4l[4];
                ldsm_x4t(b4h, uVh + boff);
                ldsm_x4t(b4l, uVl + boff);
#pragma unroll
                for (int oct = 0; oct < 2; oct++) {
                    const int g = gg * 2 + oct;
                    const uint32_t bhf[2] = { b4h[oct * 2], b4h[oct * 2 + 1] };
                    const uint32_t blf[2] = { b4l[oct * 2], b4l[oct * 2 + 1] };
                    mma_bf16(acc[g], ah, bhf);
                    mma_bf16(acc[g], ah, blf);
                    mma_bf16(acc[g], al, bhf);
                }
            }
        }
    }

    const int gid = lane >> 2, t4 = lane & 3;
#pragma unroll
    for (int g = 0; g < 8; g++) {
        const int row = wm + gid;
        const int col = wn + g * 8 + t4 * 2;
        *(float2*)(O + (size_t)row * NPIX + col) = make_float2(acc[g][0], acc[g][1]);
        *(float2*)(O + (size_t)(row + 8) * NPIX + col) = make_float2(acc[g][2], acc[g][3]);
    }
}

// ================================ launch ================================
extern "C" void kernel_launch(void* const* d_in, const int* in_sizes, int n_in,
                              void* d_out, int out_size)
{
    (void)in_sizes; (void)n_in; (void)out_size;
    const float* x     = (const float*)d_in[0];
    const float* w_qkv = (const float*)d_in[1];
    const float* w_dw  = (const float*)d_in[2];
    const float* temp  = (const float*)d_in[3];
    const float* a1    = (const float*)d_in[4];
    const float* a2    = (const float*)d_in[5];
    const float* a3    = (const float*)d_in[6];
    const float* a4    = (const float*)d_in[7];
    const float* gw1   = (const float*)d_in[8];
    const float* gb1   = (const float*)d_in[9];
    const float* gw2   = (const float*)d_in[10];
    const float* gb2   = (const float*)d_in[11];
    float* out = (float*)d_out;

    void *p_qkv, *p_g1, *p_xhi, *p_xlo, *p_wchi, *p_wclo;
    cudaGetSymbolAddress(&p_qkv, g_qkv);
    cudaGetSymbolAddress(&p_g1, g_g1b);
    cudaGetSymbolAddress(&p_xhi, g_xhi);
    cudaGetSymbolAddress(&p_xlo, g_xlo);
    cudaGetSymbolAddress(&p_wchi, g_wchi);
    cudaGetSymbolAddress(&p_wclo, g_wclo);

    // 0) bf16 splits + W fragment packing
    split_k<<<(33554432 / 4 + 255) / 256, 256>>>(x, (__nv_bfloat16*)p_xhi,
                                                 (__nv_bfloat16*)p_xlo, 33554432 / 4);
    split_k<<<(196608 / 4 + 255) / 256, 256>>>(w_qkv, (__nv_bfloat16*)p_wchi,
                                               (__nv_bfloat16*)p_wclo, 196608 / 4);
    split_k<<<(32768 / 4 + 255) / 256, 256>>>(gw1,
                                              (__nv_bfloat16*)p_wchi + 196608,
                                              (__nv_bfloat16*)p_wclo + 196608, 32768 / 4);
    {
        dim3 g(16, MTOT / 128);
        packA_k<<<g, 256>>>();
    }

    // 1) fused qkv + gate1 GEMM (A frags from global, B cp.async double-buffered)
    {
        dim3 g(NPIX / 128, MTOT / 128, BB);
        bfgemm4_k<<<g, 256>>>(
            (const __nv_bfloat16*)p_xhi, (const __nv_bfloat16*)p_xlo,
            (float*)p_qkv, (float*)p_g1, gb1);
    }
    // 2) depthwise 3x3 + fused sumsq; q/k and v -> bf16 hi/lo
    dwconv4_k<<<BB * D3 * 16, 128>>>(w_dw);
    // 3) gate stage 2 + dk
    gate2_k<<<512, 256>>>(gw2, gb2);
    dk_k<<<1, 256>>>();
    // 4) finish inverse norms
    norm2_k<<<16, 256>>>();
    // 5) attention S = Q K^T
    {
        dim3 g(NCHUNK, 32);
        attn_mma_k<<<g, 256>>>();
    }
    // 6) softmax with top-k (fused partial reduce)
    softmax_k<<<2048, 64>>>(temp, a1, a2, a3, a4);
    // 7) out = P @ V (tensor cores)
    {
        dim3 g(NPIX / 128, 32);
        av_mma_k<<<g, 256>>>(out);
    }
}

// round 13
// speedup vs baseline: 2.5359x; 1.0148x over previous
#include <cuda_runtime.h>
#include <cuda_bf16.h>
#include <math.h>
#include <stdint.h>

// ---------------- problem constants ----------------
#define BB    8
#define DIMC  256
#define D3    768          // 3*DIM
#define HEADS 4
#define CH    64           // per-head channels
#define HH    128
#define WW    128
#define NPIX  16384        // H*W
#define MTOT  896          // 768 qkv rows + 128 gate rows (fused GEMM)
#define NCHUNK 16          // attn pixel chunks (1024 px each)

// ---------------- scratch (device globals; no runtime alloc) ----------------
__device__ float g_qkv[100663296];   // [B,768,NPIX] post 1x1 conv
__device__ float g_g1b[16777216];    // [B,128,NPIX] gate hidden
__device__ float g_part[2097152];    // [16 chunks][32 bh][64][64] attn partials
__device__ float g_attn[131072];     // [32 bh][64][64] weighted P
__device__ float g_inv[4096];        // inverse L2 norms
__device__ float g_normpart[65536];  // [b*512+ch][16] sum-of-square partials
__device__ float g_gatepart[512];
__device__ int   g_dk;

__device__ __nv_bfloat16 g_xhi[33554432];   // X split hi  [B,256,NPIX]
__device__ __nv_bfloat16 g_xlo[33554432];   // X split lo
__device__ __nv_bfloat16 g_wchi[229376];    // combined weights split [896,256]
__device__ __nv_bfloat16 g_wclo[229376];
__device__ uint32_t g_wpk[229376];          // W packed in mma-fragment order
__device__ __nv_bfloat16 g_qkh[67108864];   // q/k post-dw bf16 hi [B,512,NPIX]
__device__ __nv_bfloat16 g_qkl[67108864];   // q/k post-dw bf16 lo
__device__ __nv_bfloat16 g_vh[33554432];    // v post-dw bf16 hi [B,256,NPIX]
__device__ __nv_bfloat16 g_vl[33554432];    // v post-dw bf16 lo

// ================= bf16 split conversion: v = hi + lo =================
__global__ __launch_bounds__(256) void split_k(const float* __restrict__ in,
                                               __nv_bfloat16* __restrict__ hi,
                                               __nv_bfloat16* __restrict__ lo, int n4)
{
    const int i = blockIdx.x * 256 + threadIdx.x;
    if (i >= n4) return;
    const float4 v = ((const float4*)in)[i];
    __nv_bfloat16 h0 = __float2bfloat16(v.x);
    __nv_bfloat16 h1 = __float2bfloat16(v.y);
    __nv_bfloat16 h2 = __float2bfloat16(v.z);
    __nv_bfloat16 h3 = __float2bfloat16(v.w);
    __nv_bfloat162* H = (__nv_bfloat162*)hi;
    __nv_bfloat162* L = (__nv_bfloat162*)lo;
    H[i * 2 + 0] = __nv_bfloat162(h0, h1);
    H[i * 2 + 1] = __nv_bfloat162(h2, h3);
    L[i * 2 + 0] = __nv_bfloat162(__float2bfloat16(v.x - __bfloat162float(h0)),
                                  __float2bfloat16(v.y - __bfloat162float(h1)));
    L[i * 2 + 1] = __nv_bfloat162(__float2bfloat16(v.z - __bfloat162float(h2)),
                                  __float2bfloat16(v.w - __bfloat162float(h3)));
}

// ================= MMA helpers =================
__device__ __forceinline__ uint32_t smem_u32(const void* p) {
    return (uint32_t)__cvta_generic_to_shared(p);
}
__device__ __forceinline__ void cp16(uint32_t dst, const void* src) {
    asm volatile("cp.async.cg.shared.global [%0], [%1], 16;\n" :: "r"(dst), "l"(src));
}
__device__ __forceinline__ void ldsm_x4(uint32_t* r, uint32_t a) {
    asm volatile("ldmatrix.sync.aligned.m8n8.x4.shared.b16 {%0,%1,%2,%3}, [%4];"
                 : "=r"(r[0]), "=r"(r[1]), "=r"(r[2]), "=r"(r[3]) : "r"(a));
}
__device__ __forceinline__ void ldsm_x4t(uint32_t* r, uint32_t a) {
    asm volatile("ldmatrix.sync.aligned.m8n8.x4.trans.shared.b16 {%0,%1,%2,%3}, [%4];"
                 : "=r"(r[0]), "=r"(r[1]), "=r"(r[2]), "=r"(r[3]) : "r"(a));
}
__device__ __forceinline__ void mma_bf16(float* c, const uint32_t* a, const uint32_t* b) {
    asm volatile("mma.sync.aligned.m16n8k16.row.col.f32.bf16.bf16.f32 "
                 "{%0,%1,%2,%3}, {%4,%5,%6,%7}, {%8,%9}, {%0,%1,%2,%3};"
                 : "+f"(c[0]), "+f"(c[1]), "+f"(c[2]), "+f"(c[3])
                 : "r"(a[0]), "r"(a[1]), "r"(a[2]), "r"(a[3]), "r"(b[0]), "r"(b[1]));
}

// ================= pack W fragments (replay ldmatrix semantics) =================
#define PSTR 24
__global__ __launch_bounds__(256) void packA_k()
{
    const int kstep = blockIdx.x;      // 0..15
    const int mtile = blockIdx.y;      // 0..6
    __shared__ alignas(16) __nv_bfloat16 sh[128 * PSTR], sl[128 * PSTR];
    const int tid = threadIdx.x;
    {
        const int row = tid >> 1, kc = tid & 1;
        const size_t g = (size_t)(mtile * 128 + row) * DIMC + kstep * 16 + kc * 8;
        *(uint4*)(sh + row * PSTR + kc * 8) = *(const uint4*)(g_wchi + g);
        *(uint4*)(sl + row * PSTR + kc * 8) = *(const uint4*)(g_wclo + g);
    }
    __syncthreads();
    const int warp = tid >> 5, lane = tid & 31;   // warp = m16-set 0..7
    const int mrow = warp * 16 + (lane & 15);
    const int kcol = ((lane >> 4) & 1) * 8;
    const uint32_t off = (uint32_t)(mrow * PSTR + kcol) * 2;
    uint32_t r[4];
    ldsm_x4(r, smem_u32(sh) + off);
    const size_t base = ((size_t)(mtile * 16 + kstep) * 8 + warp) * 2;
    *(uint4*)(g_wpk + base * 128 + lane * 4) = *(const uint4*)r;
    ldsm_x4(r, smem_u32(sl) + off);
    *(uint4*)(g_wpk + (base + 1) * 128 + lane * 4) = *(const uint4*)r;
}

// ====== tensor-core bf16-split GEMM: A frags from global, 3-stage B pipeline ======
#define BSTR3 136       // B smem row stride in bf16 (272 B rows)
#define OFF3_BL 4352
#define STAGE3  8704    // bytes per stage (Bh + Bl)

__global__ __launch_bounds__(256, 2) void bfgemm4_k(
    const __nv_bfloat16* __restrict__ Xhi, const __nv_bfloat16* __restrict__ Xlo,
    float* __restrict__ Cqkv, float* __restrict__ Cg1,
    const float* __restrict__ gb1)
{
    __shared__ alignas(16) char sm[3 * STAGE3];
    const int z = blockIdx.z;
    const __nv_bfloat16* __restrict__ Bh = Xhi + (size_t)z * DIMC * NPIX;
    const __nv_bfloat16* __restrict__ Bl = Xlo + (size_t)z * DIMC * NPIX;
    const int mtidx = blockIdx.y;
    const int m0 = mtidx * 128, n0 = blockIdx.x * 128;

    const int tid = threadIdx.x;
    const int warp = tid >> 5, lane = tid & 31;
    const int wm = (warp & 1) * 64;
    const int wn = (warp >> 1) * 32;
    const int mset0 = (warp & 1) * 4;

    const uint32_t uS = smem_u32(sm);
    const int bRow = tid >> 4, bNc = tid & 15; // B: 16 rows x 16 chunks

    float acc[16][4];
#pragma unroll
    for (int f = 0; f < 16; f++)
#pragma unroll
        for (int r = 0; r < 4; r++) acc[f][r] = 0.f;

    auto copy_stage = [&](int buf, int k0) {
        const uint32_t sb = uS + buf * STAGE3;
        const size_t gb = (size_t)(k0 + bRow) * NPIX + n0 + bNc * 8;
        const uint32_t so = (uint32_t)bRow * 272 + bNc * 16;
        cp16(sb + so, Bh + gb);
        cp16(sb + OFF3_BL + so, Bl + gb);
    };

    copy_stage(0, 0);
    asm volatile("cp.async.commit_group;\n");
    copy_stage(1, 16);
    asm volatile("cp.async.commit_group;\n");

    const int nsteps = DIMC / 16;  // 16
    for (int it = 0; it < nsteps; it++) {
        // A fragments from global (L2-resident packed weights)
        uint32_t ah[4][4], al[4][4];
#pragma unroll
        for (int f = 0; f < 4; f++) {
            const uint32_t* src = g_wpk +
                ((size_t)((mtidx * 16 + it) * 8 + mset0 + f) * 2) * 128 + lane * 4;
            *(uint4*)ah[f] = *(const uint4*)src;
            *(uint4*)al[f] = *(const uint4*)(src + 128);
        }

        if (it < nsteps - 1) {
            asm volatile("cp.async.wait_group 1;\n");   // stage 'it' done
        } else {
            asm volatile("cp.async.wait_group 0;\n");
        }
        __syncthreads();   // also: all threads done reading buf (it+2)%3 (iter it-1)
        if (it + 2 < nsteps) {
            copy_stage((it + 2) % 3, (it + 2) * 16);
            asm volatile("cp.async.commit_group;\n");
        }

        const uint32_t sb = uS + (it % 3) * STAGE3;
#pragma unroll
        for (int gg = 0; gg < 2; gg++) {
            const int krow = lane & 15;
            const int ncol = wn + gg * 16 + ((lane >> 4) & 1) * 8;
            const uint32_t boff = (uint32_t)(krow * BSTR3 + ncol) * 2;
            uint32_t b4h[4], b4l[4];
            ldsm_x4t(b4h, sb + boff);
            ldsm_x4t(b4l, sb + OFF3_BL + boff);
#pragma unroll
            for (int oct = 0; oct < 2; oct++) {
                const int g = gg * 2 + oct;
                const uint32_t bhf[2] = { b4h[oct * 2], b4h[oct * 2 + 1] };
                const uint32_t blf[2] = { b4l[oct * 2], b4l[oct * 2 + 1] };
#pragma unroll
                for (int f = 0; f < 4; f++) {
                    mma_bf16(acc[f * 4 + g], ah[f], bhf);
                    mma_bf16(acc[f * 4 + g], ah[f], blf);
                    mma_bf16(acc[f * 4 + g], al[f], bhf);
                }
            }
        }
    }

    // ---- epilogue: route to qkv or gate ----
    const int gid = lane >> 2, t4 = lane & 3;
    const bool isGate = (m0 >= D3);
    float* __restrict__ Cb = isGate ? (Cg1 + (size_t)z * 128 * NPIX)
                                    : (Cqkv + (size_t)z * D3 * NPIX);
    const int mAdj = isGate ? (m0 - D3) : m0;
#pragma unroll
    for (int f = 0; f < 4; f++) {
#pragma unroll
        for (int g = 0; g < 4; g++) {
            const int row = mAdj + wm + f * 16 + gid;
            const int col = n0 + wn + g * 8 + t4 * 2;
            const float* a = acc[f * 4 + g];
            float bv0 = 0.f, bv1 = 0.f;
            if (isGate) { bv0 = gb1[row]; bv1 = gb1[row + 8]; }
            float2 v0 = make_float2(a[0] + bv0, a[1] + bv0);
            float2 v1 = make_float2(a[2] + bv1, a[3] + bv1);
            if (isGate) {
                v0.x = fmaxf(v0.x, 0.f); v0.y = fmaxf(v0.y, 0.f);
                v1.x = fmaxf(v1.x, 0.f); v1.y = fmaxf(v1.y, 0.f);
            }
            *(float2*)(Cb + (size_t)row * NPIX + col) = v0;
            *(float2*)(Cb + (size_t)(row + 8) * NPIX + col) = v1;
        }
    }
}

// ===== depthwise 3x3 + fused sumsq; packed 4-px bf16 writes (8B stores) =====
// 128 threads: tx = tid&31 -> 4 px, ry = tid>>5 -> rows {ry, ry+4} of the 8-row tile.
__global__ __launch_bounds__(128) void dwconv5_k(const float* __restrict__ wdw)
{
    const int tid   = threadIdx.x;
    const int ytile = blockIdx.x & 15;
    const int bc    = blockIdx.x >> 4;          // b*768 + ch
    const int ch    = bc % D3;
    const int b     = bc / D3;
    const int y0    = ytile * 8;
    const float* __restrict__ in = g_qkv + (size_t)bc * NPIX;

    __shared__ float s[10][132];
    __shared__ float red[4];

    {
        const int x = tid;
#pragma unroll
        for (int r = 0; r < 10; r++) {
            const int yy = y0 - 1 + r;
            s[r][x + 1] = ((unsigned)yy < HH) ? in[yy * WW + x] : 0.f;
        }
        if (x == 0) {
#pragma unroll
            for (int r = 0; r < 10; r++) { s[r][0] = 0.f; s[r][129] = 0.f; }
        }
    }
    __syncthreads();

    float w[9];
#pragma unroll
    for (int i = 0; i < 9; i++) w[i] = __ldg(wdw + ch * 9 + i);

    const int tx = tid & 31;       // px group of 4
    const int ry = tid >> 5;       // 0..3
    const int x0 = tx * 4;

    float res[2][4];
    float sq = 0.f;
#pragma unroll
    for (int half = 0; half < 2; half++) {
        const int oy = ry + half * 4;       // 0..7
#pragma unroll
        for (int px = 0; px < 4; px++) {
            float acc = 0.f;
#pragma unroll
            for (int dy = 0; dy < 3; dy++)
#pragma unroll
                for (int dx = 0; dx < 3; dx++)
                    acc += s[oy + dy][x0 + px + dx] * w[dy * 3 + dx];
            res[half][px] = acc;
            sq += acc * acc;
        }
    }

    const bool isQK = (ch < 512);
    __nv_bfloat16* __restrict__ oh = isQK
        ? g_qkh + (size_t)(b * 512 + ch) * NPIX
        : g_vh + (size_t)(b * 256 + (ch - 512)) * NPIX;
    __nv_bfloat16* __restrict__ ol = isQK
        ? g_qkl + (size_t)(b * 512 + ch) * NPIX
        : g_vl + (size_t)(b * 256 + (ch - 512)) * NPIX;

#pragma unroll
    for (int half = 0; half < 2; half++) {
        const int oy = ry + half * 4;
        __nv_bfloat16 hv[4], lv[4];
#pragma unroll
        for (int px = 0; px < 4; px++) {
            hv[px] = __float2bfloat16(res[half][px]);
            lv[px] = __float2bfloat16(res[half][px] - __bfloat162float(hv[px]));
        }
        const size_t o = (size_t)(y0 + oy) * WW + x0;
        *(uint2*)(oh + o) = *(const uint2*)hv;
        *(uint2*)(ol + o) = *(const uint2*)lv;
    }

    if (isQK) {
#pragma unroll
        for (int o = 16; o > 0; o >>= 1) sq += __shfl_down_sync(0xffffffffu, sq, o);
        if ((tid & 31) == 0) red[tid >> 5] = sq;
        __syncthreads();
        if (tid == 0)
            g_normpart[(b * 512 + ch) * 16 + ytile] = red[0] + red[1] + red[2] + red[3];
    }
}

// ================= finish inverse norms from partials =================
__global__ __launch_bounds__(256) void norm2_k()
{
    const int r = blockIdx.x * 256 + threadIdx.x;   // 0..4095
    if (r >= 4096) return;
    float s = 0.f;
#pragma unroll
    for (int i = 0; i < 16; i++) s += g_normpart[r * 16 + i];
    g_inv[r] = 1.f / fmaxf(sqrtf(s), 1e-12f);
}

// ================= gate stage 2 =================
__global__ __launch_bounds__(256) void gate2_k(const float* __restrict__ w2,
                                               const float* __restrict__ b2)
{
    __shared__ float w2s[128];
    const int tid = threadIdx.x;
    if (tid < 128) w2s[tid] = w2[tid];
    __syncthreads();

    const int pg = blockIdx.x * 256 + tid;
    const int b  = pg >> 14;
    const int p  = pg & (NPIX - 1);
    const float* __restrict__ g = g_g1b + (size_t)b * 128 * NPIX + p;

    float acc = b2[0];
#pragma unroll 8
    for (int j = 0; j < 128; j++) acc += w2s[j] * g[(size_t)j * NPIX];
    const float sig = 1.f / (1.f + expf(-acc));

    __shared__ float red[256];
    red[tid] = sig;
    __syncthreads();
    for (int s = 128; s > 0; s >>= 1) {
        if (tid < s) red[tid] += red[tid + s];
        __syncthreads();
    }
    if (tid == 0) g_gatepart[blockIdx.x] = red[0];
}

// ================= dynamic-k =================
__global__ void dk_k()
{
    __shared__ float red[256];
    const int tid = threadIdx.x;
    float s = 0.f;
    for (int i = tid; i < 512; i += 256) s += g_gatepart[i];
    red[tid] = s;
    __syncthreads();
    for (int st = 128; st > 0; st >>= 1) {
        if (tid < st) red[tid] += red[tid + st];
        __syncthreads();
    }
    if (tid == 0) {
        const float mean = red[0] / (float)(BB * NPIX);
        int dk = (int)floorf(64.f * mean);
        if (dk < 1) dk = 1;
        if (dk > 64) dk = 64;
        g_dk = dk;
    }
}

// ================= attn partials: tensor-core bf16-split QK^T =================
#define QSTR 72
__global__ __launch_bounds__(256, 2) void attn_mma_k()
{
    const int bh = blockIdx.y;                 // 0..31
    const int b = bh >> 2, h = bh & 3;
    const int chunk = blockIdx.x;              // 0..15
    const __nv_bfloat16* __restrict__ Qh = g_qkh + (size_t)(b * 512 + h * CH) * NPIX;
    const __nv_bfloat16* __restrict__ Ql = g_qkl + (size_t)(b * 512 + h * CH) * NPIX;
    const __nv_bfloat16* __restrict__ Kh = g_qkh + (size_t)(b * 512 + 256 + h * CH) * NPIX;
    const __nv_bfloat16* __restrict__ Kl = g_qkl + (size_t)(b * 512 + 256 + h * CH) * NPIX;

    __shared__ alignas(16) __nv_bfloat16 sQh[64 * QSTR], sQl[64 * QSTR];
    __shared__ alignas(16) __nv_bfloat16 sKh[64 * QSTR], sKl[64 * QSTR];

    const int tid = threadIdx.x;
    const int warp = tid >> 5, lane = tid & 31;
    const int wm = (warp & 3) * 16;            // m-group (c rows)
    const int wn = (warp >> 2) * 32;           // n-group (d rows)

    const uint32_t uQh = smem_u32(sQh), uQl = smem_u32(sQl);
    const uint32_t uKh = smem_u32(sKh), uKl = smem_u32(sKl);

    float acc[4][4];
#pragma unroll
    for (int g = 0; g < 4; g++)
#pragma unroll
        for (int r = 0; r < 4; r++) acc[g][r] = 0.f;

    for (int sub = 0; sub < 16; sub++) {
        const int pix0 = chunk * 1024 + sub * 64;
#pragma unroll
        for (int i = 0; i < 2; i++) {
            const int idx = tid + i * 256;
            const int row = idx >> 3, c8 = idx & 7;
            const size_t gofs = (size_t)row * NPIX + pix0 + c8 * 8;
            const uint32_t sofs = (uint32_t)row * QSTR + c8 * 8;
            *(uint4*)(sQh + sofs) = *(const uint4*)(Qh + gofs);
            *(uint4*)(sQl + sofs) = *(const uint4*)(Ql + gofs);
            *(uint4*)(sKh + sofs) = *(const uint4*)(Kh + gofs);
            *(uint4*)(sKl + sofs) = *(const uint4*)(Kl + gofs);
        }
        __syncthreads();

#pragma unroll
        for (int ks = 0; ks < 4; ks++) {
            const int kk = ks * 16;
            const int arow = wm + (lane & 15);
            const int acol = kk + ((lane >> 4) & 1) * 8;
            const uint32_t aoff = (uint32_t)(arow * QSTR + acol) * 2;
            uint32_t ah[4], al[4];
            ldsm_x4(ah, uQh + aoff);
            ldsm_x4(al, uQl + aoff);
#pragma unroll
            for (int gg = 0; gg < 2; gg++) {
                const int brow = wn + gg * 16 + (lane & 15);
                const int bcol = kk + ((lane >> 4) & 1) * 8;
                const uint32_t boff = (uint32_t)(brow * QSTR + bcol) * 2;
                uint32_t b4h[4], b4l[4];
                ldsm_x4(b4h, uKh + boff);
                ldsm_x4(b4l, uKl + boff);
#pragma unroll
                for (int oct = 0; oct < 2; oct++) {
                    const int g = gg * 2 + oct;
                    const uint32_t bhf[2] = { b4h[oct], b4h[oct + 2] };
                    const uint32_t blf[2] = { b4l[oct], b4l[oct + 2] };
                    mma_bf16(acc[g], ah, bhf);
                    mma_bf16(acc[g], ah, blf);
                    mma_bf16(acc[g], al, bhf);
                }
            }
        }
        __syncthreads();
    }

    float* __restrict__ P = g_part + ((size_t)chunk * 32 + bh) * 4096;
    const int gid = lane >> 2, t4 = lane & 3;
#pragma unroll
    for (int g = 0; g < 4; g++) {
        const int row = wm + gid;
        const int col = wn + g * 8 + t4 * 2;
        *(float2*)(P + row * 64 + col) = make_float2(acc[g][0], acc[g][1]);
        *(float2*)(P + (row + 8) * 64 + col) = make_float2(acc[g][2], acc[g][3]);
    }
}

// ====== softmax + top-k (fused partial reduction; writes dense weighted P) ======
__global__ __launch_bounds__(64) void softmax_k(const float* __restrict__ temp,
                                                const float* __restrict__ a1,
                                                const float* __restrict__ a2,
                                                const float* __restrict__ a3,
                                                const float* __restrict__ a4)
{
    const int row = blockIdx.x;
    const int bh = row >> 6, c = row & 63;
    const int b = bh >> 2, h = bh & 3;
    const int d = threadIdx.x;

    float sraw = 0.f;
#pragma unroll
    for (int cc = 0; cc < NCHUNK; cc++) sraw += g_part[cc * 131072 + row * 64 + d];

    const float invq = g_inv[b * 512 + h * CH + c];
    const float invk = g_inv[b * 512 + 256 + h * CH + d];
    const float a = sraw * invq * invk * temp[h];

    __shared__ float sv[64], se[64];
    sv[d] = a;
    __syncthreads();

    const int dk = g_dk;
    int rank = 0;
    float mx = -3.4e38f;
#pragma unroll 8
    for (int j = 0; j < 64; j++) {
        const float v = sv[j];
        rank += (v > a);
        mx = fmaxf(mx, v);
    }
    se[d] = (rank < dk) ? a : 3.4e38f;
    __syncthreads();
    float t = 3.4e38f;
#pragma unroll 8
    for (int j = 0; j < 64; j++) t = fminf(t, se[j]);
    __syncthreads();

    const float e = (a >= t) ? expf(a - mx) : 0.f;
    se[d] = e;
    __syncthreads();
    float sum = 0.f;
#pragma unroll 8
    for (int j = 0; j < 64; j++) sum += se[j];

    const float s4 = a1[0] + a2[0] + a3[0] + a4[0];
    g_attn[row * 64 + d] = e / sum * s4;
}

// ================= out = P @ V (tensor cores, bf16 split) =================
#define VSTR 136
__global__ __launch_bounds__(256, 2) void av_mma_k(float* __restrict__ out)
{
    const int bh = blockIdx.y;
    const int b = bh >> 2, h = bh & 3;
    const int n0 = blockIdx.x * 128;
    const __nv_bfloat16* __restrict__ Vh = g_vh + (size_t)(b * 256 + h * CH) * NPIX;
    const __nv_bfloat16* __restrict__ Vl = g_vl + (size_t)(b * 256 + h * CH) * NPIX;
    float* __restrict__ O = out + (size_t)b * DIMC * NPIX + (size_t)(h * CH) * NPIX + n0;

    __shared__ alignas(16) __nv_bfloat16 sPh[64 * QSTR], sPl[64 * QSTR];
    __shared__ alignas(16) __nv_bfloat16 sVh[32 * VSTR], sVl[32 * VSTR];

    const int tid = threadIdx.x;
    const int warp = tid >> 5, lane = tid & 31;
    const int wm = (warp & 3) * 16;            // c group
    const int wn = (warp >> 2) * 64;           // px group

    const uint32_t uPh = smem_u32(sPh), uPl = smem_u32(sPl);
    const uint32_t uVh = smem_u32(sVh), uVl = smem_u32(sVl);

    const float* __restrict__ Pm = g_attn + bh * 4096;
    for (int i = tid; i < 4096; i += 256) {
        const int c = i >> 6, d = i & 63;
        const float v = Pm[i];
        const __nv_bfloat16 hh = __float2bfloat16(v);
        sPh[c * QSTR + d] = hh;
        sPl[c * QSTR + d] = __float2bfloat16(v - __bfloat162float(hh));
    }

    float acc[8][4];
#pragma unroll
    for (int g = 0; g < 8; g++)
#pragma unroll
        for (int r = 0; r < 4; r++) acc[g][r] = 0.f;

#pragma unroll
    for (int kc = 0; kc < 2; kc++) {
        __syncthreads();
#pragma unroll
        for (int i = 0; i < 2; i++) {
            const int idx = tid + i * 256;
            const int row = idx >> 4, c8 = idx & 15;
            const size_t gofs = (size_t)(kc * 32 + row) * NPIX + n0 + c8 * 8;
            const uint32_t sofs = (uint32_t)row * VSTR + c8 * 8;
            *(uint4*)(sVh + sofs) = *(const uint4*)(Vh + gofs);
            *(uint4*)(sVl + sofs) = *(const uint4*)(Vl + gofs);
        }
        __syncthreads();

#pragma unroll
        for (int ks = 0; ks < 2; ks++) {
            const int kl = ks * 16;
            const int kg = kc * 32 + kl;
            const int arow = wm + (lane & 15);
            const int acol = kg + ((lane >> 4) & 1) * 8;
            const uint32_t aoff = (uint32_t)(arow * QSTR + acol) * 2;
            uint32_t ah[4], al[4];
            ldsm_x4(ah, uPh + aoff);
            ldsm_x4(al, uPl + aoff);
#pragma unroll
            for (int gg = 0; gg < 4; gg++) {
                const int krow = kl + (lane & 15);
                const int ncol = wn + gg * 16 + ((lane >> 4) & 1) * 8;
                const uint32_t boff = (uint32_t)(krow * VSTR + ncol) * 2;
                uint32_t b4h[4], b4l[4];
                ldsm_x4t(b4h, uVh + boff);
                ldsm_x4t(b4l, uVl + boff);
#pragma unroll
                for (int oct = 0; oct < 2; oct++) {
                    const int g = gg * 2 + oct;
                    const uint32_t bhf[2] = { b4h[oct * 2], b4h[oct * 2 + 1] };
                    const uint32_t blf[2] = { b4l[oct * 2], b4l[oct * 2 + 1] };
                    mma_bf16(acc[g], ah, bhf);
                    mma_bf16(acc[g], ah, blf);
                    mma_bf16(acc[g], al, bhf);
                }
            }
        }
    }

    const int gid = lane >> 2, t4 = lane & 3;
#pragma unroll
    for (int g = 0; g < 8; g++) {
        const int row = wm + gid;
        const int col = wn + g * 8 + t4 * 2;
        *(float2*)(O + (size_t)row * NPIX + col) = make_float2(acc[g][0], acc[g][1]);
        *(float2*)(O + (size_t)(row + 8) * NPIX + col) = make_float2(acc[g][2], acc[g][3]);
    }
}

// ================================ launch ================================
extern "C" void kernel_launch(void* const* d_in, const int* in_sizes, int n_in,
                              void* d_out, int out_size)
{
    (void)in_sizes; (void)n_in; (void)out_size;
    const float* x     = (const float*)d_in[0];
    const float* w_qkv = (const float*)d_in[1];
    const float* w_dw  = (const float*)d_in[2];
    const float* temp  = (const float*)d_in[3];
    const float* a1    = (const float*)d_in[4];
    const float* a2    = (const float*)d_in[5];
    const float* a3    = (const float*)d_in[6];
    const float* a4    = (const float*)d_in[7];
    const float* gw1   = (const float*)d_in[8];
    const float* gb1   = (const float*)d_in[9];
    const float* gw2   = (const float*)d_in[10];
    const float* gb2   = (const float*)d_in[11];
    float* out = (float*)d_out;

    void *p_qkv, *p_g1, *p_xhi, *p_xlo, *p_wchi, *p_wclo;
    cudaGetSymbolAddress(&p_qkv, g_qkv);
    cudaGetSymbolAddress(&p_g1, g_g1b);
    cudaGetSymbolAddress(&p_xhi, g_xhi);
    cudaGetSymbolAddress(&p_xlo, g_xlo);
    cudaGetSymbolAddress(&p_wchi, g_wchi);
    cudaGetSymbolAddress(&p_wclo, g_wclo);

    // 0) bf16 splits + W fragment packing
    split_k<<<(33554432 / 4 + 255) / 256, 256>>>(x, (__nv_bfloat16*)p_xhi,
                                                 (__nv_bfloat16*)p_xlo, 33554432 / 4);
    split_k<<<(196608 / 4 + 255) / 256, 256>>>(w_qkv, (__nv_bfloat16*)p_wchi,
                                               (__nv_bfloat16*)p_wclo, 196608 / 4);
    split_k<<<(32768 / 4 + 255) / 256, 256>>>(gw1,
                                              (__nv_bfloat16*)p_wchi + 196608,
                                              (__nv_bfloat16*)p_wclo + 196608, 32768 / 4);
    {
        dim3 g(16, MTOT / 128);
        packA_k<<<g, 256>>>();
    }

    // 1) fused qkv + gate1 GEMM (A frags from global, 3-stage cp.async B pipeline)
    {
        dim3 g(NPIX / 128, MTOT / 128, BB);
        bfgemm4_k<<<g, 256>>>(
            (const __nv_bfloat16*)p_xhi, (const __nv_bfloat16*)p_xlo,
            (float*)p_qkv, (float*)p_g1, gb1);
    }
    // 2) depthwise 3x3 + fused sumsq; packed bf16 writes
    dwconv5_k<<<BB * D3 * 16, 128>>>(w_dw);
    // 3) gate stage 2 + dk
    gate2_k<<<512, 256>>>(gw2, gb2);
    dk_k<<<1, 256>>>();
    // 4) finish inverse norms
    norm2_k<<<16, 256>>>();
    // 5) attention S = Q K^T
    {
        dim3 g(NCHUNK, 32);
        attn_mma_k<<<g, 256>>>();
    }
    // 6) softmax with top-k (fused partial reduce)
    softmax_k<<<2048, 64>>>(temp, a1, a2, a3, a4);
    // 7) out = P @ V (tensor cores)
    {
        dim3 g(NPIX / 128, 32);
        av_mma_k<<<g, 256>>>(out);
    }
}

// round 17
// speedup vs baseline: 2.6476x; 1.0441x over previous
#include <cuda_runtime.h>
#include <cuda_bf16.h>
#include <math.h>
#include <stdint.h>

// ---------------- problem constants ----------------
#define BB    8
#define DIMC  256
#define D3    768          // 3*DIM
#define HEADS 4
#define CH    64           // per-head channels
#define HH    128
#define WW    128
#define NPIX  16384        // H*W
#define MTOT  896          // 768 qkv rows + 128 gate rows (fused GEMM)
#define NCHUNK 16          // attn pixel chunks (1024 px each)

// ---------------- scratch (device globals; no runtime alloc) ----------------
__device__ float g_qkv[100663296];   // [B,768,NPIX] post 1x1 conv
__device__ float g_g1b[16777216];    // [B,128,NPIX] gate hidden
__device__ float g_part[2097152];    // [16 chunks][32 bh][64][64] attn partials
__device__ float g_attn[131072];     // [32 bh][64][64] weighted P
__device__ float g_inv[4096];        // inverse L2 norms
__device__ float g_normpart[65536];  // [b*512+ch][16] sum-of-square partials
__device__ float g_gatepart[512];
__device__ int   g_dk;

__device__ __nv_bfloat16 g_xhi[33554432];   // X split hi  [B,256,NPIX]
__device__ __nv_bfloat16 g_xlo[33554432];   // X split lo
__device__ __nv_bfloat16 g_wchi[229376];    // combined weights split [896,256]
__device__ __nv_bfloat16 g_wclo[229376];
__device__ uint32_t g_wpk[229376];          // W packed in mma-fragment order
__device__ __nv_bfloat16 g_qkh[67108864];   // q/k post-dw bf16 hi [B,512,NPIX]
__device__ __nv_bfloat16 g_qkl[67108864];   // q/k post-dw bf16 lo
__device__ __nv_bfloat16 g_vh[33554432];    // v post-dw bf16 hi [B,256,NPIX]
__device__ __nv_bfloat16 g_vl[33554432];    // v post-dw bf16 lo

// ================= bf16 split conversion: v = hi + lo =================
__global__ __launch_bounds__(256) void split_k(const float* __restrict__ in,
                                               __nv_bfloat16* __restrict__ hi,
                                               __nv_bfloat16* __restrict__ lo, int n4)
{
    const int i = blockIdx.x * 256 + threadIdx.x;
    if (i >= n4) return;
    const float4 v = ((const float4*)in)[i];
    __nv_bfloat16 h0 = __float2bfloat16(v.x);
    __nv_bfloat16 h1 = __float2bfloat16(v.y);
    __nv_bfloat16 h2 = __float2bfloat16(v.z);
    __nv_bfloat16 h3 = __float2bfloat16(v.w);
    __nv_bfloat162* H = (__nv_bfloat162*)hi;
    __nv_bfloat162* L = (__nv_bfloat162*)lo;
    H[i * 2 + 0] = __nv_bfloat162(h0, h1);
    H[i * 2 + 1] = __nv_bfloat162(h2, h3);
    L[i * 2 + 0] = __nv_bfloat162(__float2bfloat16(v.x - __bfloat162float(h0)),
                                  __float2bfloat16(v.y - __bfloat162float(h1)));
    L[i * 2 + 1] = __nv_bfloat162(__float2bfloat16(v.z - __bfloat162float(h2)),
                                  __float2bfloat16(v.w - __bfloat162float(h3)));
}

// ================= MMA helpers =================
__device__ __forceinline__ uint32_t smem_u32(const void* p) {
    return (uint32_t)__cvta_generic_to_shared(p);
}
__device__ __forceinline__ void cp16(uint32_t dst, const void* src) {
    asm volatile("cp.async.cg.shared.global [%0], [%1], 16;\n" :: "r"(dst), "l"(src));
}
__device__ __forceinline__ void ldsm_x4(uint32_t* r, uint32_t a) {
    asm volatile("ldmatrix.sync.aligned.m8n8.x4.shared.b16 {%0,%1,%2,%3}, [%4];"
                 : "=r"(r[0]), "=r"(r[1]), "=r"(r[2]), "=r"(r[3]) : "r"(a));
}
__device__ __forceinline__ void ldsm_x4t(uint32_t* r, uint32_t a) {
    asm volatile("ldmatrix.sync.aligned.m8n8.x4.trans.shared.b16 {%0,%1,%2,%3}, [%4];"
                 : "=r"(r[0]), "=r"(r[1]), "=r"(r[2]), "=r"(r[3]) : "r"(a));
}
__device__ __forceinline__ void mma_bf16(float* c, const uint32_t* a, const uint32_t* b) {
    asm volatile("mma.sync.aligned.m16n8k16.row.col.f32.bf16.bf16.f32 "
                 "{%0,%1,%2,%3}, {%4,%5,%6,%7}, {%8,%9}, {%0,%1,%2,%3};"
                 : "+f"(c[0]), "+f"(c[1]), "+f"(c[2]), "+f"(c[3])
                 : "r"(a[0]), "r"(a[1]), "r"(a[2]), "r"(a[3]), "r"(b[0]), "r"(b[1]));
}

// ================= pack W fragments (replay ldmatrix semantics) =================
#define PSTR 24
__global__ __launch_bounds__(256) void packA_k()
{
    const int kstep = blockIdx.x;      // 0..15
    const int mtile = blockIdx.y;      // 0..6
    __shared__ alignas(16) __nv_bfloat16 sh[128 * PSTR], sl[128 * PSTR];
    const int tid = threadIdx.x;
    {
        const int row = tid >> 1, kc = tid & 1;
        const size_t g = (size_t)(mtile * 128 + row) * DIMC + kstep * 16 + kc * 8;
        *(uint4*)(sh + row * PSTR + kc * 8) = *(const uint4*)(g_wchi + g);
        *(uint4*)(sl + row * PSTR + kc * 8) = *(const uint4*)(g_wclo + g);
    }
    __syncthreads();
    const int warp = tid >> 5, lane = tid & 31;   // warp = m16-set 0..7
    const int mrow = warp * 16 + (lane & 15);
    const int kcol = ((lane >> 4) & 1) * 8;
    const uint32_t off = (uint32_t)(mrow * PSTR + kcol) * 2;
    uint32_t r[4];
    ldsm_x4(r, smem_u32(sh) + off);
    const size_t base = ((size_t)(mtile * 16 + kstep) * 8 + warp) * 2;
    *(uint4*)(g_wpk + base * 128 + lane * 4) = *(const uint4*)r;
    ldsm_x4(r, smem_u32(sl) + off);
    *(uint4*)(g_wpk + (base + 1) * 128 + lane * 4) = *(const uint4*)r;
}

// ====== tensor-core bf16-split GEMM: A frags from global, 3-stage B pipeline ======
// MMA issue order is term-major (hh all, hl all, lh all) -> dependent distance 8.
#define BSTR3 136       // B smem row stride in bf16 (272 B rows)
#define OFF3_BL 4352
#define STAGE3  8704    // bytes per stage (Bh + Bl)

__global__ __launch_bounds__(256, 2) void bfgemm4_k(
    const __nv_bfloat16* __restrict__ Xhi, const __nv_bfloat16* __restrict__ Xlo,
    float* __restrict__ Cqkv, float* __restrict__ Cg1,
    const float* __restrict__ gb1)
{
    __shared__ alignas(16) char sm[3 * STAGE3];
    const int z = blockIdx.z;
    const __nv_bfloat16* __restrict__ Bh = Xhi + (size_t)z * DIMC * NPIX;
    const __nv_bfloat16* __restrict__ Bl = Xlo + (size_t)z * DIMC * NPIX;
    const int mtidx = blockIdx.y;
    const int m0 = mtidx * 128, n0 = blockIdx.x * 128;

    const int tid = threadIdx.x;
    const int warp = tid >> 5, lane = tid & 31;
    const int wm = (warp & 1) * 64;
    const int wn = (warp >> 1) * 32;
    const int mset0 = (warp & 1) * 4;

    const uint32_t uS = smem_u32(sm);
    const int bRow = tid >> 4, bNc = tid & 15; // B: 16 rows x 16 chunks

    float acc[16][4];
#pragma unroll
    for (int f = 0; f < 16; f++)
#pragma unroll
        for (int r = 0; r < 4; r++) acc[f][r] = 0.f;

    auto copy_stage = [&](int buf, int k0) {
        const uint32_t sb = uS + buf * STAGE3;
        const size_t gb = (size_t)(k0 + bRow) * NPIX + n0 + bNc * 8;
        const uint32_t so = (uint32_t)bRow * 272 + bNc * 16;
        cp16(sb + so, Bh + gb);
        cp16(sb + OFF3_BL + so, Bl + gb);
    };

    copy_stage(0, 0);
    asm volatile("cp.async.commit_group;\n");
    copy_stage(1, 16);
    asm volatile("cp.async.commit_group;\n");

    const int nsteps = DIMC / 16;  // 16
    for (int it = 0; it < nsteps; it++) {
        // A fragments from global (L2-resident packed weights)
        uint32_t ah[4][4], al[4][4];
#pragma unroll
        for (int f = 0; f < 4; f++) {
            const uint32_t* src = g_wpk +
                ((size_t)((mtidx * 16 + it) * 8 + mset0 + f) * 2) * 128 + lane * 4;
            *(uint4*)ah[f] = *(const uint4*)src;
            *(uint4*)al[f] = *(const uint4*)(src + 128);
        }

        if (it < nsteps - 1) {
            asm volatile("cp.async.wait_group 1;\n");   // stage 'it' done
        } else {
            asm volatile("cp.async.wait_group 0;\n");
        }
        __syncthreads();   // all threads done reading buf (it+2)%3 (iter it-1)
        if (it + 2 < nsteps) {
            copy_stage((it + 2) % 3, (it + 2) * 16);
            asm volatile("cp.async.commit_group;\n");
        }

        const uint32_t sb = uS + (it % 3) * STAGE3;
#pragma unroll
        for (int gg = 0; gg < 2; gg++) {
            const int krow = lane & 15;
            const int ncol = wn + gg * 16 + ((lane >> 4) & 1) * 8;
            const uint32_t boff = (uint32_t)(krow * BSTR3 + ncol) * 2;
            uint32_t b4h[4], b4l[4];
            ldsm_x4t(b4h, sb + boff);
            ldsm_x4t(b4l, sb + OFF3_BL + boff);
            // term-major issue: distance-8 dependent chains per accumulator
#pragma unroll
            for (int oct = 0; oct < 2; oct++) {
                const int g = gg * 2 + oct;
                const uint32_t bhf[2] = { b4h[oct * 2], b4h[oct * 2 + 1] };
#pragma unroll
                for (int f = 0; f < 4; f++) mma_bf16(acc[f * 4 + g], ah[f], bhf);
            }
#pragma unroll
            for (int oct = 0; oct < 2; oct++) {
                const int g = gg * 2 + oct;
                const uint32_t blf[2] = { b4l[oct * 2], b4l[oct * 2 + 1] };
#pragma unroll
                for (int f = 0; f < 4; f++) mma_bf16(acc[f * 4 + g], ah[f], blf);
            }
#pragma unroll
            for (int oct = 0; oct < 2; oct++) {
                const int g = gg * 2 + oct;
                const uint32_t bhf[2] = { b4h[oct * 2], b4h[oct * 2 + 1] };
#pragma unroll
                for (int f = 0; f < 4; f++) mma_bf16(acc[f * 4 + g], al[f], bhf);
            }
        }
    }

    // ---- epilogue: route to qkv or gate ----
    const int gid = lane >> 2, t4 = lane & 3;
    const bool isGate = (m0 >= D3);
    float* __restrict__ Cb = isGate ? (Cg1 + (size_t)z * 128 * NPIX)
                                    : (Cqkv + (size_t)z * D3 * NPIX);
    const int mAdj = isGate ? (m0 - D3) : m0;
#pragma unroll
    for (int f = 0; f < 4; f++) {
#pragma unroll
        for (int g = 0; g < 4; g++) {
            const int row = mAdj + wm + f * 16 + gid;
            const int col = n0 + wn + g * 8 + t4 * 2;
            const float* a = acc[f * 4 + g];
            float bv0 = 0.f, bv1 = 0.f;
            if (isGate) { bv0 = gb1[row]; bv1 = gb1[row + 8]; }
            float2 v0 = make_float2(a[0] + bv0, a[1] + bv0);
            float2 v1 = make_float2(a[2] + bv1, a[3] + bv1);
            if (isGate) {
                v0.x = fmaxf(v0.x, 0.f); v0.y = fmaxf(v0.y, 0.f);
                v1.x = fmaxf(v1.x, 0.f); v1.y = fmaxf(v1.y, 0.f);
            }
            *(float2*)(Cb + (size_t)row * NPIX + col) = v0;
            *(float2*)(Cb + (size_t)(row + 8) * NPIX + col) = v1;
        }
    }
}

// ===== depthwise 3x3 + fused sumsq; packed 4-px bf16 writes (8B stores) =====
__global__ __launch_bounds__(128) void dwconv5_k(const float* __restrict__ wdw)
{
    const int tid   = threadIdx.x;
    const int ytile = blockIdx.x & 15;
    const int bc    = blockIdx.x >> 4;          // b*768 + ch
    const int ch    = bc % D3;
    const int b     = bc / D3;
    const int y0    = ytile * 8;
    const float* __restrict__ in = g_qkv + (size_t)bc * NPIX;

    __shared__ float s[10][132];
    __shared__ float red[4];

    {
        const int x = tid;
#pragma unroll
        for (int r = 0; r < 10; r++) {
            const int yy = y0 - 1 + r;
            s[r][x + 1] = ((unsigned)yy < HH) ? in[yy * WW + x] : 0.f;
        }
        if (x == 0) {
#pragma unroll
            for (int r = 0; r < 10; r++) { s[r][0] = 0.f; s[r][129] = 0.f; }
        }
    }
    __syncthreads();

    float w[9];
#pragma unroll
    for (int i = 0; i < 9; i++) w[i] = __ldg(wdw + ch * 9 + i);

    const int tx = tid & 31;       // px group of 4
    const int ry = tid >> 5;       // 0..3
    const int x0 = tx * 4;

    float res[2][4];
    float sq = 0.f;
#pragma unroll
    for (int half = 0; half < 2; half++) {
        const int oy = ry + half * 4;       // 0..7
#pragma unroll
        for (int px = 0; px < 4; px++) {
            float acc = 0.f;
#pragma unroll
            for (int dy = 0; dy < 3; dy++)
#pragma unroll
                for (int dx = 0; dx < 3; dx++)
                    acc += s[oy + dy][x0 + px + dx] * w[dy * 3 + dx];
            res[half][px] = acc;
            sq += acc * acc;
        }
    }

    const bool isQK = (ch < 512);
    __nv_bfloat16* __restrict__ oh = isQK
        ? g_qkh + (size_t)(b * 512 + ch) * NPIX
        : g_vh + (size_t)(b * 256 + (ch - 512)) * NPIX;
    __nv_bfloat16* __restrict__ ol = isQK
        ? g_qkl + (size_t)(b * 512 + ch) * NPIX
        : g_vl + (size_t)(b * 256 + (ch - 512)) * NPIX;

#pragma unroll
    for (int half = 0; half < 2; half++) {
        const int oy = ry + half * 4;
        __nv_bfloat16 hv[4], lv[4];
#pragma unroll
        for (int px = 0; px < 4; px++) {
            hv[px] = __float2bfloat16(res[half][px]);
            lv[px] = __float2bfloat16(res[half][px] - __bfloat162float(hv[px]));
        }
        const size_t o = (size_t)(y0 + oy) * WW + x0;
        *(uint2*)(oh + o) = *(const uint2*)hv;
        *(uint2*)(ol + o) = *(const uint2*)lv;
    }

    if (isQK) {
#pragma unroll
        for (int o = 16; o > 0; o >>= 1) sq += __shfl_down_sync(0xffffffffu, sq, o);
        if ((tid & 31) == 0) red[tid >> 5] = sq;
        __syncthreads();
        if (tid == 0)
            g_normpart[(b * 512 + ch) * 16 + ytile] = red[0] + red[1] + red[2] + red[3];
    }
}

// ================= finish inverse norms from partials =================
__global__ __launch_bounds__(256) void norm2_k()
{
    const int r = blockIdx.x * 256 + threadIdx.x;   // 0..4095
    if (r >= 4096) return;
    float s = 0.f;
#pragma unroll
    for (int i = 0; i < 16; i++) s += g_normpart[r * 16 + i];
    g_inv[r] = 1.f / fmaxf(sqrtf(s), 1e-12f);
}

// ================= gate stage 2 =================
__global__ __launch_bounds__(256) void gate2_k(const float* __restrict__ w2,
                                               const float* __restrict__ b2)
{
    __shared__ float w2s[128];
    const int tid = threadIdx.x;
    if (tid < 128) w2s[tid] = w2[tid];
    __syncthreads();

    const int pg = blockIdx.x * 256 + tid;
    const int b  = pg >> 14;
    const int p  = pg & (NPIX - 1);
    const float* __restrict__ g = g_g1b + (size_t)b * 128 * NPIX + p;

    float acc = b2[0];
#pragma unroll 8
    for (int j = 0; j < 128; j++) acc += w2s[j] * g[(size_t)j * NPIX];
    const float sig = 1.f / (1.f + expf(-acc));

    __shared__ float red[256];
    red[tid] = sig;
    __syncthreads();
    for (int s = 128; s > 0; s >>= 1) {
        if (tid < s) red[tid] += red[tid + s];
        __syncthreads();
    }
    if (tid == 0) g_gatepart[blockIdx.x] = red[0];
}

// ================= dynamic-k =================
__global__ void dk_k()
{
    __shared__ float red[256];
    const int tid = threadIdx.x;
    float s = 0.f;
    for (int i = tid; i < 512; i += 256) s += g_gatepart[i];
    red[tid] = s;
    __syncthreads();
    for (int st = 128; st > 0; st >>= 1) {
        if (tid < st) red[tid] += red[tid + st];
        __syncthreads();
    }
    if (tid == 0) {
        const float mean = red[0] / (float)(BB * NPIX);
        int dk = (int)floorf(64.f * mean);
        if (dk < 1) dk = 1;
        if (dk > 64) dk = 64;
        g_dk = dk;
    }
}

// ================= attn partials: bf16-split QK^T (term-major mma) =================
#define QSTR 72
__global__ __launch_bounds__(256, 2) void attn_mma_k()
{
    const int bh = blockIdx.y;                 // 0..31
    const int b = bh >> 2, h = bh & 3;
    const int chunk = blockIdx.x;              // 0..15
    const __nv_bfloat16* __restrict__ Qh = g_qkh + (size_t)(b * 512 + h * CH) * NPIX;
    const __nv_bfloat16* __restrict__ Ql = g_qkl + (size_t)(b * 512 + h * CH) * NPIX;
    const __nv_bfloat16* __restrict__ Kh = g_qkh + (size_t)(b * 512 + 256 + h * CH) * NPIX;
    const __nv_bfloat16* __restrict__ Kl = g_qkl + (size_t)(b * 512 + 256 + h * CH) * NPIX;

    __shared__ alignas(16) __nv_bfloat16 sQh[64 * QSTR], sQl[64 * QSTR];
    __shared__ alignas(16) __nv_bfloat16 sKh[64 * QSTR], sKl[64 * QSTR];

    const int tid = threadIdx.x;
    const int warp = tid >> 5, lane = tid & 31;
    const int wm = (warp & 3) * 16;            // m-group (c rows)
    const int wn = (warp >> 2) * 32;           // n-group (d rows)

    const uint32_t uQh = smem_u32(sQh), uQl = smem_u32(sQl);
    const uint32_t uKh = smem_u32(sKh), uKl = smem_u32(sKl);

    float acc[4][4];
#pragma unroll
    for (int g = 0; g < 4; g++)
#pragma unroll
        for (int r = 0; r < 4; r++) acc[g][r] = 0.f;

    for (int sub = 0; sub < 16; sub++) {
        const int pix0 = chunk * 1024 + sub * 64;
#pragma unroll
        for (int i = 0; i < 2; i++) {
            const int idx = tid + i * 256;
            const int row = idx >> 3, c8 = idx & 7;
            const size_t gofs = (size_t)row * NPIX + pix0 + c8 * 8;
            const uint32_t sofs = (uint32_t)row * QSTR + c8 * 8;
            *(uint4*)(sQh + sofs) = *(const uint4*)(Qh + gofs);
            *(uint4*)(sQl + sofs) = *(const uint4*)(Ql + gofs);
            *(uint4*)(sKh + sofs) = *(const uint4*)(Kh + gofs);
            *(uint4*)(sKl + sofs) = *(const uint4*)(Kl + gofs);
        }
        __syncthreads();

#pragma unroll
        for (int ks = 0; ks < 4; ks++) {
            const int kk = ks * 16;
            const int arow = wm + (lane & 15);
            const int acol = kk + ((lane >> 4) & 1) * 8;
            const uint32_t aoff = (uint32_t)(arow * QSTR + acol) * 2;
            uint32_t ah[4], al[4];
            ldsm_x4(ah, uQh + aoff);
            ldsm_x4(al, uQl + aoff);
            // hoist all B fragments, then term-major: distance-4 chains
            uint32_t b4h[2][4], b4l[2][4];
#pragma unroll
            for (int gg = 0; gg < 2; gg++) {
                const int brow = wn + gg * 16 + (lane & 15);
                const int bcol = kk + ((lane >> 4) & 1) * 8;
                const uint32_t boff = (uint32_t)(brow * QSTR + bcol) * 2;
                ldsm_x4(b4h[gg], uKh + boff);
                ldsm_x4(b4l[gg], uKl + boff);
            }
#pragma unroll
            for (int g = 0; g < 4; g++) {
                const uint32_t bhf[2] = { b4h[g >> 1][g & 1], b4h[g >> 1][(g & 1) + 2] };
                mma_bf16(acc[g], ah, bhf);
            }
#pragma unroll
            for (int g = 0; g < 4; g++) {
                const uint32_t blf[2] = { b4l[g >> 1][g & 1], b4l[g >> 1][(g & 1) + 2] };
                mma_bf16(acc[g], ah, blf);
            }
#pragma unroll
            for (int g = 0; g < 4; g++) {
                const uint32_t bhf[2] = { b4h[g >> 1][g & 1], b4h[g >> 1][(g & 1) + 2] };
                mma_bf16(acc[g], al, bhf);
            }
        }
        __syncthreads();
    }

    float* __restrict__ P = g_part + ((size_t)chunk * 32 + bh) * 4096;
    const int gid = lane >> 2, t4 = lane & 3;
#pragma unroll
    for (int g = 0; g < 4; g++) {
        const int row = wm + gid;
        const int col = wn + g * 8 + t4 * 2;
        *(float2*)(P + row * 64 + col) = make_float2(acc[g][0], acc[g][1]);
        *(float2*)(P + (row + 8) * 64 + col) = make_float2(acc[g][2], acc[g][3]);
    }
}

// ====== softmax + top-k (fused partial reduction; writes dense weighted P) ======
__global__ __launch_bounds__(64) void softmax_k(const float* __restrict__ temp,
                                                const float* __restrict__ a1,
                                                const float* __restrict__ a2,
                                                const float* __restrict__ a3,
                                                const float* __restrict__ a4)
{
    const int row = blockIdx.x;
    const int bh = row >> 6, c = row & 63;
    const int b = bh >> 2, h = bh & 3;
    const int d = threadIdx.x;

    float sraw = 0.f;
#pragma unroll
    for (int cc = 0; cc < NCHUNK; cc++) sraw += g_part[cc * 131072 + row * 64 + d];

    const float invq = g_inv[b * 512 + h * CH + c];
    const float invk = g_inv[b * 512 + 256 + h * CH + d];
    const float a = sraw * invq * invk * temp[h];

    __shared__ float sv[64], se[64];
    sv[d] = a;
    __syncthreads();

    const int dk = g_dk;
    int rank = 0;
    float mx = -3.4e38f;
#pragma unroll 8
    for (int j = 0; j < 64; j++) {
        const float v = sv[j];
        rank += (v > a);
        mx = fmaxf(mx, v);
    }
    se[d] = (rank < dk) ? a : 3.4e38f;
    __syncthreads();
    float t = 3.4e38f;
#pragma unroll 8
    for (int j = 0; j < 64; j++) t = fminf(t, se[j]);
    __syncthreads();

    const float e = (a >= t) ? expf(a - mx) : 0.f;
    se[d] = e;
    __syncthreads();
    float sum = 0.f;
#pragma unroll 8
    for (int j = 0; j < 64; j++) sum += se[j];

    const float s4 = a1[0] + a2[0] + a3[0] + a4[0];
    g_attn[row * 64 + d] = e / sum * s4;
}

// ================= out = P @ V (term-major mma) =================
#define VSTR 136
__global__ __launch_bounds__(256, 2) void av_mma_k(float* __restrict__ out)
{
    const int bh = blockIdx.y;
    const int b = bh >> 2, h = bh & 3;
    const int n0 = blockIdx.x * 128;
    const __nv_bfloat16* __restrict__ Vh = g_vh + (size_t)(b * 256 + h * CH) * NPIX;
    const __nv_bfloat16* __restrict__ Vl = g_vl + (size_t)(b * 256 + h * CH) * NPIX;
    float* __restrict__ O = out + (size_t)b * DIMC * NPIX + (size_t)(h * CH) * NPIX + n0;

    __shared__ alignas(16) __nv_bfloat16 sPh[64 * QSTR], sPl[64 * QSTR];
    __shared__ alignas(16) __nv_bfloat16 sVh[32 * VSTR], sVl[32 * VSTR];

    const int tid = threadIdx.x;
    const int warp = tid >> 5, lane = tid & 31;
    const int wm = (warp & 3) * 16;            // c group
    const int wn = (warp >> 2) * 64;           // px group

    const uint32_t uPh = smem_u32(sPh), uPl = smem_u32(sPl);
    const uint32_t uVh = smem_u32(sVh), uVl = smem_u32(sVl);

    const float* __restrict__ Pm = g_attn + bh * 4096;
    for (int i = tid; i < 4096; i += 256) {
        const int c = i >> 6, d = i & 63;
        const float v = Pm[i];
        const __nv_bfloat16 hh = __float2bfloat16(v);
        sPh[c * QSTR + d] = hh;
        sPl[c * QSTR + d] = __float2bfloat16(v - __bfloat162float(hh));
    }

    float acc[8][4];
#pragma unroll
    for (int g = 0; g < 8; g++)
#pragma unroll
        for (int r = 0; r < 4; r++) acc[g][r] = 0.f;

#pragma unroll
    for (int kc = 0; kc < 2; kc++) {
        __syncthreads();
#pragma unroll
        for (int i = 0; i < 2; i++) {
            const int idx = tid + i * 256;
            const int row = idx >> 4, c8 = idx & 15;
            const size_t gofs = (size_t)(kc * 32 + row) * NPIX + n0 + c8 * 8;
            const uint32_t sofs = (uint32_t)row * VSTR + c8 * 8;
            *(uint4*)(sVh + sofs) = *(const uint4*)(Vh + gofs);
            *(uint4*)(sVl + sofs) = *(const uint4*)(Vl + gofs);
        }
        __syncthreads();

#pragma unroll
        for (int ks = 0; ks < 2; ks++) {
            const int kl = ks * 16;
            const int kg = kc * 32 + kl;
            const int arow = wm + (lane & 15);
            const int acol = kg + ((lane >> 4) & 1) * 8;
            const uint32_t aoff = (uint32_t)(arow * QSTR + acol) * 2;
            uint32_t ah[4], al[4];
            ldsm_x4(ah, uPh + aoff);
            ldsm_x4(al, uPl + aoff);
#pragma unroll
            for (int gg = 0; gg < 4; gg++) {
                const int krow = kl + (lane & 15);
                const int ncol = wn + gg * 16 + ((lane >> 4) & 1) * 8;
                const uint32_t boff = (uint32_t)(krow * VSTR + ncol) * 2;
                uint32_t b4h[4], b4l[4];
                ldsm_x4t(b4h, uVh + boff);
                ldsm_x4t(b4l, uVl + boff);
                // term-major within this gg: distance-2 chains
#pragma unroll
                for (int oct = 0; oct < 2; oct++) {
                    const int g = gg * 2 + oct;
                    const uint32_t bhf[2] = { b4h[oct * 2], b4h[oct * 2 + 1] };
                    mma_bf16(acc[g], ah, bhf);
                }
#pragma unroll
                for (int oct = 0; oct < 2; oct++) {
                    const int g = gg * 2 + oct;
                    const uint32_t blf[2] = { b4l[oct * 2], b4l[oct * 2 + 1] };
                    mma_bf16(acc[g], ah, blf);
                }
#pragma unroll
                for (int oct = 0; oct < 2; oct++) {
                    const int g = gg * 2 + oct;
                    const uint32_t bhf[2] = { b4h[oct * 2], b4h[oct * 2 + 1] };
                    mma_bf16(acc[g], al, bhf);
                }
            }
        }
    }

    const int gid = lane >> 2, t4 = lane & 3;
#pragma unroll
    for (int g = 0; g < 8; g++) {
        const int row = wm + gid;
        const int col = wn + g * 8 + t4 * 2;
        *(float2*)(O + (size_t)row * NPIX + col) = make_float2(acc[g][0], acc[g][1]);
        *(float2*)(O + (size_t)(row + 8) * NPIX + col) = make_float2(acc[g][2], acc[g][3]);
    }
}

// ================================ launch ================================
extern "C" void kernel_launch(void* const* d_in, const int* in_sizes, int n_in,
                              void* d_out, int out_size)
{
    (void)in_sizes; (void)n_in; (void)out_size;
    const float* x     = (const float*)d_in[0];
    const float* w_qkv = (const float*)d_in[1];
    const float* w_dw  = (const float*)d_in[2];
    const float* temp  = (const float*)d_in[3];
    const float* a1    = (const float*)d_in[4];
    const float* a2    = (const float*)d_in[5];
    const float* a3    = (const float*)d_in[6];
    const float* a4    = (const float*)d_in[7];
    const float* gw1   = (const float*)d_in[8];
    const float* gb1   = (const float*)d_in[9];
    const float* gw2   = (const float*)d_in[10];
    const float* gb2   = (const float*)d_in[11];
    float* out = (float*)d_out;

    void *p_qkv, *p_g1, *p_xhi, *p_xlo, *p_wchi, *p_wclo;
    cudaGetSymbolAddress(&p_qkv, g_qkv);
    cudaGetSymbolAddress(&p_g1, g_g1b);
    cudaGetSymbolAddress(&p_xhi, g_xhi);
    cudaGetSymbolAddress(&p_xlo, g_xlo);
    cudaGetSymbolAddress(&p_wchi, g_wchi);
    cudaGetSymbolAddress(&p_wclo, g_wclo);

    // 0) bf16 splits + W fragment packing
    split_k<<<(33554432 / 4 + 255) / 256, 256>>>(x, (__nv_bfloat16*)p_xhi,
                                                 (__nv_bfloat16*)p_xlo, 33554432 / 4);
    split_k<<<(196608 / 4 + 255) / 256, 256>>>(w_qkv, (__nv_bfloat16*)p_wchi,
                                               (__nv_bfloat16*)p_wclo, 196608 / 4);
    split_k<<<(32768 / 4 + 255) / 256, 256>>>(gw1,
                                              (__nv_bfloat16*)p_wchi + 196608,
                                              (__nv_bfloat16*)p_wclo + 196608, 32768 / 4);
    {
        dim3 g(16, MTOT / 128);
        packA_k<<<g, 256>>>();
    }

    // 1) fused qkv + gate1 GEMM (A frags from global, 3-stage cp.async B pipeline)
    {
        dim3 g(NPIX / 128, MTOT / 128, BB);
        bfgemm4_k<<<g, 256>>>(
            (const __nv_bfloat16*)p_xhi, (const __nv_bfloat16*)p_xlo,
            (float*)p_qkv, (float*)p_g1, gb1);
    }
    // 2) depthwise 3x3 + fused sumsq; packed bf16 writes
    dwconv5_k<<<BB * D3 * 16, 128>>>(w_dw);
    // 3) gate stage 2 + dk
    gate2_k<<<512, 256>>>(gw2, gb2);
    dk_k<<<1, 256>>>();
    // 4) finish inverse norms
    norm2_k<<<16, 256>>>();
    // 5) attention S = Q K^T
    {
        dim3 g(NCHUNK, 32);
        attn_mma_k<<<g, 256>>>();
    }
    // 6) softmax with top-k (fused partial reduce)
    softmax_k<<<2048, 64>>>(temp, a1, a2, a3, a4);
    // 7) out = P @ V (tensor cores)
    {
        dim3 g(NPIX / 128, 32);
        av_mma_k<<<g, 256>>>(out);
    }
}